// round 1
// baseline (speedup 1.0000x reference)
#include <cuda_runtime.h>
#include <math.h>

// Problem dims (fixed by the dataset)
#define B_  2
#define N_  1024
#define C_  256
#define NQ_ 100
#define HALF_ 128

// Scratch (device globals: no allocation allowed)
__device__ float g_h[B_ * N_ * C_];     // gelu(LN(x)@W_in + b_in)
__device__ float g_A[B_ * N_ * C_];     // local@W1a + glob@W1b + b1   (per b,t)
__device__ float g_Cq[B_ * NQ_ * C_];   // q@W1c                        (per b,i)
__device__ float g_gt[B_ * C_];         // glob@W1b + b1                (per b)

__device__ __forceinline__ float gelu_f(float x) {
    return 0.5f * x * (1.0f + erff(x * 0.70710678118654752440f));
}

// ---------------------------------------------------------------------------
// K1: h = gelu(LN(x) @ W_in + b_in).  8 rows per block, 256 threads.
// ---------------------------------------------------------------------------
__global__ void __launch_bounds__(256) k1_ln_gemm_gelu(
    const float* __restrict__ x, const float* __restrict__ ln_g,
    const float* __restrict__ ln_b, const float* __restrict__ Win,
    const float* __restrict__ bin)
{
    __shared__ float sY[8][C_];
    __shared__ float sred[8];
    __shared__ float sbc[2];
    const int tid = threadIdx.x;
    const int lane = tid & 31, wid = tid >> 5;
    const int row0 = blockIdx.x * 8;

    const float gv = ln_g[tid];
    const float bv = ln_b[tid];

    for (int r = 0; r < 8; r++) {
        float xv = x[(row0 + r) * C_ + tid];
        // mean
        float v = xv;
        #pragma unroll
        for (int o = 16; o; o >>= 1) v += __shfl_xor_sync(0xffffffffu, v, o);
        if (lane == 0) sred[wid] = v;
        __syncthreads();
        if (tid == 0) {
            float s = 0.f;
            #pragma unroll
            for (int w = 0; w < 8; w++) s += sred[w];
            sbc[0] = s * (1.0f / C_);
        }
        __syncthreads();
        const float mu = sbc[0];
        const float d = xv - mu;
        v = d * d;
        #pragma unroll
        for (int o = 16; o; o >>= 1) v += __shfl_xor_sync(0xffffffffu, v, o);
        if (lane == 0) sred[wid] = v;
        __syncthreads();
        if (tid == 0) {
            float s = 0.f;
            #pragma unroll
            for (int w = 0; w < 8; w++) s += sred[w];
            sbc[1] = rsqrtf(s * (1.0f / C_) + 1e-5f);
        }
        __syncthreads();
        sY[r][tid] = d * sbc[1] * gv + bv;
        __syncthreads();
    }

    float acc[8];
    const float bi0 = bin[tid];
    #pragma unroll
    for (int r = 0; r < 8; r++) acc[r] = bi0;
    for (int k = 0; k < C_; k++) {
        const float w = Win[k * C_ + tid];
        #pragma unroll
        for (int r = 0; r < 8; r++) acc[r] += sY[r][k] * w;
    }
    #pragma unroll
    for (int r = 0; r < 8; r++)
        g_h[(row0 + r) * C_ + tid] = gelu_f(acc[r]);
}

// ---------------------------------------------------------------------------
// K2: glob[b] = sum_t h[b,t,128:]*pol / sum_t pol ;  gt[b,:] = glob@W1b + b1
// grid = B, 256 threads
// ---------------------------------------------------------------------------
__global__ void __launch_bounds__(256) k2_glob(
    const float* __restrict__ policy, const float* __restrict__ W1,
    const float* __restrict__ b1)
{
    const int b = blockIdx.x;
    const int tid = threadIdx.x;
    const int lane = tid & 31, wid = tid >> 5;
    __shared__ float sred[8];
    __shared__ float sps;
    __shared__ float sglob[HALF_];

    float ps = 0.f;
    for (int t = tid; t < N_; t += 256) ps += policy[b * N_ + t];
    #pragma unroll
    for (int o = 16; o; o >>= 1) ps += __shfl_xor_sync(0xffffffffu, ps, o);
    if (lane == 0) sred[wid] = ps;
    __syncthreads();
    if (tid == 0) {
        float s = 0.f;
        #pragma unroll
        for (int w = 0; w < 8; w++) s += sred[w];
        sps = s;
    }
    __syncthreads();

    if (tid < HALF_) {
        float acc = 0.f;
        for (int t = 0; t < N_; t++)
            acc += g_h[(b * N_ + t) * C_ + HALF_ + tid] * policy[b * N_ + t];
        sglob[tid] = acc / sps;
    }
    __syncthreads();

    float g = b1[tid];
    for (int k = 0; k < HALF_; k++)
        g += sglob[k] * W1[(HALF_ + k) * C_ + tid];
    g_gt[b * C_ + tid] = g;
}

// ---------------------------------------------------------------------------
// K3a: A[b,t,:] = h[b,t,:128] @ W1[0:128] + gt[b,:]
// ---------------------------------------------------------------------------
__global__ void __launch_bounds__(256) k3a_local(const float* __restrict__ W1)
{
    __shared__ float sH[8][HALF_];
    const int tid = threadIdx.x;
    const int row0 = blockIdx.x * 8;
    const int b = row0 >> 10;  // / N_

    for (int idx = tid; idx < 8 * HALF_; idx += 256) {
        const int r = idx >> 7, k = idx & 127;
        sH[r][k] = g_h[(row0 + r) * C_ + k];
    }
    __syncthreads();

    float acc[8];
    const float g0 = g_gt[b * C_ + tid];
    #pragma unroll
    for (int r = 0; r < 8; r++) acc[r] = g0;
    for (int k = 0; k < HALF_; k++) {
        const float w = W1[k * C_ + tid];
        #pragma unroll
        for (int r = 0; r < 8; r++) acc[r] += sH[r][k] * w;
    }
    #pragma unroll
    for (int r = 0; r < 8; r++)
        g_A[(row0 + r) * C_ + tid] = acc[r];
}

// ---------------------------------------------------------------------------
// K3b: Cq[b,i,:] = query[i,b,:] @ W1[256:512].  200 rows, 8/block -> 25 blocks
// ---------------------------------------------------------------------------
__global__ void __launch_bounds__(256) k3b_query(
    const float* __restrict__ query, const float* __restrict__ W1)
{
    __shared__ float sQ[8][C_];
    const int tid = threadIdx.x;
    const int row0 = blockIdx.x * 8;

    for (int idx = tid; idx < 8 * C_; idx += 256) {
        const int r = idx >> 8, k = idx & 255;
        const int gr = row0 + r;
        const int b = gr / NQ_, i = gr % NQ_;
        sQ[r][k] = query[(i * B_ + b) * C_ + k];
    }
    __syncthreads();

    float acc[8];
    #pragma unroll
    for (int r = 0; r < 8; r++) acc[r] = 0.f;
    for (int k = 0; k < C_; k++) {
        const float w = W1[(C_ + k) * C_ + tid];
        #pragma unroll
        for (int r = 0; r < 8; r++) acc[r] += sQ[r][k] * w;
    }
    #pragma unroll
    for (int r = 0; r < 8; r++)
        g_Cq[(row0 + r) * C_ + tid] = acc[r];
}

// ---------------------------------------------------------------------------
// K4: fused   u = gelu(A[b,t]+Cq[b,i]) ; v = gelu(u@W2+b2) ; w = v@W3+b3 ;
//             out = log_softmax(w)
// grid (N/128, B*n) = (8, 200), 256 threads, 128x128 tile, 8x8 per thread.
// ---------------------------------------------------------------------------
__global__ void __launch_bounds__(256) k4_fused(
    const float* __restrict__ W2, const float* __restrict__ b2,
    const float* __restrict__ W3, const float* __restrict__ b3,
    float* __restrict__ out)
{
    __shared__ __align__(16) float sU[128 * 33];   // gelu chunk, padded
    __shared__ __align__(16) float sW[32 * 128];   // W2 chunk
    __shared__ float sC[C_];
    __shared__ float sB2[128];
    __shared__ float sW3[256];

    const int tid = threadIdx.x;
    const int bi = blockIdx.y;            // b*100 + i
    const int b = bi / NQ_;
    const int t0 = blockIdx.x * 128;
    const float* aBase = g_A + (b * N_ + t0) * C_;

    sC[tid] = g_Cq[bi * C_ + tid];
    if (tid < 128) sB2[tid] = b2[tid];
    sW3[tid] = W3[tid];                   // 128x2 = 256 elems

    const int tx = tid & 15, ty = tid >> 4;

    float acc[8][8];
    #pragma unroll
    for (int r = 0; r < 8; r++)
        #pragma unroll
        for (int c = 0; c < 8; c++) acc[r][c] = 0.f;

    for (int k0 = 0; k0 < C_; k0 += 32) {
        __syncthreads();
        #pragma unroll
        for (int idx = tid; idx < 4096; idx += 256) {
            const int t = idx >> 5, kk = idx & 31;
            const float av = aBase[t * C_ + k0 + kk] + sC[k0 + kk];
            sU[t * 33 + kk] = gelu_f(av);
        }
        #pragma unroll
        for (int idx = tid; idx < 4096; idx += 256) {
            const int kr = idx >> 7, j = idx & 127;
            sW[kr * 128 + j] = W2[(k0 + kr) * 128 + j];
        }
        __syncthreads();

        #pragma unroll
        for (int kk = 0; kk < 32; kk++) {
            float a[8];
            #pragma unroll
            for (int r = 0; r < 8; r++) a[r] = sU[(ty * 8 + r) * 33 + kk];
            const float4 bA = *(const float4*)&sW[kk * 128 + tx * 4];
            const float4 bBv = *(const float4*)&sW[kk * 128 + 64 + tx * 4];
            #pragma unroll
            for (int r = 0; r < 8; r++) {
                acc[r][0] += a[r] * bA.x;  acc[r][1] += a[r] * bA.y;
                acc[r][2] += a[r] * bA.z;  acc[r][3] += a[r] * bA.w;
                acc[r][4] += a[r] * bBv.x; acc[r][5] += a[r] * bBv.y;
                acc[r][6] += a[r] * bBv.z; acc[r][7] += a[r] * bBv.w;
            }
        }
    }

    const float b30 = b3[0], b31 = b3[1];
    #pragma unroll
    for (int r = 0; r < 8; r++) {
        float pw0 = 0.f, pw1 = 0.f;
        #pragma unroll
        for (int g = 0; g < 2; g++) {
            #pragma unroll
            for (int jj = 0; jj < 4; jj++) {
                const int j = g * 64 + tx * 4 + jj;
                float v = acc[r][g * 4 + jj] + sB2[j];
                v = gelu_f(v);
                pw0 += v * sW3[2 * j];
                pw1 += v * sW3[2 * j + 1];
            }
        }
        // reduce over the 16 tx lanes (stay within half-warp)
        #pragma unroll
        for (int o = 1; o < 16; o <<= 1) {
            pw0 += __shfl_xor_sync(0xffffffffu, pw0, o);
            pw1 += __shfl_xor_sync(0xffffffffu, pw1, o);
        }
        if (tx == 0) {
            const float w0 = pw0 + b30, w1 = pw1 + b31;
            const float m = fmaxf(w0, w1);
            const float l = m + logf(expf(w0 - m) + expf(w1 - m));
            const int t = t0 + ty * 8 + r;
            const long long o0 = ((long long)bi * N_ + t) * 2;
            out[o0]     = w0 - l;
            out[o0 + 1] = w1 - l;
        }
    }
}

// ---------------------------------------------------------------------------
extern "C" void kernel_launch(void* const* d_in, const int* in_sizes, int n_in,
                              void* d_out, int out_size)
{
    const float* x      = (const float*)d_in[0];
    const float* query  = (const float*)d_in[1];
    const float* policy = (const float*)d_in[2];
    const float* ln_g   = (const float*)d_in[3];
    const float* ln_b   = (const float*)d_in[4];
    const float* W_in   = (const float*)d_in[5];
    const float* b_in   = (const float*)d_in[6];
    const float* W1     = (const float*)d_in[7];
    const float* b1     = (const float*)d_in[8];
    const float* W2     = (const float*)d_in[9];
    const float* b2     = (const float*)d_in[10];
    const float* W3     = (const float*)d_in[11];
    const float* b3     = (const float*)d_in[12];
    float* out = (float*)d_out;

    k1_ln_gemm_gelu<<<(B_ * N_) / 8, 256>>>(x, ln_g, ln_b, W_in, b_in);
    k2_glob<<<B_, 256>>>(policy, W1, b1);
    k3a_local<<<(B_ * N_) / 8, 256>>>(W1);
    k3b_query<<<(B_ * NQ_) / 8, 256>>>(query, W1);
    k4_fused<<<dim3(N_ / 128, B_ * NQ_), 256>>>(W2, b2, W3, b3, out);
}

// round 3
// speedup vs baseline: 1.7662x; 1.7662x over previous
#include <cuda_runtime.h>
#include <math.h>
#include <stdint.h>

// Problem dims (fixed by the dataset)
#define B_  2
#define N_  1024
#define C_  256
#define NQ_ 100
#define HALF_ 128

// Scratch (device globals: no allocation allowed)
__device__ float g_h[B_ * N_ * C_];     // gelu(LN(x)@W_in + b_in)
__device__ float g_A[B_ * N_ * C_];     // local@W1a + glob@W1b + b1   (per b,t)
__device__ float g_Cq[B_ * NQ_ * C_];   // q@W1c                        (per b,i)
__device__ float g_gt[B_ * C_];         // glob@W1b + b1                (per b)

__device__ __forceinline__ float gelu_f(float x) {
    return 0.5f * x * (1.0f + erff(x * 0.70710678118654752440f));
}

__device__ __forceinline__ uint32_t f2tf32(float f) {
    uint32_t u;
    asm("cvt.rna.tf32.f32 %0, %1;" : "=r"(u) : "f"(f));
    return u;
}

__device__ __forceinline__ void mma_tf32(float* d, const uint32_t* a, const uint32_t* b) {
    asm volatile(
        "mma.sync.aligned.m16n8k8.row.col.f32.tf32.tf32.f32 "
        "{%0,%1,%2,%3}, {%4,%5,%6,%7}, {%8,%9}, {%0,%1,%2,%3};"
        : "+f"(d[0]), "+f"(d[1]), "+f"(d[2]), "+f"(d[3])
        : "r"(a[0]), "r"(a[1]), "r"(a[2]), "r"(a[3]), "r"(b[0]), "r"(b[1]));
}

// ---------------------------------------------------------------------------
// K1: h = gelu(LN(x) @ W_in + b_in).  8 rows per block, 256 threads, 3 syncs.
// ---------------------------------------------------------------------------
__global__ void __launch_bounds__(256) k1_ln_gemm_gelu(
    const float* __restrict__ x, const float* __restrict__ ln_g,
    const float* __restrict__ ln_b, const float* __restrict__ Win,
    const float* __restrict__ bin)
{
    __shared__ float sY[8][C_];
    __shared__ float sred[8][8][2];
    __shared__ float smu[8], ssc[8];
    const int tid = threadIdx.x;
    const int lane = tid & 31, wid = tid >> 5;
    const int row0 = blockIdx.x * 8;

    const float gv = ln_g[tid];
    const float bv = ln_b[tid];

    float xv[8];
    #pragma unroll
    for (int r = 0; r < 8; r++) xv[r] = x[(row0 + r) * C_ + tid];

    #pragma unroll
    for (int r = 0; r < 8; r++) {
        float s = xv[r], q = xv[r] * xv[r];
        #pragma unroll
        for (int o = 16; o; o >>= 1) {
            s += __shfl_xor_sync(0xffffffffu, s, o);
            q += __shfl_xor_sync(0xffffffffu, q, o);
        }
        if (lane == 0) { sred[r][wid][0] = s; sred[r][wid][1] = q; }
    }
    __syncthreads();
    // warp r finishes row r's stats
    if (wid < 8) {
        float s = (lane < 8) ? sred[wid][lane][0] : 0.f;
        float q = (lane < 8) ? sred[wid][lane][1] : 0.f;
        #pragma unroll
        for (int o = 4; o; o >>= 1) {
            s += __shfl_xor_sync(0xffffffffu, s, o);
            q += __shfl_xor_sync(0xffffffffu, q, o);
        }
        if (lane == 0) {
            const float mu = s * (1.0f / C_);
            const float var = q * (1.0f / C_) - mu * mu;
            smu[wid] = mu;
            ssc[wid] = rsqrtf(var + 1e-5f);
        }
    }
    __syncthreads();
    #pragma unroll
    for (int r = 0; r < 8; r++)
        sY[r][tid] = (xv[r] - smu[r]) * ssc[r] * gv + bv;
    __syncthreads();

    float acc[8];
    const float bi0 = bin[tid];
    #pragma unroll
    for (int r = 0; r < 8; r++) acc[r] = bi0;
    for (int k = 0; k < C_; k++) {
        const float w = Win[k * C_ + tid];
        #pragma unroll
        for (int r = 0; r < 8; r++) acc[r] += sY[r][k] * w;
    }
    #pragma unroll
    for (int r = 0; r < 8; r++)
        g_h[(row0 + r) * C_ + tid] = gelu_f(acc[r]);
}

// ---------------------------------------------------------------------------
// K2: glob[b] = sum_t h[b,t,128:]*pol / sum_t pol ;  gt[b,:] = glob@W1b + b1
// grid = B, 512 threads
// ---------------------------------------------------------------------------
__global__ void __launch_bounds__(512) k2_glob(
    const float* __restrict__ policy, const float* __restrict__ W1,
    const float* __restrict__ b1)
{
    const int b = blockIdx.x;
    const int tid = threadIdx.x;
    const int lane = tid & 31, wid = tid >> 5;
    __shared__ float spol[N_];
    __shared__ float sred[16];
    __shared__ float sps;
    __shared__ float sG[4][HALF_];
    __shared__ float sglob[HALF_];

    spol[tid] = policy[b * N_ + tid];
    spol[tid + 512] = policy[b * N_ + tid + 512];
    __syncthreads();

    float ps = spol[tid] + spol[tid + 512];
    #pragma unroll
    for (int o = 16; o; o >>= 1) ps += __shfl_xor_sync(0xffffffffu, ps, o);
    if (lane == 0) sred[wid] = ps;

    const int c = tid & 127;
    const int sl = tid >> 7;     // 4 slices of 256 t
    float acc = 0.f;
    for (int t = sl * 256; t < sl * 256 + 256; t++)
        acc += g_h[(b * N_ + t) * C_ + HALF_ + c] * spol[t];
    sG[sl][c] = acc;
    __syncthreads();
    if (tid == 0) {
        float s = 0.f;
        #pragma unroll
        for (int w = 0; w < 16; w++) s += sred[w];
        sps = s;
    }
    __syncthreads();
    if (tid < HALF_)
        sglob[tid] = (sG[0][tid] + sG[1][tid] + sG[2][tid] + sG[3][tid]) / sps;
    __syncthreads();

    if (tid < C_) {
        float g = b1[tid];
        for (int k = 0; k < HALF_; k++)
            g += sglob[k] * W1[(HALF_ + k) * C_ + tid];
        g_gt[b * C_ + tid] = g;
    }
}

// ---------------------------------------------------------------------------
// K3a: A[b,t,:] = h[b,t,:128] @ W1[0:128] + gt[b,:]
// ---------------------------------------------------------------------------
__global__ void __launch_bounds__(256) k3a_local(const float* __restrict__ W1)
{
    __shared__ float sH[8][HALF_];
    const int tid = threadIdx.x;
    const int row0 = blockIdx.x * 8;
    const int b = row0 >> 10;  // / N_

    for (int idx = tid; idx < 8 * HALF_; idx += 256) {
        const int r = idx >> 7, k = idx & 127;
        sH[r][k] = g_h[(row0 + r) * C_ + k];
    }
    __syncthreads();

    float acc[8];
    const float g0 = g_gt[b * C_ + tid];
    #pragma unroll
    for (int r = 0; r < 8; r++) acc[r] = g0;
    for (int k = 0; k < HALF_; k++) {
        const float w = W1[k * C_ + tid];
        #pragma unroll
        for (int r = 0; r < 8; r++) acc[r] += sH[r][k] * w;
    }
    #pragma unroll
    for (int r = 0; r < 8; r++)
        g_A[(row0 + r) * C_ + tid] = acc[r];
}

// ---------------------------------------------------------------------------
// K3b: Cq[b,i,:] = query[i,b,:] @ W1[256:512].  One block per (b,i) -> 200 CTAs.
// ---------------------------------------------------------------------------
__global__ void __launch_bounds__(256) k3b_query(
    const float* __restrict__ query, const float* __restrict__ W1)
{
    __shared__ float sQ[C_];
    const int tid = threadIdx.x;
    const int bi = blockIdx.x;
    const int b = bi / NQ_, i = bi % NQ_;

    sQ[tid] = query[(i * B_ + b) * C_ + tid];
    __syncthreads();

    float acc = 0.f;
    for (int k = 0; k < C_; k++)
        acc += sQ[k] * W1[(C_ + k) * C_ + tid];
    g_Cq[bi * C_ + tid] = acc;
}

// ---------------------------------------------------------------------------
// K4: fused   u = gelu(A[b,t]+Cq[b,i]) ; v = gelu(u@W2+b2) ; w = v@W3+b3 ;
//             out = log_softmax(w)
// tf32 tensor-core version. grid (8, 200), 256 threads = 8 warps (2x4 tiling),
// block tile 128(t) x 128(j), K=256 in chunks of 32.
// ---------------------------------------------------------------------------
__global__ void __launch_bounds__(256) k4_mma(
    const float* __restrict__ W2, const float* __restrict__ b2,
    const float* __restrict__ W3, const float* __restrict__ b3,
    float* __restrict__ out)
{
    __shared__ uint32_t sU[128 * 36];    // gelu(A+C) chunk, tf32 bits, pad 36
    __shared__ uint32_t sWt[128 * 36];   // W2 chunk transposed [j][k], tf32 bits
    __shared__ float sC[C_];
    __shared__ float sB2[128];
    __shared__ float sW3[256];
    __shared__ float sPW[4][128][2];

    const int tid = threadIdx.x;
    const int lane = tid & 31, warp = tid >> 5;
    const int wm = warp >> 2, wn = warp & 3;  // 2x4 warp grid
    const int g = lane >> 2, tig = lane & 3;

    const int bi = blockIdx.y;            // b*100 + i
    const int b = bi / NQ_;
    const int t0 = blockIdx.x * 128;
    const float* aBase = g_A + (b * N_ + t0) * C_;

    sC[tid] = g_Cq[bi * C_ + tid];
    if (tid < 128) sB2[tid] = b2[tid];
    sW3[tid] = W3[tid];

    float acc[4][4][4];
    #pragma unroll
    for (int mi = 0; mi < 4; mi++)
        #pragma unroll
        for (int ni = 0; ni < 4; ni++)
            #pragma unroll
            for (int q = 0; q < 4; q++) acc[mi][ni][q] = 0.f;

    for (int k0 = 0; k0 < C_; k0 += 32) {
        __syncthreads();
        #pragma unroll
        for (int idx = tid; idx < 4096; idx += 256) {
            const int t = idx >> 5, kk = idx & 31;
            const float av = aBase[t * C_ + k0 + kk] + sC[k0 + kk];
            sU[t * 36 + kk] = f2tf32(gelu_f(av));
        }
        #pragma unroll
        for (int idx = tid; idx < 4096; idx += 256) {
            const int j = idx & 127, kk = idx >> 7;
            sWt[j * 36 + kk] = f2tf32(W2[(k0 + kk) * 128 + j]);
        }
        __syncthreads();

        #pragma unroll
        for (int ks = 0; ks < 32; ks += 8) {
            uint32_t af[4][4], bf[4][2];
            #pragma unroll
            for (int mi = 0; mi < 4; mi++) {
                const int row = wm * 64 + mi * 16 + g;
                af[mi][0] = sU[row * 36 + ks + tig];
                af[mi][1] = sU[(row + 8) * 36 + ks + tig];
                af[mi][2] = sU[row * 36 + ks + tig + 4];
                af[mi][3] = sU[(row + 8) * 36 + ks + tig + 4];
            }
            #pragma unroll
            for (int ni = 0; ni < 4; ni++) {
                const int j = wn * 32 + ni * 8 + g;
                bf[ni][0] = sWt[j * 36 + ks + tig];
                bf[ni][1] = sWt[j * 36 + ks + tig + 4];
            }
            #pragma unroll
            for (int mi = 0; mi < 4; mi++)
                #pragma unroll
                for (int ni = 0; ni < 4; ni++)
                    mma_tf32(acc[mi][ni], af[mi], bf[ni]);
        }
    }

    // Epilogue: v = gelu(acc + b2), partial w = v @ W3 per warp, reduce.
    #pragma unroll
    for (int mi = 0; mi < 4; mi++) {
        float p00 = 0.f, p01 = 0.f, p10 = 0.f, p11 = 0.f;
        #pragma unroll
        for (int ni = 0; ni < 4; ni++) {
            const int jb = wn * 32 + ni * 8 + tig * 2;
            const float v0 = gelu_f(acc[mi][ni][0] + sB2[jb]);
            const float v1 = gelu_f(acc[mi][ni][1] + sB2[jb + 1]);
            const float v2 = gelu_f(acc[mi][ni][2] + sB2[jb]);
            const float v3 = gelu_f(acc[mi][ni][3] + sB2[jb + 1]);
            p00 += v0 * sW3[2 * jb]     + v1 * sW3[2 * jb + 2];
            p01 += v0 * sW3[2 * jb + 1] + v1 * sW3[2 * jb + 3];
            p10 += v2 * sW3[2 * jb]     + v3 * sW3[2 * jb + 2];
            p11 += v2 * sW3[2 * jb + 1] + v3 * sW3[2 * jb + 3];
        }
        #pragma unroll
        for (int o = 1; o < 4; o <<= 1) {
            p00 += __shfl_xor_sync(0xffffffffu, p00, o);
            p01 += __shfl_xor_sync(0xffffffffu, p01, o);
            p10 += __shfl_xor_sync(0xffffffffu, p10, o);
            p11 += __shfl_xor_sync(0xffffffffu, p11, o);
        }
        if (tig == 0) {
            const int r0 = wm * 64 + mi * 16 + g;
            sPW[wn][r0][0] = p00;  sPW[wn][r0][1] = p01;
            sPW[wn][r0 + 8][0] = p10;  sPW[wn][r0 + 8][1] = p11;
        }
    }
    __syncthreads();

    if (tid < 128) {
        float w0 = b3[0], w1 = b3[1];
        #pragma unroll
        for (int w = 0; w < 4; w++) {
            w0 += sPW[w][tid][0];
            w1 += sPW[w][tid][1];
        }
        const float m = fmaxf(w0, w1);
        const float l = m + logf(expf(w0 - m) + expf(w1 - m));
        const int t = t0 + tid;
        const long long o0 = ((long long)bi * N_ + t) * 2;
        out[o0]     = w0 - l;
        out[o0 + 1] = w1 - l;
    }
}

// ---------------------------------------------------------------------------
extern "C" void kernel_launch(void* const* d_in, const int* in_sizes, int n_in,
                              void* d_out, int out_size)
{
    const float* x      = (const float*)d_in[0];
    const float* query  = (const float*)d_in[1];
    const float* policy = (const float*)d_in[2];
    const float* ln_g   = (const float*)d_in[3];
    const float* ln_b   = (const float*)d_in[4];
    const float* W_in   = (const float*)d_in[5];
    const float* b_in   = (const float*)d_in[6];
    const float* W1     = (const float*)d_in[7];
    const float* b1     = (const float*)d_in[8];
    const float* W2     = (const float*)d_in[9];
    const float* b2     = (const float*)d_in[10];
    const float* W3     = (const float*)d_in[11];
    const float* b3     = (const float*)d_in[12];
    float* out = (float*)d_out;

    k1_ln_gemm_gelu<<<(B_ * N_) / 8, 256>>>(x, ln_g, ln_b, W_in, b_in);
    k2_glob<<<B_, 512>>>(policy, W1, b1);
    k3a_local<<<(B_ * N_) / 8, 256>>>(W1);
    k3b_query<<<B_ * NQ_, 256>>>(query, W1);
    k4_mma<<<dim3(N_ / 128, B_ * NQ_), 256>>>(W2, b2, W3, b3, out);
}

// round 4
// speedup vs baseline: 2.4268x; 1.3740x over previous
#include <cuda_runtime.h>
#include <math.h>
#include <stdint.h>

// Problem dims (fixed by the dataset)
#define B_  2
#define N_  1024
#define C_  256
#define NQ_ 100
#define HALF_ 128

// Scratch (device globals: no allocation allowed)
__device__ float g_A[B_ * N_ * C_];        // h_loc @ W1a           (per b,t)
__device__ float g_hg[B_ * N_ * HALF_];    // h glob half           (per b,t)
__device__ float g_Cq[B_ * NQ_ * C_];      // q@W1c + gt            (per b,i)
__device__ float g_gt[B_ * C_];            // glob@W1b + b1         (per b)
__device__ uint32_t g_W2t[HALF_ * C_];     // W2 transposed [j][k], tf32 bits

__device__ __forceinline__ float gelu_f(float x) {
    return 0.5f * x * (1.0f + erff(x * 0.70710678118654752440f));
}

__device__ __forceinline__ uint32_t f2tf32(float f) {
    uint32_t u;
    asm("cvt.rna.tf32.f32 %0, %1;" : "=r"(u) : "f"(f));
    return u;
}

__device__ __forceinline__ void mma_tf32(float* d, const uint32_t* a, const uint32_t* b) {
    asm volatile(
        "mma.sync.aligned.m16n8k8.row.col.f32.tf32.tf32.f32 "
        "{%0,%1,%2,%3}, {%4,%5,%6,%7}, {%8,%9}, {%0,%1,%2,%3};"
        : "+f"(d[0]), "+f"(d[1]), "+f"(d[2]), "+f"(d[3])
        : "r"(a[0]), "r"(a[1]), "r"(a[2]), "r"(a[3]), "r"(b[0]), "r"(b[1]));
}

// ---------------------------------------------------------------------------
// K0: W2t[j][k] = tf32(W2[k][j])
// ---------------------------------------------------------------------------
__global__ void __launch_bounds__(256) k0_w2t(const float* __restrict__ W2)
{
    const int j = blockIdx.x;        // 0..127
    const int k = threadIdx.x;       // 0..255
    g_W2t[j * C_ + k] = f2tf32(W2[k * HALF_ + j]);
}

// ---------------------------------------------------------------------------
// K1: h = gelu(LN(x) @ W_in + b_in);  also A_loc = h[:, :128] @ W1[0:128]
//     and stores the glob half of h. 8 rows per block, 256 threads.
// ---------------------------------------------------------------------------
__global__ void __launch_bounds__(256) k1_ln_gemm_gelu(
    const float* __restrict__ x, const float* __restrict__ ln_g,
    const float* __restrict__ ln_b, const float* __restrict__ Win,
    const float* __restrict__ bin, const float* __restrict__ W1)
{
    __shared__ float sY[8][C_];
    __shared__ float sred[8][8][2];
    __shared__ float smu[8], ssc[8];
    const int tid = threadIdx.x;
    const int lane = tid & 31, wid = tid >> 5;
    const int row0 = blockIdx.x * 8;

    const float gv = ln_g[tid];
    const float bv = ln_b[tid];

    float xv[8];
    #pragma unroll
    for (int r = 0; r < 8; r++) xv[r] = x[(row0 + r) * C_ + tid];

    #pragma unroll
    for (int r = 0; r < 8; r++) {
        float s = xv[r], q = xv[r] * xv[r];
        #pragma unroll
        for (int o = 16; o; o >>= 1) {
            s += __shfl_xor_sync(0xffffffffu, s, o);
            q += __shfl_xor_sync(0xffffffffu, q, o);
        }
        if (lane == 0) { sred[r][wid][0] = s; sred[r][wid][1] = q; }
    }
    __syncthreads();
    if (wid < 8) {
        float s = (lane < 8) ? sred[wid][lane][0] : 0.f;
        float q = (lane < 8) ? sred[wid][lane][1] : 0.f;
        #pragma unroll
        for (int o = 4; o; o >>= 1) {
            s += __shfl_xor_sync(0xffffffffu, s, o);
            q += __shfl_xor_sync(0xffffffffu, q, o);
        }
        if (lane == 0) {
            const float mu = s * (1.0f / C_);
            const float var = q * (1.0f / C_) - mu * mu;
            smu[wid] = mu;
            ssc[wid] = rsqrtf(var + 1e-5f);
        }
    }
    __syncthreads();
    #pragma unroll
    for (int r = 0; r < 8; r++)
        sY[r][tid] = (xv[r] - smu[r]) * ssc[r] * gv + bv;
    __syncthreads();

    float acc[8];
    const float bi0 = bin[tid];
    #pragma unroll
    for (int r = 0; r < 8; r++) acc[r] = bi0;
    for (int k = 0; k < C_; k++) {
        const float w = Win[k * C_ + tid];
        #pragma unroll
        for (int r = 0; r < 8; r++) acc[r] += sY[r][k] * w;
    }
    #pragma unroll
    for (int r = 0; r < 8; r++) acc[r] = gelu_f(acc[r]);

    // stash h: local half to smem (reuse sY), glob half to gmem
    __syncthreads();
    float (*sHl)[HALF_] = (float (*)[HALF_])sY;
    if (tid < HALF_) {
        #pragma unroll
        for (int r = 0; r < 8; r++) sHl[r][tid] = acc[r];
    } else {
        #pragma unroll
        for (int r = 0; r < 8; r++)
            g_hg[(row0 + r) * HALF_ + tid - HALF_] = acc[r];
    }
    __syncthreads();

    // A_loc = h_loc @ W1[0:128]
    float a2[8];
    #pragma unroll
    for (int r = 0; r < 8; r++) a2[r] = 0.f;
    for (int k = 0; k < HALF_; k++) {
        const float w = W1[k * C_ + tid];
        #pragma unroll
        for (int r = 0; r < 8; r++) a2[r] += sHl[r][k] * w;
    }
    #pragma unroll
    for (int r = 0; r < 8; r++)
        g_A[(row0 + r) * C_ + tid] = a2[r];
}

// ---------------------------------------------------------------------------
// K2: glob[b] = sum_t hg[b,t]*pol / sum_t pol ;  gt[b,:] = glob@W1b + b1
// ---------------------------------------------------------------------------
__global__ void __launch_bounds__(512) k2_glob(
    const float* __restrict__ policy, const float* __restrict__ W1,
    const float* __restrict__ b1)
{
    const int b = blockIdx.x;
    const int tid = threadIdx.x;
    const int lane = tid & 31, wid = tid >> 5;
    __shared__ float spol[N_];
    __shared__ float sred[16];
    __shared__ float sps;
    __shared__ float sG[4][HALF_];
    __shared__ float sglob[HALF_];

    spol[tid] = policy[b * N_ + tid];
    spol[tid + 512] = policy[b * N_ + tid + 512];
    __syncthreads();

    float ps = spol[tid] + spol[tid + 512];
    #pragma unroll
    for (int o = 16; o; o >>= 1) ps += __shfl_xor_sync(0xffffffffu, ps, o);
    if (lane == 0) sred[wid] = ps;

    const int c = tid & 127;
    const int sl = tid >> 7;     // 4 slices of 256 t
    float acc = 0.f;
    for (int t = sl * 256; t < sl * 256 + 256; t++)
        acc += g_hg[(b * N_ + t) * HALF_ + c] * spol[t];
    sG[sl][c] = acc;
    __syncthreads();
    if (tid == 0) {
        float s = 0.f;
        #pragma unroll
        for (int w = 0; w < 16; w++) s += sred[w];
        sps = s;
    }
    __syncthreads();
    if (tid < HALF_)
        sglob[tid] = (sG[0][tid] + sG[1][tid] + sG[2][tid] + sG[3][tid]) / sps;
    __syncthreads();

    if (tid < C_) {
        float g = b1[tid];
        for (int k = 0; k < HALF_; k++)
            g += sglob[k] * W1[(HALF_ + k) * C_ + tid];
        g_gt[b * C_ + tid] = g;
    }
}

// ---------------------------------------------------------------------------
// K3b: Cq[b,i,:] = query[i,b,:] @ W1[256:512] + gt[b,:]
// ---------------------------------------------------------------------------
__global__ void __launch_bounds__(256) k3b_query(
    const float* __restrict__ query, const float* __restrict__ W1)
{
    __shared__ float sQ[C_];
    const int tid = threadIdx.x;
    const int bi = blockIdx.x;
    const int b = bi / NQ_, i = bi % NQ_;

    sQ[tid] = query[(i * B_ + b) * C_ + tid];
    __syncthreads();

    float a0 = 0.f, a1 = 0.f, a2 = 0.f, a3 = 0.f;
    #pragma unroll 4
    for (int k = 0; k < C_; k += 4) {
        a0 += sQ[k]     * W1[(C_ + k)     * C_ + tid];
        a1 += sQ[k + 1] * W1[(C_ + k + 1) * C_ + tid];
        a2 += sQ[k + 2] * W1[(C_ + k + 2) * C_ + tid];
        a3 += sQ[k + 3] * W1[(C_ + k + 3) * C_ + tid];
    }
    g_Cq[bi * C_ + tid] = (a0 + a1) + (a2 + a3) + g_gt[b * C_ + tid];
}

// ---------------------------------------------------------------------------
// K4: fused  u = gelu(Aloc[b,t]+D[b,i]) ; v = gelu(u@W2+b2) ; w = v@W3+b3 ;
//            out = log_softmax(w)
// tf32 mma, double-buffered smem pipeline. grid (8, 200), 256 thr = 8 warps.
// ---------------------------------------------------------------------------
#define K4_STRIDE 36
#define K4_BUF    (128 * K4_STRIDE)

__global__ void __launch_bounds__(256, 2) k4_mma(
    const float* __restrict__ b2v,
    const float* __restrict__ W3, const float* __restrict__ b3,
    float* __restrict__ out)
{
    extern __shared__ uint32_t dyn[];
    uint32_t* sU  = dyn;                // [2][128*36] gelu tile, tf32 bits
    uint32_t* sWt = dyn + 2 * K4_BUF;   // [2][128*36] W2t chunk

    __shared__ __align__(16) float sC[C_];
    __shared__ float sB2[HALF_];
    __shared__ float sW3[2 * HALF_];
    __shared__ float sPW[4][HALF_][2];

    const int tid = threadIdx.x;
    const int lane = tid & 31, warp = tid >> 5;
    const int wm = warp >> 2, wn = warp & 3;  // 2x4 warp grid
    const int g = lane >> 2, tig = lane & 3;

    const int bi = blockIdx.y;            // b*100 + i
    const int b = bi / NQ_;
    const int t0 = blockIdx.x * 128;
    const float* aBase = g_A + (b * N_ + t0) * C_;

    sC[tid] = g_Cq[bi * C_ + tid];
    if (tid < HALF_) sB2[tid] = b2v[tid];
    sW3[tid] = W3[tid];

    float acc[4][4][4];
    #pragma unroll
    for (int mi = 0; mi < 4; mi++)
        #pragma unroll
        for (int ni = 0; ni < 4; ni++)
            #pragma unroll
            for (int q = 0; q < 4; q++) acc[mi][ni][q] = 0.f;
    __syncthreads();   // sC ready before first fill

    // fill chunk 0 into buffer 0
    {
        #pragma unroll
        for (int i = 0; i < 4; i++) {
            const int idx = tid + i * 256;
            const int t = idx >> 3, kk = (idx & 7) * 4;
            const float4 av = *(const float4*)(aBase + t * C_ + kk);
            const float4 cv = *(const float4*)(sC + kk);
            uint4 u;
            u.x = f2tf32(gelu_f(av.x + cv.x));
            u.y = f2tf32(gelu_f(av.y + cv.y));
            u.z = f2tf32(gelu_f(av.z + cv.z));
            u.w = f2tf32(gelu_f(av.w + cv.w));
            *(uint4*)(sU + t * K4_STRIDE + kk) = u;
        }
        #pragma unroll
        for (int i = 0; i < 4; i++) {
            const int idx = tid + i * 256;
            const int j = idx >> 3, kk = (idx & 7) * 4;
            *(uint4*)(sWt + j * K4_STRIDE + kk) =
                *(const uint4*)(g_W2t + j * C_ + kk);
        }
    }
    __syncthreads();

    for (int c = 0; c < 8; c++) {
        const uint32_t* bU  = sU  + (c & 1) * K4_BUF;
        const uint32_t* bW  = sWt + (c & 1) * K4_BUF;

        #pragma unroll
        for (int ks = 0; ks < 32; ks += 8) {
            uint32_t af[4][4], bf[4][2];
            #pragma unroll
            for (int mi = 0; mi < 4; mi++) {
                const int row = wm * 64 + mi * 16 + g;
                af[mi][0] = bU[row * K4_STRIDE + ks + tig];
                af[mi][1] = bU[(row + 8) * K4_STRIDE + ks + tig];
                af[mi][2] = bU[row * K4_STRIDE + ks + tig + 4];
                af[mi][3] = bU[(row + 8) * K4_STRIDE + ks + tig + 4];
            }
            #pragma unroll
            for (int ni = 0; ni < 4; ni++) {
                const int j = wn * 32 + ni * 8 + g;
                bf[ni][0] = bW[j * K4_STRIDE + ks + tig];
                bf[ni][1] = bW[j * K4_STRIDE + ks + tig + 4];
            }
            #pragma unroll
            for (int mi = 0; mi < 4; mi++)
                #pragma unroll
                for (int ni = 0; ni < 4; ni++)
                    mma_tf32(acc[mi][ni], af[mi], bf[ni]);
        }

        if (c < 7) {
            const int k0 = (c + 1) * 32;
            uint32_t* nU = sU  + ((c + 1) & 1) * K4_BUF;
            uint32_t* nW = sWt + ((c + 1) & 1) * K4_BUF;
            #pragma unroll
            for (int i = 0; i < 4; i++) {
                const int idx = tid + i * 256;
                const int t = idx >> 3, kk = (idx & 7) * 4;
                const float4 av = *(const float4*)(aBase + t * C_ + k0 + kk);
                const float4 cv = *(const float4*)(sC + k0 + kk);
                uint4 u;
                u.x = f2tf32(gelu_f(av.x + cv.x));
                u.y = f2tf32(gelu_f(av.y + cv.y));
                u.z = f2tf32(gelu_f(av.z + cv.z));
                u.w = f2tf32(gelu_f(av.w + cv.w));
                *(uint4*)(nU + t * K4_STRIDE + kk) = u;
            }
            #pragma unroll
            for (int i = 0; i < 4; i++) {
                const int idx = tid + i * 256;
                const int j = idx >> 3, kk = (idx & 7) * 4;
                *(uint4*)(nW + j * K4_STRIDE + kk) =
                    *(const uint4*)(g_W2t + j * C_ + k0 + kk);
            }
        }
        __syncthreads();
    }

    // Epilogue: v = gelu(acc + b2), partial w = v @ W3 per warp, reduce.
    #pragma unroll
    for (int mi = 0; mi < 4; mi++) {
        float p00 = 0.f, p01 = 0.f, p10 = 0.f, p11 = 0.f;
        #pragma unroll
        for (int ni = 0; ni < 4; ni++) {
            const int jb = wn * 32 + ni * 8 + tig * 2;
            const float v0 = gelu_f(acc[mi][ni][0] + sB2[jb]);
            const float v1 = gelu_f(acc[mi][ni][1] + sB2[jb + 1]);
            const float v2 = gelu_f(acc[mi][ni][2] + sB2[jb]);
            const float v3 = gelu_f(acc[mi][ni][3] + sB2[jb + 1]);
            p00 += v0 * sW3[2 * jb]     + v1 * sW3[2 * jb + 2];
            p01 += v0 * sW3[2 * jb + 1] + v1 * sW3[2 * jb + 3];
            p10 += v2 * sW3[2 * jb]     + v3 * sW3[2 * jb + 2];
            p11 += v2 * sW3[2 * jb + 1] + v3 * sW3[2 * jb + 3];
        }
        #pragma unroll
        for (int o = 1; o < 4; o <<= 1) {
            p00 += __shfl_xor_sync(0xffffffffu, p00, o);
            p01 += __shfl_xor_sync(0xffffffffu, p01, o);
            p10 += __shfl_xor_sync(0xffffffffu, p10, o);
            p11 += __shfl_xor_sync(0xffffffffu, p11, o);
        }
        if (tig == 0) {
            const int r0 = wm * 64 + mi * 16 + g;
            sPW[wn][r0][0] = p00;  sPW[wn][r0][1] = p01;
            sPW[wn][r0 + 8][0] = p10;  sPW[wn][r0 + 8][1] = p11;
        }
    }
    __syncthreads();

    if (tid < 128) {
        float w0 = b3[0], w1 = b3[1];
        #pragma unroll
        for (int w = 0; w < 4; w++) {
            w0 += sPW[w][tid][0];
            w1 += sPW[w][tid][1];
        }
        const float m = fmaxf(w0, w1);
        const float l = m + logf(expf(w0 - m) + expf(w1 - m));
        const int t = t0 + tid;
        const long long o0 = ((long long)bi * N_ + t) * 2;
        out[o0]     = w0 - l;
        out[o0 + 1] = w1 - l;
    }
}

// ---------------------------------------------------------------------------
extern "C" void kernel_launch(void* const* d_in, const int* in_sizes, int n_in,
                              void* d_out, int out_size)
{
    const float* x      = (const float*)d_in[0];
    const float* query  = (const float*)d_in[1];
    const float* policy = (const float*)d_in[2];
    const float* ln_g   = (const float*)d_in[3];
    const float* ln_b   = (const float*)d_in[4];
    const float* W_in   = (const float*)d_in[5];
    const float* b_in   = (const float*)d_in[6];
    const float* W1     = (const float*)d_in[7];
    const float* b1     = (const float*)d_in[8];
    const float* W2     = (const float*)d_in[9];
    const float* b2     = (const float*)d_in[10];
    const float* W3     = (const float*)d_in[11];
    const float* b3     = (const float*)d_in[12];
    float* out = (float*)d_out;

    static int smem_set = 0;
    const int dyn_bytes = 4 * K4_BUF * (int)sizeof(uint32_t);  // 73728
    if (!smem_set) {
        cudaFuncSetAttribute(k4_mma, cudaFuncAttributeMaxDynamicSharedMemorySize,
                             dyn_bytes);
        smem_set = 1;
    }

    k0_w2t<<<HALF_, 256>>>(W2);
    k1_ln_gemm_gelu<<<(B_ * N_) / 8, 256>>>(x, ln_g, ln_b, W_in, b_in, W1);
    k2_glob<<<B_, 512>>>(policy, W1, b1);
    k3b_query<<<B_ * NQ_, 256>>>(query, W1);
    k4_mma<<<dim3(N_ / 128, B_ * NQ_), 256, dyn_bytes>>>(b2, W3, b3, out);
}

// round 7
// speedup vs baseline: 2.7642x; 1.1391x over previous
#include <cuda_runtime.h>
#include <math.h>
#include <stdint.h>
#include <cuda_fp16.h>

// Problem dims (fixed by the dataset)
#define B_  2
#define N_  1024
#define C_  256
#define NQ_ 100
#define HALF_ 128

// Scratch (device globals: no allocation allowed)
__device__ float  g_A[B_ * N_ * C_];       // h_loc @ W1a          (per b,t)
__device__ float  g_hg[B_ * N_ * HALF_];   // h glob half          (per b,t)
__device__ float  g_Cq[B_ * NQ_ * C_];     // q@W1c                (per b,i)
__device__ float  g_gt[B_ * C_];           // glob@W1b + b1        (per b)
__device__ __half g_W2h[HALF_ * C_];       // W2 transposed [j][k], fp16

__device__ __forceinline__ float gelu_f(float x) {
    return 0.5f * x * (1.0f + erff(x * 0.70710678118654752440f));
}

__device__ __forceinline__ uint32_t f2h2(float a, float b) {
    __half2 h = __floats2half2_rn(a, b);
    return *reinterpret_cast<uint32_t*>(&h);
}

__device__ __forceinline__ void mma_f16(float* d, const uint32_t* a, const uint32_t* b) {
    asm volatile(
        "mma.sync.aligned.m16n8k16.row.col.f32.f16.f16.f32 "
        "{%0,%1,%2,%3}, {%4,%5,%6,%7}, {%8,%9}, {%0,%1,%2,%3};"
        : "+f"(d[0]), "+f"(d[1]), "+f"(d[2]), "+f"(d[3])
        : "r"(a[0]), "r"(a[1]), "r"(a[2]), "r"(a[3]), "r"(b[0]), "r"(b[1]));
}

// ---------------------------------------------------------------------------
// K1: h = gelu(LN(x) @ W_in + b_in);  also A_loc = h[:, :128] @ W1[0:128]
// (proven version from the 197us kernel)
// ---------------------------------------------------------------------------
__global__ void __launch_bounds__(256) k1_ln_gemm_gelu(
    const float* __restrict__ x, const float* __restrict__ ln_g,
    const float* __restrict__ ln_b, const float* __restrict__ Win,
    const float* __restrict__ bin, const float* __restrict__ W1)
{
    __shared__ float sY[8][C_];
    __shared__ float sred[8][8][2];
    __shared__ float smu[8], ssc[8];
    const int tid = threadIdx.x;
    const int lane = tid & 31, wid = tid >> 5;
    const int row0 = blockIdx.x * 8;

    const float gv = ln_g[tid];
    const float bv = ln_b[tid];

    float xv[8];
    #pragma unroll
    for (int r = 0; r < 8; r++) xv[r] = x[(row0 + r) * C_ + tid];

    #pragma unroll
    for (int r = 0; r < 8; r++) {
        float s = xv[r], q = xv[r] * xv[r];
        #pragma unroll
        for (int o = 16; o; o >>= 1) {
            s += __shfl_xor_sync(0xffffffffu, s, o);
            q += __shfl_xor_sync(0xffffffffu, q, o);
        }
        if (lane == 0) { sred[r][wid][0] = s; sred[r][wid][1] = q; }
    }
    __syncthreads();
    if (wid < 8) {
        float s = (lane < 8) ? sred[wid][lane][0] : 0.f;
        float q = (lane < 8) ? sred[wid][lane][1] : 0.f;
        #pragma unroll
        for (int o = 4; o; o >>= 1) {
            s += __shfl_xor_sync(0xffffffffu, s, o);
            q += __shfl_xor_sync(0xffffffffu, q, o);
        }
        if (lane == 0) {
            const float mu = s * (1.0f / C_);
            const float var = q * (1.0f / C_) - mu * mu;
            smu[wid] = mu;
            ssc[wid] = rsqrtf(var + 1e-5f);
        }
    }
    __syncthreads();
    #pragma unroll
    for (int r = 0; r < 8; r++)
        sY[r][tid] = (xv[r] - smu[r]) * ssc[r] * gv + bv;
    __syncthreads();

    float acc[8];
    const float bi0 = bin[tid];
    #pragma unroll
    for (int r = 0; r < 8; r++) acc[r] = bi0;
    for (int k = 0; k < C_; k++) {
        const float w = Win[k * C_ + tid];
        #pragma unroll
        for (int r = 0; r < 8; r++) acc[r] += sY[r][k] * w;
    }
    #pragma unroll
    for (int r = 0; r < 8; r++) acc[r] = gelu_f(acc[r]);

    __syncthreads();
    float (*sHl)[HALF_] = (float (*)[HALF_])sY;
    if (tid < HALF_) {
        #pragma unroll
        for (int r = 0; r < 8; r++) sHl[r][tid] = acc[r];
    } else {
        #pragma unroll
        for (int r = 0; r < 8; r++)
            g_hg[(row0 + r) * HALF_ + tid - HALF_] = acc[r];
    }
    __syncthreads();

    float a2[8];
    #pragma unroll
    for (int r = 0; r < 8; r++) a2[r] = 0.f;
    for (int k = 0; k < HALF_; k++) {
        const float w = W1[k * C_ + tid];
        #pragma unroll
        for (int r = 0; r < 8; r++) a2[r] += sHl[r][k] * w;
    }
    #pragma unroll
    for (int r = 0; r < 8; r++)
        g_A[(row0 + r) * C_ + tid] = a2[r];
}

// ---------------------------------------------------------------------------
// K23: combined prologue.  grid = 218 CTAs x 256 thr.
//   blocks 0..199   : Cq[b,i,:] = query[i,b,:] @ W1[256:512]
//   blocks 200..201 : glob + gt (needs g_hg from k1)
//   blocks 202..217 : W2h transpose to fp16
// ---------------------------------------------------------------------------
__global__ void __launch_bounds__(256) k23_pre(
    const float* __restrict__ query, const float* __restrict__ W1,
    const float* __restrict__ policy, const float* __restrict__ b1,
    const float* __restrict__ W2)
{
    const int blk = blockIdx.x;
    const int tid = threadIdx.x;

    if (blk < 200) {
        __shared__ float sQ[C_];
        const int b = blk / NQ_, i = blk % NQ_;
        sQ[tid] = query[(i * B_ + b) * C_ + tid];
        __syncthreads();

        float a[8];
        #pragma unroll
        for (int u = 0; u < 8; u++) a[u] = 0.f;
        #pragma unroll 4
        for (int k = 0; k < C_; k += 8) {
            #pragma unroll
            for (int u = 0; u < 8; u++)
                a[u] += sQ[k + u] * W1[(C_ + k + u) * C_ + tid];
        }
        g_Cq[blk * C_ + tid] =
            ((a[0] + a[1]) + (a[2] + a[3])) + ((a[4] + a[5]) + (a[6] + a[7]));
    } else if (blk < 202) {
        const int b = blk - 200;
        const int lane = tid & 31, wid = tid >> 5;
        __shared__ float spol[N_];
        __shared__ float sred[8];
        __shared__ float sps;
        __shared__ float sG[2][HALF_];
        __shared__ float sglob[HALF_];

        float ps = 0.f;
        #pragma unroll
        for (int i = 0; i < 4; i++) {
            const float p = policy[b * N_ + tid + i * 256];
            spol[tid + i * 256] = p;
            ps += p;
        }
        #pragma unroll
        for (int o = 16; o; o >>= 1) ps += __shfl_xor_sync(0xffffffffu, ps, o);
        if (lane == 0) sred[wid] = ps;
        __syncthreads();

        const int c = tid & 127, hf = tid >> 7;
        float acc = 0.f;
        for (int t = hf * 512; t < hf * 512 + 512; t++)
            acc += g_hg[(b * N_ + t) * HALF_ + c] * spol[t];
        sG[hf][c] = acc;
        if (tid == 0) {
            float s = 0.f;
            #pragma unroll
            for (int w = 0; w < 8; w++) s += sred[w];
            sps = s;
        }
        __syncthreads();
        if (tid < HALF_)
            sglob[tid] = (sG[0][tid] + sG[1][tid]) / sps;
        __syncthreads();

        float g = b1[tid];
        for (int k = 0; k < HALF_; k++)
            g += sglob[k] * W1[(HALF_ + k) * C_ + tid];
        g_gt[b * C_ + tid] = g;
    } else {
        const int base = (blk - 202) * 2048;
        #pragma unroll
        for (int i = 0; i < 8; i++) {
            const int lin = base + i * 256 + tid;   // index into W2 [k][j]
            const int k = lin >> 7, j = lin & 127;
            g_W2h[j * C_ + k] = __float2half_rn(W2[lin]);
        }
    }
}

// ---------------------------------------------------------------------------
// K4: fused  u = gelu(Aloc[b,t]+Cq[b,i]+gt[b]) ; v = gelu(u@W2+b2) ;
//            w = v@W3+b3 ; out = log_softmax(w)
// fp16 mma.sync m16n8k16, fp32 accum. Double-buffered K-chunks of 64.
// grid (8, 200), 256 threads = 8 warps (2x4 warp tile over 128x128).
// ---------------------------------------------------------------------------
#define KC  64                 // K elements per chunk
#define US  72                 // smem row stride in halves (pad 8)
#define UBUF (128 * US)        // halves per buffer

__global__ void __launch_bounds__(256, 2) k4_h16(
    const float* __restrict__ b2v,
    const float* __restrict__ W3, const float* __restrict__ b3,
    float* __restrict__ out)
{
    extern __shared__ __half dynh[];
    __half* sU = dynh;                  // [2][128*US] gelu tile (fp16)
    __half* sW = dynh + 2 * UBUF;       // [2][128*US] W2 chunk  (fp16)

    __shared__ __align__(16) float sC[C_];
    __shared__ float sB2[HALF_];
    __shared__ float sW3[2 * HALF_];
    __shared__ float sPW[4][HALF_][2];

    const int tid = threadIdx.x;
    const int lane = tid & 31, warp = tid >> 5;
    const int wm = warp >> 2, wn = warp & 3;  // 2x4 warp grid
    const int g = lane >> 2, tig = lane & 3;

    const int bi = blockIdx.y;            // b*100 + i
    const int b = bi / NQ_;
    const int t0 = blockIdx.x * 128;
    const float* aBase = g_A + (b * N_ + t0) * C_;

    sC[tid] = g_Cq[bi * C_ + tid] + g_gt[b * C_ + tid];
    if (tid < HALF_) sB2[tid] = b2v[tid];
    sW3[tid] = W3[tid];

    float acc[4][4][4];
    #pragma unroll
    for (int mi = 0; mi < 4; mi++)
        #pragma unroll
        for (int ni = 0; ni < 4; ni++)
            #pragma unroll
            for (int q = 0; q < 4; q++) acc[mi][ni][q] = 0.f;
    __syncthreads();   // sC ready before first fill

    // fill chunk 0 into buffer 0
    {
        __half* uDst = sU;
        __half* wDst = sW;
        #pragma unroll
        for (int i = 0; i < 4; i++) {
            const int e = tid + i * 256;
            const int t = e >> 3, q = e & 7;       // q: 8-half group in [0,64)
            const float4 a0 = *(const float4*)(aBase + t * C_ + q * 8);
            const float4 a1 = *(const float4*)(aBase + t * C_ + q * 8 + 4);
            const float4 c0 = *(const float4*)(sC + q * 8);
            const float4 c1 = *(const float4*)(sC + q * 8 + 4);
            uint4 u;
            u.x = f2h2(gelu_f(a0.x + c0.x), gelu_f(a0.y + c0.y));
            u.y = f2h2(gelu_f(a0.z + c0.z), gelu_f(a0.w + c0.w));
            u.z = f2h2(gelu_f(a1.x + c1.x), gelu_f(a1.y + c1.y));
            u.w = f2h2(gelu_f(a1.z + c1.z), gelu_f(a1.w + c1.w));
            *(uint4*)(uDst + t * US + q * 8) = u;
        }
        #pragma unroll
        for (int i = 0; i < 4; i++) {
            const int e = tid + i * 256;
            const int j = e >> 3, q = e & 7;
            *(uint4*)(wDst + j * US + q * 8) =
                *(const uint4*)(g_W2h + j * C_ + q * 8);
        }
    }
    __syncthreads();

    for (int c = 0; c < 4; c++) {
        const __half* bU = sU + (c & 1) * UBUF;
        const __half* bW = sW + (c & 1) * UBUF;

        #pragma unroll
        for (int ks = 0; ks < KC; ks += 16) {
            uint32_t af[4][4], bf[4][2];
            #pragma unroll
            for (int mi = 0; mi < 4; mi++) {
                const int row = wm * 64 + mi * 16 + g;
                af[mi][0] = *(const uint32_t*)(bU + row * US + ks + 2 * tig);
                af[mi][1] = *(const uint32_t*)(bU + (row + 8) * US + ks + 2 * tig);
                af[mi][2] = *(const uint32_t*)(bU + row * US + ks + 2 * tig + 8);
                af[mi][3] = *(const uint32_t*)(bU + (row + 8) * US + ks + 2 * tig + 8);
            }
            #pragma unroll
            for (int ni = 0; ni < 4; ni++) {
                const int j = wn * 32 + ni * 8 + g;
                bf[ni][0] = *(const uint32_t*)(bW + j * US + ks + 2 * tig);
                bf[ni][1] = *(const uint32_t*)(bW + j * US + ks + 2 * tig + 8);
            }
            #pragma unroll
            for (int mi = 0; mi < 4; mi++)
                #pragma unroll
                for (int ni = 0; ni < 4; ni++)
                    mma_f16(acc[mi][ni], af[mi], bf[ni]);
        }

        if (c < 3) {
            const int k0 = (c + 1) * KC;
            __half* uDst = sU + ((c + 1) & 1) * UBUF;
            __half* wDst = sW + ((c + 1) & 1) * UBUF;
            #pragma unroll
            for (int i = 0; i < 4; i++) {
                const int e = tid + i * 256;
                const int t = e >> 3, q = e & 7;
                const float4 a0 = *(const float4*)(aBase + t * C_ + k0 + q * 8);
                const float4 a1 = *(const float4*)(aBase + t * C_ + k0 + q * 8 + 4);
                const float4 c0 = *(const float4*)(sC + k0 + q * 8);
                const float4 c1 = *(const float4*)(sC + k0 + q * 8 + 4);
                uint4 u;
                u.x = f2h2(gelu_f(a0.x + c0.x), gelu_f(a0.y + c0.y));
                u.y = f2h2(gelu_f(a0.z + c0.z), gelu_f(a0.w + c0.w));
                u.z = f2h2(gelu_f(a1.x + c1.x), gelu_f(a1.y + c1.y));
                u.w = f2h2(gelu_f(a1.z + c1.z), gelu_f(a1.w + c1.w));
                *(uint4*)(uDst + t * US + q * 8) = u;
            }
            #pragma unroll
            for (int i = 0; i < 4; i++) {
                const int e = tid + i * 256;
                const int j = e >> 3, q = e & 7;
                *(uint4*)(wDst + j * US + q * 8) =
                    *(const uint4*)(g_W2h + j * C_ + k0 + q * 8);
            }
        }
        __syncthreads();
    }

    // Epilogue: v = gelu(acc + b2), partial w = v @ W3 per warp, reduce.
    #pragma unroll
    for (int mi = 0; mi < 4; mi++) {
        float p00 = 0.f, p01 = 0.f, p10 = 0.f, p11 = 0.f;
        #pragma unroll
        for (int ni = 0; ni < 4; ni++) {
            const int jb = wn * 32 + ni * 8 + tig * 2;
            const float v0 = gelu_f(acc[mi][ni][0] + sB2[jb]);
            const float v1 = gelu_f(acc[mi][ni][1] + sB2[jb + 1]);
            const float v2 = gelu_f(acc[mi][ni][2] + sB2[jb]);
            const float v3 = gelu_f(acc[mi][ni][3] + sB2[jb + 1]);
            p00 += v0 * sW3[2 * jb]     + v1 * sW3[2 * jb + 2];
            p01 += v0 * sW3[2 * jb + 1] + v1 * sW3[2 * jb + 3];
            p10 += v2 * sW3[2 * jb]     + v3 * sW3[2 * jb + 2];
            p11 += v2 * sW3[2 * jb + 1] + v3 * sW3[2 * jb + 3];
        }
        #pragma unroll
        for (int o = 1; o < 4; o <<= 1) {
            p00 += __shfl_xor_sync(0xffffffffu, p00, o);
            p01 += __shfl_xor_sync(0xffffffffu, p01, o);
            p10 += __shfl_xor_sync(0xffffffffu, p10, o);
            p11 += __shfl_xor_sync(0xffffffffu, p11, o);
        }
        if (tig == 0) {
            const int r0 = wm * 64 + mi * 16 + g;
            sPW[wn][r0][0] = p00;  sPW[wn][r0][1] = p01;
            sPW[wn][r0 + 8][0] = p10;  sPW[wn][r0 + 8][1] = p11;
        }
    }
    __syncthreads();

    if (tid < HALF_) {
        float w0 = b3[0], w1 = b3[1];
        #pragma unroll
        for (int w = 0; w < 4; w++) {
            w0 += sPW[w][tid][0];
            w1 += sPW[w][tid][1];
        }
        const float m = fmaxf(w0, w1);
        const float l = m + logf(expf(w0 - m) + expf(w1 - m));
        const int t = t0 + tid;
        const long long o0 = ((long long)bi * N_ + t) * 2;
        out[o0]     = w0 - l;
        out[o0 + 1] = w1 - l;
    }
}

// ---------------------------------------------------------------------------
extern "C" void kernel_launch(void* const* d_in, const int* in_sizes, int n_in,
                              void* d_out, int out_size)
{
    const float* x      = (const float*)d_in[0];
    const float* query  = (const float*)d_in[1];
    const float* policy = (const float*)d_in[2];
    const float* ln_g   = (const float*)d_in[3];
    const float* ln_b   = (const float*)d_in[4];
    const float* W_in   = (const float*)d_in[5];
    const float* b_in   = (const float*)d_in[6];
    const float* W1     = (const float*)d_in[7];
    const float* b1     = (const float*)d_in[8];
    const float* W2     = (const float*)d_in[9];
    const float* b2     = (const float*)d_in[10];
    const float* W3     = (const float*)d_in[11];
    const float* b3     = (const float*)d_in[12];
    float* out = (float*)d_out;

    const int dyn_bytes = 4 * UBUF * (int)sizeof(__half);  // 73728
    cudaFuncSetAttribute(k4_h16, cudaFuncAttributeMaxDynamicSharedMemorySize,
                         dyn_bytes);

    k1_ln_gemm_gelu<<<(B_ * N_) / 8, 256>>>(x, ln_g, ln_b, W_in, b_in, W1);
    k23_pre<<<218, 256>>>(query, W1, policy, b1, W2);
    k4_h16<<<dim3(N_ / 128, B_ * NQ_), 256, dyn_bytes>>>(b2, W3, b3, out);
}

// round 8
// speedup vs baseline: 2.9123x; 1.0536x over previous
#include <cuda_runtime.h>
#include <math.h>
#include <stdint.h>
#include <cuda_fp16.h>

// Problem dims (fixed by the dataset)
#define B_  2
#define N_  1024
#define C_  256
#define NQ_ 100
#define HALF_ 128

// Scratch (device globals: no allocation allowed)
__device__ __half g_Ah[B_ * N_ * C_];      // h_loc @ W1a (fp16)   (per b,t)
__device__ float  g_hg[B_ * N_ * HALF_];   // h glob half          (per b,t)
__device__ float  g_Cq[B_ * NQ_ * C_];     // q@W1c                (per b,i)
__device__ float  g_gt[B_ * C_];           // glob@W1b + b1        (per b)
__device__ __half g_W2h[HALF_ * C_];       // W2 transposed [j][k], fp16

__device__ __forceinline__ float gelu_f(float x) {
    return 0.5f * x * (1.0f + erff(x * 0.70710678118654752440f));
}

__device__ __forceinline__ uint32_t f2h2(float a, float b) {
    __half2 h = __floats2half2_rn(a, b);
    return *reinterpret_cast<uint32_t*>(&h);
}

__device__ __forceinline__ void mma_f16(float* d, const uint32_t* a, const uint32_t* b) {
    asm volatile(
        "mma.sync.aligned.m16n8k16.row.col.f32.f16.f16.f32 "
        "{%0,%1,%2,%3}, {%4,%5,%6,%7}, {%8,%9}, {%0,%1,%2,%3};"
        : "+f"(d[0]), "+f"(d[1]), "+f"(d[2]), "+f"(d[3])
        : "r"(a[0]), "r"(a[1]), "r"(a[2]), "r"(a[3]), "r"(b[0]), "r"(b[1]));
}

// ---------------------------------------------------------------------------
// K1: h = gelu(LN(x) @ W_in + b_in);  A_loc = h[:, :128] @ W1[0:128] (fp16)
// 8 rows per block, 512 threads, split-K: thread = (col, khalf).
// ---------------------------------------------------------------------------
__global__ void __launch_bounds__(512) k1_ln_gemm_gelu(
    const float* __restrict__ x, const float* __restrict__ ln_g,
    const float* __restrict__ ln_b, const float* __restrict__ Win,
    const float* __restrict__ bin, const float* __restrict__ W1)
{
    __shared__ float sY[8][C_];
    __shared__ float pp[8][C_];
    __shared__ float sred[8][8][2];
    __shared__ float smu[8], ssc[8];

    const int tid = threadIdx.x;
    const int col = tid & 255;
    const int kh  = tid >> 8;            // 0 or 1
    const int lane = tid & 31;
    const int wid  = tid >> 5;           // 0..15
    const int row0 = blockIdx.x * 8;

    const float gv = ln_g[col];
    const float bv = ln_b[col];

    // --- stats: first 256 threads own rows 0-3, second 256 own rows 4-7 ---
    const int rbase = kh * 4;
    float xv[4];
    #pragma unroll
    for (int r = 0; r < 4; r++)
        xv[r] = x[(row0 + rbase + r) * C_ + col];

    {
        const int w8 = wid & 7;
        #pragma unroll
        for (int r = 0; r < 4; r++) {
            float s = xv[r], q = xv[r] * xv[r];
            #pragma unroll
            for (int o = 16; o; o >>= 1) {
                s += __shfl_xor_sync(0xffffffffu, s, o);
                q += __shfl_xor_sync(0xffffffffu, q, o);
            }
            if (lane == 0) { sred[rbase + r][w8][0] = s; sred[rbase + r][w8][1] = q; }
        }
    }
    __syncthreads();
    if (wid < 8) {
        float s = (lane < 8) ? sred[wid][lane][0] : 0.f;
        float q = (lane < 8) ? sred[wid][lane][1] : 0.f;
        #pragma unroll
        for (int o = 4; o; o >>= 1) {
            s += __shfl_xor_sync(0xffffffffu, s, o);
            q += __shfl_xor_sync(0xffffffffu, q, o);
        }
        if (lane == 0) {
            const float mu = s * (1.0f / C_);
            const float var = q * (1.0f / C_) - mu * mu;
            smu[wid] = mu;
            ssc[wid] = rsqrtf(var + 1e-5f);
        }
    }
    __syncthreads();
    #pragma unroll
    for (int r = 0; r < 4; r++)
        sY[rbase + r][col] = (xv[r] - smu[rbase + r]) * ssc[rbase + r] * gv + bv;
    __syncthreads();

    // --- GEMM1: y @ W_in, K=256 split 128/128 across kh ---
    float acc[8];
    #pragma unroll
    for (int r = 0; r < 8; r++) acc[r] = 0.f;
    {
        const int kb = kh * 128;
        for (int k = kb; k < kb + 128; k++) {
            const float w = Win[k * C_ + col];
            #pragma unroll
            for (int r = 0; r < 8; r++) acc[r] += sY[r][k] * w;
        }
    }
    if (kh == 1) {
        #pragma unroll
        for (int r = 0; r < 8; r++) pp[r][col] = acc[r];
    }
    __syncthreads();

    float hr[8];
    if (kh == 0) {
        const float bi0 = bin[col];
        #pragma unroll
        for (int r = 0; r < 8; r++)
            hr[r] = gelu_f(acc[r] + pp[r][col] + bi0);
        if (col < HALF_) {
            #pragma unroll
            for (int r = 0; r < 8; r++) sY[r][col] = hr[r];
        } else {
            #pragma unroll
            for (int r = 0; r < 8; r++)
                g_hg[(row0 + r) * HALF_ + col - HALF_] = hr[r];
        }
    }
    __syncthreads();

    // --- GEMM2: h_loc @ W1[0:128], K=128 split 64/64 across kh ---
    float a2[8];
    #pragma unroll
    for (int r = 0; r < 8; r++) a2[r] = 0.f;
    {
        const int kb = kh * 64;
        for (int k = kb; k < kb + 64; k++) {
            const float w = W1[k * C_ + col];
            #pragma unroll
            for (int r = 0; r < 8; r++) a2[r] += sY[r][k] * w;
        }
    }
    if (kh == 1) {
        #pragma unroll
        for (int r = 0; r < 8; r++) pp[r][col] = a2[r];
    }
    __syncthreads();
    if (kh == 0) {
        #pragma unroll
        for (int r = 0; r < 8; r++)
            g_Ah[(row0 + r) * C_ + col] = __float2half_rn(a2[r] + pp[r][col]);
    }
}

// ---------------------------------------------------------------------------
// K23: combined prologue.  grid = 218 CTAs x 256 thr.
//   blocks 0..199   : Cq[b,i,:] = query[i,b,:] @ W1[256:512]
//   blocks 200..201 : glob + gt (needs g_hg from k1)
//   blocks 202..217 : W2h transpose to fp16
// ---------------------------------------------------------------------------
__global__ void __launch_bounds__(256) k23_pre(
    const float* __restrict__ query, const float* __restrict__ W1,
    const float* __restrict__ policy, const float* __restrict__ b1,
    const float* __restrict__ W2)
{
    const int blk = blockIdx.x;
    const int tid = threadIdx.x;

    if (blk < 200) {
        __shared__ float sQ[C_];
        const int b = blk / NQ_, i = blk % NQ_;
        sQ[tid] = query[(i * B_ + b) * C_ + tid];
        __syncthreads();

        float a[8];
        #pragma unroll
        for (int u = 0; u < 8; u++) a[u] = 0.f;
        #pragma unroll 4
        for (int k = 0; k < C_; k += 8) {
            #pragma unroll
            for (int u = 0; u < 8; u++)
                a[u] += sQ[k + u] * W1[(C_ + k + u) * C_ + tid];
        }
        g_Cq[blk * C_ + tid] =
            ((a[0] + a[1]) + (a[2] + a[3])) + ((a[4] + a[5]) + (a[6] + a[7]));
    } else if (blk < 202) {
        const int b = blk - 200;
        const int lane = tid & 31, wid = tid >> 5;
        __shared__ float spol[N_];
        __shared__ float sred[8];
        __shared__ float sps;
        __shared__ float sG[2][HALF_];
        __shared__ float sglob[HALF_];

        float ps = 0.f;
        #pragma unroll
        for (int i = 0; i < 4; i++) {
            const float p = policy[b * N_ + tid + i * 256];
            spol[tid + i * 256] = p;
            ps += p;
        }
        #pragma unroll
        for (int o = 16; o; o >>= 1) ps += __shfl_xor_sync(0xffffffffu, ps, o);
        if (lane == 0) sred[wid] = ps;
        __syncthreads();

        const int c = tid & 127, hf = tid >> 7;
        float acc = 0.f;
        for (int t = hf * 512; t < hf * 512 + 512; t++)
            acc += g_hg[(b * N_ + t) * HALF_ + c] * spol[t];
        sG[hf][c] = acc;
        if (tid == 0) {
            float s = 0.f;
            #pragma unroll
            for (int w = 0; w < 8; w++) s += sred[w];
            sps = s;
        }
        __syncthreads();
        if (tid < HALF_)
            sglob[tid] = (sG[0][tid] + sG[1][tid]) / sps;
        __syncthreads();

        float g = b1[tid];
        for (int k = 0; k < HALF_; k++)
            g += sglob[k] * W1[(HALF_ + k) * C_ + tid];
        g_gt[b * C_ + tid] = g;
    } else {
        const int base = (blk - 202) * 2048;
        #pragma unroll
        for (int i = 0; i < 8; i++) {
            const int lin = base + i * 256 + tid;   // index into W2 [k][j]
            const int k = lin >> 7, j = lin & 127;
            g_W2h[j * C_ + k] = __float2half_rn(W2[lin]);
        }
    }
}

// ---------------------------------------------------------------------------
// K4: fused  u = gelu(Aloc[b,t]+Cq[b,i]+gt[b]) ; v = gelu(u@W2+b2) ;
//            w = v@W3+b3 ; out = log_softmax(w)
// fp16 mma.sync m16n8k16, fp32 accum. Double-buffered K-chunks of 64.
// grid (8, 200), 256 threads = 8 warps (2x4 warp tile over 128x128).
// ---------------------------------------------------------------------------
#define KC  64                 // K elements per chunk
#define US  72                 // smem row stride in halves (pad 8)
#define UBUF (128 * US)        // halves per buffer

__global__ void __launch_bounds__(256, 2) k4_h16(
    const float* __restrict__ b2v,
    const float* __restrict__ W3, const float* __restrict__ b3,
    float* __restrict__ out)
{
    extern __shared__ __half dynh[];
    __half* sU = dynh;                  // [2][128*US] gelu tile (fp16)
    __half* sW = dynh + 2 * UBUF;       // [2][128*US] W2 chunk  (fp16)

    __shared__ __align__(16) float sC[C_];
    __shared__ float sB2[HALF_];
    __shared__ float sW3[2 * HALF_];
    __shared__ float sPW[4][HALF_][2];

    const int tid = threadIdx.x;
    const int lane = tid & 31, warp = tid >> 5;
    const int wm = warp >> 2, wn = warp & 3;  // 2x4 warp grid
    const int g = lane >> 2, tig = lane & 3;

    const int bi = blockIdx.y;            // b*100 + i
    const int b = bi / NQ_;
    const int t0 = blockIdx.x * 128;
    const __half* aBase = g_Ah + (b * N_ + t0) * C_;

    sC[tid] = g_Cq[bi * C_ + tid] + g_gt[b * C_ + tid];
    if (tid < HALF_) sB2[tid] = b2v[tid];
    sW3[tid] = W3[tid];

    float acc[4][4][4];
    #pragma unroll
    for (int mi = 0; mi < 4; mi++)
        #pragma unroll
        for (int ni = 0; ni < 4; ni++)
            #pragma unroll
            for (int q = 0; q < 4; q++) acc[mi][ni][q] = 0.f;
    __syncthreads();   // sC ready before first fill

    // fill chunk 0 into buffer 0
    {
        __half* uDst = sU;
        __half* wDst = sW;
        #pragma unroll
        for (int i = 0; i < 4; i++) {
            const int e = tid + i * 256;
            const int t = e >> 3, q = e & 7;       // q: 8-half group in [0,64)
            const uint4 a4 = *(const uint4*)(aBase + t * C_ + q * 8);
            const float2 a0 = __half22float2(*(const __half2*)&a4.x);
            const float2 a1 = __half22float2(*(const __half2*)&a4.y);
            const float2 a2 = __half22float2(*(const __half2*)&a4.z);
            const float2 a3 = __half22float2(*(const __half2*)&a4.w);
            const float4 c0 = *(const float4*)(sC + q * 8);
            const float4 c1 = *(const float4*)(sC + q * 8 + 4);
            uint4 u;
            u.x = f2h2(gelu_f(a0.x + c0.x), gelu_f(a0.y + c0.y));
            u.y = f2h2(gelu_f(a1.x + c0.z), gelu_f(a1.y + c0.w));
            u.z = f2h2(gelu_f(a2.x + c1.x), gelu_f(a2.y + c1.y));
            u.w = f2h2(gelu_f(a3.x + c1.z), gelu_f(a3.y + c1.w));
            *(uint4*)(uDst + t * US + q * 8) = u;
        }
        #pragma unroll
        for (int i = 0; i < 4; i++) {
            const int e = tid + i * 256;
            const int j = e >> 3, q = e & 7;
            *(uint4*)(wDst + j * US + q * 8) =
                *(const uint4*)(g_W2h + j * C_ + q * 8);
        }
    }
    __syncthreads();

    for (int c = 0; c < 4; c++) {
        const __half* bU = sU + (c & 1) * UBUF;
        const __half* bW = sW + (c & 1) * UBUF;

        #pragma unroll
        for (int ks = 0; ks < KC; ks += 16) {
            uint32_t af[4][4], bf[4][2];
            #pragma unroll
            for (int mi = 0; mi < 4; mi++) {
                const int row = wm * 64 + mi * 16 + g;
                af[mi][0] = *(const uint32_t*)(bU + row * US + ks + 2 * tig);
                af[mi][1] = *(const uint32_t*)(bU + (row + 8) * US + ks + 2 * tig);
                af[mi][2] = *(const uint32_t*)(bU + row * US + ks + 2 * tig + 8);
                af[mi][3] = *(const uint32_t*)(bU + (row + 8) * US + ks + 2 * tig + 8);
            }
            #pragma unroll
            for (int ni = 0; ni < 4; ni++) {
                const int j = wn * 32 + ni * 8 + g;
                bf[ni][0] = *(const uint32_t*)(bW + j * US + ks + 2 * tig);
                bf[ni][1] = *(const uint32_t*)(bW + j * US + ks + 2 * tig + 8);
            }
            #pragma unroll
            for (int mi = 0; mi < 4; mi++)
                #pragma unroll
                for (int ni = 0; ni < 4; ni++)
                    mma_f16(acc[mi][ni], af[mi], bf[ni]);
        }

        if (c < 3) {
            const int k0 = (c + 1) * KC;
            __half* uDst = sU + ((c + 1) & 1) * UBUF;
            __half* wDst = sW + ((c + 1) & 1) * UBUF;
            #pragma unroll
            for (int i = 0; i < 4; i++) {
                const int e = tid + i * 256;
                const int t = e >> 3, q = e & 7;
                const uint4 a4 = *(const uint4*)(aBase + t * C_ + k0 + q * 8);
                const float2 a0 = __half22float2(*(const __half2*)&a4.x);
                const float2 a1 = __half22float2(*(const __half2*)&a4.y);
                const float2 a2 = __half22float2(*(const __half2*)&a4.z);
                const float2 a3 = __half22float2(*(const __half2*)&a4.w);
                const float4 c0 = *(const float4*)(sC + k0 + q * 8);
                const float4 c1 = *(const float4*)(sC + k0 + q * 8 + 4);
                uint4 u;
                u.x = f2h2(gelu_f(a0.x + c0.x), gelu_f(a0.y + c0.y));
                u.y = f2h2(gelu_f(a1.x + c0.z), gelu_f(a1.y + c0.w));
                u.z = f2h2(gelu_f(a2.x + c1.x), gelu_f(a2.y + c1.y));
                u.w = f2h2(gelu_f(a3.x + c1.z), gelu_f(a3.y + c1.w));
                *(uint4*)(uDst + t * US + q * 8) = u;
            }
            #pragma unroll
            for (int i = 0; i < 4; i++) {
                const int e = tid + i * 256;
                const int j = e >> 3, q = e & 7;
                *(uint4*)(wDst + j * US + q * 8) =
                    *(const uint4*)(g_W2h + j * C_ + k0 + q * 8);
            }
        }
        __syncthreads();
    }

    // Epilogue: v = gelu(acc + b2), partial w = v @ W3 per warp, reduce.
    #pragma unroll
    for (int mi = 0; mi < 4; mi++) {
        float p00 = 0.f, p01 = 0.f, p10 = 0.f, p11 = 0.f;
        #pragma unroll
        for (int ni = 0; ni < 4; ni++) {
            const int jb = wn * 32 + ni * 8 + tig * 2;
            const float v0 = gelu_f(acc[mi][ni][0] + sB2[jb]);
            const float v1 = gelu_f(acc[mi][ni][1] + sB2[jb + 1]);
            const float v2 = gelu_f(acc[mi][ni][2] + sB2[jb]);
            const float v3 = gelu_f(acc[mi][ni][3] + sB2[jb + 1]);
            p00 += v0 * sW3[2 * jb]     + v1 * sW3[2 * jb + 2];
            p01 += v0 * sW3[2 * jb + 1] + v1 * sW3[2 * jb + 3];
            p10 += v2 * sW3[2 * jb]     + v3 * sW3[2 * jb + 2];
            p11 += v2 * sW3[2 * jb + 1] + v3 * sW3[2 * jb + 3];
        }
        #pragma unroll
        for (int o = 1; o < 4; o <<= 1) {
            p00 += __shfl_xor_sync(0xffffffffu, p00, o);
            p01 += __shfl_xor_sync(0xffffffffu, p01, o);
            p10 += __shfl_xor_sync(0xffffffffu, p10, o);
            p11 += __shfl_xor_sync(0xffffffffu, p11, o);
        }
        if (tig == 0) {
            const int r0 = wm * 64 + mi * 16 + g;
            sPW[wn][r0][0] = p00;  sPW[wn][r0][1] = p01;
            sPW[wn][r0 + 8][0] = p10;  sPW[wn][r0 + 8][1] = p11;
        }
    }
    __syncthreads();

    if (tid < HALF_) {
        float w0 = b3[0], w1 = b3[1];
        #pragma unroll
        for (int w = 0; w < 4; w++) {
            w0 += sPW[w][tid][0];
            w1 += sPW[w][tid][1];
        }
        const float m = fmaxf(w0, w1);
        const float l = m + logf(expf(w0 - m) + expf(w1 - m));
        const int t = t0 + tid;
        const long long o0 = ((long long)bi * N_ + t) * 2;
        out[o0]     = w0 - l;
        out[o0 + 1] = w1 - l;
    }
}

// ---------------------------------------------------------------------------
extern "C" void kernel_launch(void* const* d_in, const int* in_sizes, int n_in,
                              void* d_out, int out_size)
{
    const float* x      = (const float*)d_in[0];
    const float* query  = (const float*)d_in[1];
    const float* policy = (const float*)d_in[2];
    const float* ln_g   = (const float*)d_in[3];
    const float* ln_b   = (const float*)d_in[4];
    const float* W_in   = (const float*)d_in[5];
    const float* b_in   = (const float*)d_in[6];
    const float* W1     = (const float*)d_in[7];
    const float* b1     = (const float*)d_in[8];
    const float* W2     = (const float*)d_in[9];
    const float* b2     = (const float*)d_in[10];
    const float* W3     = (const float*)d_in[11];
    const float* b3     = (const float*)d_in[12];
    float* out = (float*)d_out;

    const int dyn_bytes = 4 * UBUF * (int)sizeof(__half);  // 73728
    cudaFuncSetAttribute(k4_h16, cudaFuncAttributeMaxDynamicSharedMemorySize,
                         dyn_bytes);

    k1_ln_gemm_gelu<<<(B_ * N_) / 8, 512>>>(x, ln_g, ln_b, W_in, b_in, W1);
    k23_pre<<<218, 256>>>(query, W1, policy, b1, W2);
    k4_h16<<<dim3(N_ / 128, B_ * NQ_), 256, dyn_bytes>>>(b2, W3, b3, out);
}

// round 10
// speedup vs baseline: 3.1719x; 1.0891x over previous
#include <cuda_runtime.h>
#include <math.h>
#include <stdint.h>
#include <cuda_fp16.h>

// Problem dims (fixed by the dataset)
#define B_  2
#define N_  1024
#define C_  256
#define NQ_ 100
#define HALF_ 128

// Scratch (device globals: no allocation allowed)
__device__ __half g_Ah[B_ * N_ * C_];      // h_loc @ W1a (fp16)   (per b,t)
__device__ float  g_hg[B_ * N_ * HALF_];   // h glob half          (per b,t)
__device__ float  g_Cq[B_ * NQ_ * C_];     // q@W1c                (per b,i)
__device__ float  g_gt[B_ * C_];           // glob@W1b + b1        (per b)
__device__ __half g_W2h[HALF_ * C_];       // W2 transposed [j][k], fp16

// Exact-precision gelu via Abramowitz-Stegun 7.1.26 erf (|err| <= 1.5e-7),
// branchless: 1 rcp + 1 ex2 + ~10 fma. Much cheaper than libdevice erff's
// divergent two-path implementation.
__device__ __forceinline__ float gelu_f(float x) {
    const float ax = fabsf(x) * 0.70710678118654752440f;
    const float t = __fdividef(1.0f, fmaf(0.3275911f, ax, 1.0f));
    float p = fmaf(1.061405429f, t, -1.453152027f);
    p = fmaf(p, t, 1.421413741f);
    p = fmaf(p, t, -0.284496736f);
    p = fmaf(p, t, 0.254829592f);
    p = p * t;
    const float e = __expf(-ax * ax);
    const float er = fmaf(-p, e, 1.0f);          // erf(ax), ax >= 0
    const float s = copysignf(er, x);
    return 0.5f * x * (1.0f + s);
}

__device__ __forceinline__ uint32_t f2h2(float a, float b) {
    __half2 h = __floats2half2_rn(a, b);
    return *reinterpret_cast<uint32_t*>(&h);
}

__device__ __forceinline__ void mma_f16(float* d, const uint32_t* a, const uint32_t* b) {
    asm volatile(
        "mma.sync.aligned.m16n8k16.row.col.f32.f16.f16.f32 "
        "{%0,%1,%2,%3}, {%4,%5,%6,%7}, {%8,%9}, {%0,%1,%2,%3};"
        : "+f"(d[0]), "+f"(d[1]), "+f"(d[2]), "+f"(d[3])
        : "r"(a[0]), "r"(a[1]), "r"(a[2]), "r"(a[3]), "r"(b[0]), "r"(b[1]));
}

// ---------------------------------------------------------------------------
// K1: h = gelu(LN(x) @ W_in + b_in);  A_loc = h[:, :128] @ W1[0:128] (fp16)
// 8 rows per block, 512 threads, split-K: thread = (col, khalf).
// ---------------------------------------------------------------------------
__global__ void __launch_bounds__(512) k1_ln_gemm_gelu(
    const float* __restrict__ x, const float* __restrict__ ln_g,
    const float* __restrict__ ln_b, const float* __restrict__ Win,
    const float* __restrict__ bin, const float* __restrict__ W1)
{
    __shared__ __align__(16) float sY[8][C_];
    __shared__ float pp[8][C_];
    __shared__ float sred[8][8][2];
    __shared__ float smu[8], ssc[8];

    const int tid = threadIdx.x;
    const int col = tid & 255;
    const int kh  = tid >> 8;            // 0 or 1
    const int lane = tid & 31;
    const int wid  = tid >> 5;           // 0..15
    const int row0 = blockIdx.x * 8;

    const float gv = ln_g[col];
    const float bv = ln_b[col];

    // --- stats: first 256 threads own rows 0-3, second 256 own rows 4-7 ---
    const int rbase = kh * 4;
    float xv[4];
    #pragma unroll
    for (int r = 0; r < 4; r++)
        xv[r] = x[(row0 + rbase + r) * C_ + col];

    {
        const int w8 = wid & 7;
        #pragma unroll
        for (int r = 0; r < 4; r++) {
            float s = xv[r], q = xv[r] * xv[r];
            #pragma unroll
            for (int o = 16; o; o >>= 1) {
                s += __shfl_xor_sync(0xffffffffu, s, o);
                q += __shfl_xor_sync(0xffffffffu, q, o);
            }
            if (lane == 0) { sred[rbase + r][w8][0] = s; sred[rbase + r][w8][1] = q; }
        }
    }
    __syncthreads();
    if (wid < 8) {
        float s = (lane < 8) ? sred[wid][lane][0] : 0.f;
        float q = (lane < 8) ? sred[wid][lane][1] : 0.f;
        #pragma unroll
        for (int o = 4; o; o >>= 1) {
            s += __shfl_xor_sync(0xffffffffu, s, o);
            q += __shfl_xor_sync(0xffffffffu, q, o);
        }
        if (lane == 0) {
            const float mu = s * (1.0f / C_);
            const float var = q * (1.0f / C_) - mu * mu;
            smu[wid] = mu;
            ssc[wid] = rsqrtf(var + 1e-5f);
        }
    }
    __syncthreads();
    #pragma unroll
    for (int r = 0; r < 4; r++)
        sY[rbase + r][col] = (xv[r] - smu[rbase + r]) * ssc[rbase + r] * gv + bv;
    __syncthreads();

    // --- GEMM1: y @ W_in, K=256 split 128/128 across kh, 4x k-unroll ---
    float acc[8];
    #pragma unroll
    for (int r = 0; r < 8; r++) acc[r] = 0.f;
    {
        const int kb = kh * 128;
        for (int k = kb; k < kb + 128; k += 4) {
            const float w0 = Win[(k + 0) * C_ + col];
            const float w1 = Win[(k + 1) * C_ + col];
            const float w2 = Win[(k + 2) * C_ + col];
            const float w3 = Win[(k + 3) * C_ + col];
            #pragma unroll
            for (int r = 0; r < 8; r++) {
                const float4 y = *(const float4*)&sY[r][k];
                acc[r] += y.x * w0 + y.y * w1 + y.z * w2 + y.w * w3;
            }
        }
    }
    if (kh == 1) {
        #pragma unroll
        for (int r = 0; r < 8; r++) pp[r][col] = acc[r];
    }
    __syncthreads();

    float hr[8];
    if (kh == 0) {
        const float bi0 = bin[col];
        #pragma unroll
        for (int r = 0; r < 8; r++)
            hr[r] = gelu_f(acc[r] + pp[r][col] + bi0);
        if (col < HALF_) {
            #pragma unroll
            for (int r = 0; r < 8; r++) sY[r][col] = hr[r];
        } else {
            #pragma unroll
            for (int r = 0; r < 8; r++)
                g_hg[(row0 + r) * HALF_ + col - HALF_] = hr[r];
        }
    }
    __syncthreads();

    // --- GEMM2: h_loc @ W1[0:128], K=128 split 64/64 across kh, 4x unroll ---
    float a2[8];
    #pragma unroll
    for (int r = 0; r < 8; r++) a2[r] = 0.f;
    {
        const int kb = kh * 64;
        for (int k = kb; k < kb + 64; k += 4) {
            const float w0 = W1[(k + 0) * C_ + col];
            const float w1 = W1[(k + 1) * C_ + col];
            const float w2 = W1[(k + 2) * C_ + col];
            const float w3 = W1[(k + 3) * C_ + col];
            #pragma unroll
            for (int r = 0; r < 8; r++) {
                const float4 y = *(const float4*)&sY[r][k];
                a2[r] += y.x * w0 + y.y * w1 + y.z * w2 + y.w * w3;
            }
        }
    }
    if (kh == 1) {
        #pragma unroll
        for (int r = 0; r < 8; r++) pp[r][col] = a2[r];
    }
    __syncthreads();
    if (kh == 0) {
        #pragma unroll
        for (int r = 0; r < 8; r++)
            g_Ah[(row0 + r) * C_ + col] = __float2half_rn(a2[r] + pp[r][col]);
    }
}

// ---------------------------------------------------------------------------
// K23: combined prologue.  grid = 218 CTAs x 256 thr.
//   blocks 0..199   : Cq[b,i,:] = query[i,b,:] @ W1[256:512]
//   blocks 200..201 : glob + gt (needs g_hg from k1)
//   blocks 202..217 : W2h transpose to fp16
// ---------------------------------------------------------------------------
__global__ void __launch_bounds__(256) k23_pre(
    const float* __restrict__ query, const float* __restrict__ W1,
    const float* __restrict__ policy, const float* __restrict__ b1,
    const float* __restrict__ W2)
{
    const int blk = blockIdx.x;
    const int tid = threadIdx.x;

    if (blk < 200) {
        __shared__ float sQ[C_];
        const int b = blk / NQ_, i = blk % NQ_;
        sQ[tid] = query[(i * B_ + b) * C_ + tid];
        __syncthreads();

        float a[8];
        #pragma unroll
        for (int u = 0; u < 8; u++) a[u] = 0.f;
        #pragma unroll 4
        for (int k = 0; k < C_; k += 8) {
            #pragma unroll
            for (int u = 0; u < 8; u++)
                a[u] += sQ[k + u] * W1[(C_ + k + u) * C_ + tid];
        }
        g_Cq[blk * C_ + tid] =
            ((a[0] + a[1]) + (a[2] + a[3])) + ((a[4] + a[5]) + (a[6] + a[7]));
    } else if (blk < 202) {
        const int b = blk - 200;
        const int lane = tid & 31, wid = tid >> 5;
        __shared__ float spol[N_];
        __shared__ float sred[8];
        __shared__ float sps;
        __shared__ float sG[2][HALF_];
        __shared__ float sglob[HALF_];

        float ps = 0.f;
        #pragma unroll
        for (int i = 0; i < 4; i++) {
            const float p = policy[b * N_ + tid + i * 256];
            spol[tid + i * 256] = p;
            ps += p;
        }
        #pragma unroll
        for (int o = 16; o; o >>= 1) ps += __shfl_xor_sync(0xffffffffu, ps, o);
        if (lane == 0) sred[wid] = ps;
        __syncthreads();

        const int c = tid & 127, hf = tid >> 7;
        float acc = 0.f;
        for (int t = hf * 512; t < hf * 512 + 512; t++)
            acc += g_hg[(b * N_ + t) * HALF_ + c] * spol[t];
        sG[hf][c] = acc;
        if (tid == 0) {
            float s = 0.f;
            #pragma unroll
            for (int w = 0; w < 8; w++) s += sred[w];
            sps = s;
        }
        __syncthreads();
        if (tid < HALF_)
            sglob[tid] = (sG[0][tid] + sG[1][tid]) / sps;
        __syncthreads();

        float g = b1[tid];
        for (int k = 0; k < HALF_; k++)
            g += sglob[k] * W1[(HALF_ + k) * C_ + tid];
        g_gt[b * C_ + tid] = g;
    } else {
        const int base = (blk - 202) * 2048;
        #pragma unroll
        for (int i = 0; i < 8; i++) {
            const int lin = base + i * 256 + tid;   // index into W2 [k][j]
            const int k = lin >> 7, j = lin & 127;
            g_W2h[j * C_ + k] = __float2half_rn(W2[lin]);
        }
    }
}

// ---------------------------------------------------------------------------
// K4: fused  u = gelu(Aloc[b,t]+Cq[b,i]+gt[b]) ; v = gelu(u@W2+b2) ;
//            w = v@W3+b3 ; out = log_softmax(w)
// fp16 mma.sync m16n8k16, fp32 accum. Double-buffered K-chunks of 64.
// grid (8, 200), 256 threads = 8 warps (2x4 warp tile over 128x128).
// ---------------------------------------------------------------------------
#define KC  64                 // K elements per chunk
#define US  72                 // smem row stride in halves (pad 8)
#define UBUF (128 * US)        // halves per buffer

__global__ void __launch_bounds__(256, 2) k4_h16(
    const float* __restrict__ b2v,
    const float* __restrict__ W3, const float* __restrict__ b3,
    float* __restrict__ out)
{
    extern __shared__ __half dynh[];
    __half* sU = dynh;                  // [2][128*US] gelu tile (fp16)
    __half* sW = dynh + 2 * UBUF;       // [2][128*US] W2 chunk  (fp16)

    __shared__ __align__(16) float sC[C_];
    __shared__ float sB2[HALF_];
    __shared__ float sW3[2 * HALF_];
    __shared__ float sPW[4][HALF_][2];

    const int tid = threadIdx.x;
    const int lane = tid & 31, warp = tid >> 5;
    const int wm = warp >> 2, wn = warp & 3;  // 2x4 warp grid
    const int g = lane >> 2, tig = lane & 3;

    const int bi = blockIdx.y;            // b*100 + i
    const int b = bi / NQ_;
    const int t0 = blockIdx.x * 128;
    const __half* aBase = g_Ah + (b * N_ + t0) * C_;

    sC[tid] = g_Cq[bi * C_ + tid] + g_gt[b * C_ + tid];
    if (tid < HALF_) sB2[tid] = b2v[tid];
    sW3[tid] = W3[tid];

    float acc[4][4][4];
    #pragma unroll
    for (int mi = 0; mi < 4; mi++)
        #pragma unroll
        for (int ni = 0; ni < 4; ni++)
            #pragma unroll
            for (int q = 0; q < 4; q++) acc[mi][ni][q] = 0.f;
    __syncthreads();   // sC ready before first fill

    // fill chunk 0 into buffer 0
    {
        __half* uDst = sU;
        __half* wDst = sW;
        #pragma unroll
        for (int i = 0; i < 4; i++) {
            const int e = tid + i * 256;
            const int t = e >> 3, q = e & 7;       // q: 8-half group in [0,64)
            const uint4 a4 = *(const uint4*)(aBase + t * C_ + q * 8);
            const float2 a0 = __half22float2(*(const __half2*)&a4.x);
            const float2 a1 = __half22float2(*(const __half2*)&a4.y);
            const float2 a2 = __half22float2(*(const __half2*)&a4.z);
            const float2 a3 = __half22float2(*(const __half2*)&a4.w);
            const float4 c0 = *(const float4*)(sC + q * 8);
            const float4 c1 = *(const float4*)(sC + q * 8 + 4);
            uint4 u;
            u.x = f2h2(gelu_f(a0.x + c0.x), gelu_f(a0.y + c0.y));
            u.y = f2h2(gelu_f(a1.x + c0.z), gelu_f(a1.y + c0.w));
            u.z = f2h2(gelu_f(a2.x + c1.x), gelu_f(a2.y + c1.y));
            u.w = f2h2(gelu_f(a3.x + c1.z), gelu_f(a3.y + c1.w));
            *(uint4*)(uDst + t * US + q * 8) = u;
        }
        #pragma unroll
        for (int i = 0; i < 4; i++) {
            const int e = tid + i * 256;
            const int j = e >> 3, q = e & 7;
            *(uint4*)(wDst + j * US + q * 8) =
                *(const uint4*)(g_W2h + j * C_ + q * 8);
        }
    }
    __syncthreads();

    for (int c = 0; c < 4; c++) {
        const __half* bU = sU + (c & 1) * UBUF;
        const __half* bW = sW + (c & 1) * UBUF;

        #pragma unroll
        for (int ks = 0; ks < KC; ks += 16) {
            uint32_t af[4][4], bf[4][2];
            #pragma unroll
            for (int mi = 0; mi < 4; mi++) {
                const int row = wm * 64 + mi * 16 + g;
                af[mi][0] = *(const uint32_t*)(bU + row * US + ks + 2 * tig);
                af[mi][1] = *(const uint32_t*)(bU + (row + 8) * US + ks + 2 * tig);
                af[mi][2] = *(const uint32_t*)(bU + row * US + ks + 2 * tig + 8);
                af[mi][3] = *(const uint32_t*)(bU + (row + 8) * US + ks + 2 * tig + 8);
            }
            #pragma unroll
            for (int ni = 0; ni < 4; ni++) {
                const int j = wn * 32 + ni * 8 + g;
                bf[ni][0] = *(const uint32_t*)(bW + j * US + ks + 2 * tig);
                bf[ni][1] = *(const uint32_t*)(bW + j * US + ks + 2 * tig + 8);
            }
            #pragma unroll
            for (int mi = 0; mi < 4; mi++)
                #pragma unroll
                for (int ni = 0; ni < 4; ni++)
                    mma_f16(acc[mi][ni], af[mi], bf[ni]);
        }

        if (c < 3) {
            const int k0 = (c + 1) * KC;
            __half* uDst = sU + ((c + 1) & 1) * UBUF;
            __half* wDst = sW + ((c + 1) & 1) * UBUF;
            #pragma unroll
            for (int i = 0; i < 4; i++) {
                const int e = tid + i * 256;
                const int t = e >> 3, q = e & 7;
                const uint4 a4 = *(const uint4*)(aBase + t * C_ + k0 + q * 8);
                const float2 a0 = __half22float2(*(const __half2*)&a4.x);
                const float2 a1 = __half22float2(*(const __half2*)&a4.y);
                const float2 a2 = __half22float2(*(const __half2*)&a4.z);
                const float2 a3 = __half22float2(*(const __half2*)&a4.w);
                const float4 c0 = *(const float4*)(sC + k0 + q * 8);
                const float4 c1 = *(const float4*)(sC + k0 + q * 8 + 4);
                uint4 u;
                u.x = f2h2(gelu_f(a0.x + c0.x), gelu_f(a0.y + c0.y));
                u.y = f2h2(gelu_f(a1.x + c0.z), gelu_f(a1.y + c0.w));
                u.z = f2h2(gelu_f(a2.x + c1.x), gelu_f(a2.y + c1.y));
                u.w = f2h2(gelu_f(a3.x + c1.z), gelu_f(a3.y + c1.w));
                *(uint4*)(uDst + t * US + q * 8) = u;
            }
            #pragma unroll
            for (int i = 0; i < 4; i++) {
                const int e = tid + i * 256;
                const int j = e >> 3, q = e & 7;
                *(uint4*)(wDst + j * US + q * 8) =
                    *(const uint4*)(g_W2h + j * C_ + k0 + q * 8);
            }
        }
        __syncthreads();
    }

    // Epilogue: v = gelu(acc + b2), partial w = v @ W3 per warp, reduce.
    #pragma unroll
    for (int mi = 0; mi < 4; mi++) {
        float p00 = 0.f, p01 = 0.f, p10 = 0.f, p11 = 0.f;
        #pragma unroll
        for (int ni = 0; ni < 4; ni++) {
            const int jb = wn * 32 + ni * 8 + tig * 2;
            const float v0 = gelu_f(acc[mi][ni][0] + sB2[jb]);
            const float v1 = gelu_f(acc[mi][ni][1] + sB2[jb + 1]);
            const float v2 = gelu_f(acc[mi][ni][2] + sB2[jb]);
            const float v3 = gelu_f(acc[mi][ni][3] + sB2[jb + 1]);
            p00 += v0 * sW3[2 * jb]     + v1 * sW3[2 * jb + 2];
            p01 += v0 * sW3[2 * jb + 1] + v1 * sW3[2 * jb + 3];
            p10 += v2 * sW3[2 * jb]     + v3 * sW3[2 * jb + 2];
            p11 += v2 * sW3[2 * jb + 1] + v3 * sW3[2 * jb + 3];
        }
        #pragma unroll
        for (int o = 1; o < 4; o <<= 1) {
            p00 += __shfl_xor_sync(0xffffffffu, p00, o);
            p01 += __shfl_xor_sync(0xffffffffu, p01, o);
            p10 += __shfl_xor_sync(0xffffffffu, p10, o);
            p11 += __shfl_xor_sync(0xffffffffu, p11, o);
        }
        if (tig == 0) {
            const int r0 = wm * 64 + mi * 16 + g;
            sPW[wn][r0][0] = p00;  sPW[wn][r0][1] = p01;
            sPW[wn][r0 + 8][0] = p10;  sPW[wn][r0 + 8][1] = p11;
        }
    }
    __syncthreads();

    if (tid < HALF_) {
        float w0 = b3[0], w1 = b3[1];
        #pragma unroll
        for (int w = 0; w < 4; w++) {
            w0 += sPW[w][tid][0];
            w1 += sPW[w][tid][1];
        }
        const float m = fmaxf(w0, w1);
        const float l = m + logf(expf(w0 - m) + expf(w1 - m));
        const int t = t0 + tid;
        const long long o0 = ((long long)bi * N_ + t) * 2;
        out[o0]     = w0 - l;
        out[o0 + 1] = w1 - l;
    }
}

// ---------------------------------------------------------------------------
extern "C" void kernel_launch(void* const* d_in, const int* in_sizes, int n_in,
                              void* d_out, int out_size)
{
    const float* x      = (const float*)d_in[0];
    const float* query  = (const float*)d_in[1];
    const float* policy = (const float*)d_in[2];
    const float* ln_g   = (const float*)d_in[3];
    const float* ln_b   = (const float*)d_in[4];
    const float* W_in   = (const float*)d_in[5];
    const float* b_in   = (const float*)d_in[6];
    const float* W1     = (const float*)d_in[7];
    const float* b1     = (const float*)d_in[8];
    const float* W2     = (const float*)d_in[9];
    const float* b2     = (const float*)d_in[10];
    const float* W3     = (const float*)d_in[11];
    const float* b3     = (const float*)d_in[12];
    float* out = (float*)d_out;

    const int dyn_bytes = 4 * UBUF * (int)sizeof(__half);  // 73728
    cudaFuncSetAttribute(k4_h16, cudaFuncAttributeMaxDynamicSharedMemorySize,
                         dyn_bytes);

    k1_ln_gemm_gelu<<<(B_ * N_) / 8, 512>>>(x, ln_g, ln_b, W_in, b_in, W1);
    k23_pre<<<218, 256>>>(query, W1, policy, b1, W2);
    k4_h16<<<dim3(N_ / 128, B_ * NQ_), 256, dyn_bytes>>>(b2, W3, b3, out);
}

// round 11
// speedup vs baseline: 3.3339x; 1.0511x over previous
#include <cuda_runtime.h>
#include <math.h>
#include <stdint.h>
#include <cuda_fp16.h>

// Problem dims (fixed by the dataset)
#define B_  2
#define N_  1024
#define C_  256
#define NQ_ 100
#define HALF_ 128

// Scratch (device globals: no allocation allowed)
__device__ __half g_Ah[B_ * N_ * C_];      // h_loc @ W1a (fp16)   (per b,t)
__device__ float  g_hg[B_ * N_ * HALF_];   // h glob half          (per b,t)
__device__ float  g_Cq[B_ * NQ_ * C_];     // q@W1c                (per b,i)
__device__ float  g_gt[B_ * C_];           // glob@W1b + b1        (per b)
__device__ __half g_W2h[HALF_ * C_];       // W2 transposed [j][k], fp16

// ---------------------------------------------------------------------------
// gelu, scalar (A-S 7.1.26 erf, |err|<=1.5e-7, branchless)
// ---------------------------------------------------------------------------
__device__ __forceinline__ float gelu_f(float x) {
    const float ax = fabsf(x) * 0.70710678118654752440f;
    const float t = __fdividef(1.0f, fmaf(0.3275911f, ax, 1.0f));
    float p = fmaf(1.061405429f, t, -1.453152027f);
    p = fmaf(p, t, 1.421413741f);
    p = fmaf(p, t, -0.284496736f);
    p = fmaf(p, t, 0.254829592f);
    p = p * t;
    const float e = __expf(-ax * ax);
    const float er = fmaf(-p, e, 1.0f);
    const float s = copysignf(er, x);
    return 0.5f * x * (1.0f + s);
}

// ---------------------------------------------------------------------------
// gelu, packed 2-wide via f32x2 (sm_100+ PTX; full fp32 precision).
// Same A-S 7.1.26 formula: the fma-pipe work is halved vs. scalar.
// ---------------------------------------------------------------------------
__device__ __forceinline__ uint64_t dup2_(float c) {
    uint64_t r; asm("mov.b64 %0, {%1, %1};" : "=l"(r) : "f"(c)); return r;
}
#define FMA2_(d, a, b, c) asm("fma.rn.f32x2 %0, %1, %2, %3;" : "=l"(d) : "l"(a), "l"(b), "l"(c))
#define MUL2_(d, a, b)    asm("mul.rn.f32x2 %0, %1, %2;"     : "=l"(d) : "l"(a), "l"(b))
#define ADD2_(d, a, b)    asm("add.rn.f32x2 %0, %1, %2;"     : "=l"(d) : "l"(a), "l"(b))

__device__ __forceinline__ void gelu2_f(float xa, float xb, float& ra, float& rb) {
    uint64_t xp; asm("mov.b64 %0, {%1, %2};" : "=l"(xp) : "f"(xa), "f"(xb));
    const uint64_t ap = xp & 0x7FFFFFFF7FFFFFFFULL;
    uint64_t axk; MUL2_(axk, ap, dup2_(0.70710678118654752440f));
    uint64_t den; FMA2_(den, axk, dup2_(0.3275911f), dup2_(1.0f));
    float d0, d1; asm("mov.b64 {%0, %1}, %2;" : "=f"(d0), "=f"(d1) : "l"(den));
    float t0, t1;
    asm("rcp.approx.f32 %0, %1;" : "=f"(t0) : "f"(d0));
    asm("rcp.approx.f32 %0, %1;" : "=f"(t1) : "f"(d1));
    uint64_t t; asm("mov.b64 %0, {%1, %2};" : "=l"(t) : "f"(t0), "f"(t1));
    uint64_t p;
    FMA2_(p, dup2_(1.061405429f), t, dup2_(-1.453152027f));
    FMA2_(p, p, t, dup2_(1.421413741f));
    FMA2_(p, p, t, dup2_(-0.284496736f));
    FMA2_(p, p, t, dup2_(0.254829592f));
    MUL2_(p, p, t);
    uint64_t z2; MUL2_(z2, axk, axk);
    uint64_t w;  MUL2_(w, z2, dup2_(-1.4426950408889634f));   // -z^2 * log2(e)
    float w0, w1; asm("mov.b64 {%0, %1}, %2;" : "=f"(w0), "=f"(w1) : "l"(w));
    float e0, e1;
    asm("ex2.approx.f32 %0, %1;" : "=f"(e0) : "f"(w0));
    asm("ex2.approx.f32 %0, %1;" : "=f"(e1) : "f"(w1));
    uint64_t e; asm("mov.b64 %0, {%1, %2};" : "=l"(e) : "f"(e0), "f"(e1));
    uint64_t pe; MUL2_(pe, p, e);
    uint64_t er; FMA2_(er, pe, dup2_(-1.0f), dup2_(1.0f));    // 1 - p*e = erf(ax)
    const uint64_t s = er | (xp & 0x8000000080000000ULL);     // copysign (er>0)
    uint64_t onep; ADD2_(onep, s, dup2_(1.0f));
    uint64_t hx;   MUL2_(hx, xp, dup2_(0.5f));
    uint64_t res;  MUL2_(res, onep, hx);
    asm("mov.b64 {%0, %1}, %2;" : "=f"(ra), "=f"(rb) : "l"(res));
}

__device__ __forceinline__ uint32_t f2h2(float a, float b) {
    __half2 h = __floats2half2_rn(a, b);
    return *reinterpret_cast<uint32_t*>(&h);
}

__device__ __forceinline__ uint32_t gelu2_h2(float xa, float xb) {
    float ra, rb;
    gelu2_f(xa, xb, ra, rb);
    return f2h2(ra, rb);
}

__device__ __forceinline__ void mma_f16(float* d, const uint32_t* a, const uint32_t* b) {
    asm volatile(
        "mma.sync.aligned.m16n8k16.row.col.f32.f16.f16.f32 "
        "{%0,%1,%2,%3}, {%4,%5,%6,%7}, {%8,%9}, {%0,%1,%2,%3};"
        : "+f"(d[0]), "+f"(d[1]), "+f"(d[2]), "+f"(d[3])
        : "r"(a[0]), "r"(a[1]), "r"(a[2]), "r"(a[3]), "r"(b[0]), "r"(b[1]));
}

// ---------------------------------------------------------------------------
// K1: h = gelu(LN(x) @ W_in + b_in);  A_loc = h[:, :128] @ W1[0:128] (fp16)
// 4 rows per block (512 CTAs -> ~84% occ), 512 threads, split-K.
// ---------------------------------------------------------------------------
__global__ void __launch_bounds__(512) k1_ln_gemm_gelu(
    const float* __restrict__ x, const float* __restrict__ ln_g,
    const float* __restrict__ ln_b, const float* __restrict__ Win,
    const float* __restrict__ bin, const float* __restrict__ W1)
{
    __shared__ __align__(16) float sY[4][C_];
    __shared__ float pp[4][C_];
    __shared__ float sred[4][8][2];
    __shared__ float smu[4], ssc[4];

    const int tid = threadIdx.x;
    const int col = tid & 255;
    const int kh  = tid >> 8;            // 0 or 1
    const int lane = tid & 31;
    const int wid  = tid >> 5;           // 0..15
    const int row0 = blockIdx.x * 4;

    const float gv = ln_g[col];
    const float bv = ln_b[col];

    // --- stats: kh=0 owns rows 0-1, kh=1 owns rows 2-3 ---
    const int rbase = kh * 2;
    float xv[2];
    #pragma unroll
    for (int r = 0; r < 2; r++)
        xv[r] = x[(row0 + rbase + r) * C_ + col];

    {
        const int w8 = wid & 7;
        #pragma unroll
        for (int r = 0; r < 2; r++) {
            float s = xv[r], q = xv[r] * xv[r];
            #pragma unroll
            for (int o = 16; o; o >>= 1) {
                s += __shfl_xor_sync(0xffffffffu, s, o);
                q += __shfl_xor_sync(0xffffffffu, q, o);
            }
            if (lane == 0) { sred[rbase + r][w8][0] = s; sred[rbase + r][w8][1] = q; }
        }
    }
    __syncthreads();
    if (wid < 4) {
        float s = (lane < 8) ? sred[wid][lane][0] : 0.f;
        float q = (lane < 8) ? sred[wid][lane][1] : 0.f;
        #pragma unroll
        for (int o = 4; o; o >>= 1) {
            s += __shfl_xor_sync(0xffffffffu, s, o);
            q += __shfl_xor_sync(0xffffffffu, q, o);
        }
        if (lane == 0) {
            const float mu = s * (1.0f / C_);
            const float var = q * (1.0f / C_) - mu * mu;
            smu[wid] = mu;
            ssc[wid] = rsqrtf(var + 1e-5f);
        }
    }
    __syncthreads();
    #pragma unroll
    for (int r = 0; r < 2; r++)
        sY[rbase + r][col] = (xv[r] - smu[rbase + r]) * ssc[rbase + r] * gv + bv;
    __syncthreads();

    // --- GEMM1: y @ W_in, K=256 split 128/128 across kh, 4x k-unroll ---
    float acc[4];
    #pragma unroll
    for (int r = 0; r < 4; r++) acc[r] = 0.f;
    {
        const int kb = kh * 128;
        for (int k = kb; k < kb + 128; k += 4) {
            const float w0 = Win[(k + 0) * C_ + col];
            const float w1 = Win[(k + 1) * C_ + col];
            const float w2 = Win[(k + 2) * C_ + col];
            const float w3 = Win[(k + 3) * C_ + col];
            #pragma unroll
            for (int r = 0; r < 4; r++) {
                const float4 y = *(const float4*)&sY[r][k];
                acc[r] += y.x * w0 + y.y * w1 + y.z * w2 + y.w * w3;
            }
        }
    }
    if (kh == 1) {
        #pragma unroll
        for (int r = 0; r < 4; r++) pp[r][col] = acc[r];
    }
    __syncthreads();

    if (kh == 0) {
        const float bi0 = bin[col];
        float hr[4];
        #pragma unroll
        for (int r = 0; r < 4; r += 2)
            gelu2_f(acc[r] + pp[r][col] + bi0,
                    acc[r + 1] + pp[r + 1][col] + bi0, hr[r], hr[r + 1]);
        if (col < HALF_) {
            #pragma unroll
            for (int r = 0; r < 4; r++) sY[r][col] = hr[r];
        } else {
            #pragma unroll
            for (int r = 0; r < 4; r++)
                g_hg[(row0 + r) * HALF_ + col - HALF_] = hr[r];
        }
    }
    __syncthreads();

    // --- GEMM2: h_loc @ W1[0:128], K=128 split 64/64 across kh, 4x unroll ---
    float a2[4];
    #pragma unroll
    for (int r = 0; r < 4; r++) a2[r] = 0.f;
    {
        const int kb = kh * 64;
        for (int k = kb; k < kb + 64; k += 4) {
            const float w0 = W1[(k + 0) * C_ + col];
            const float w1 = W1[(k + 1) * C_ + col];
            const float w2 = W1[(k + 2) * C_ + col];
            const float w3 = W1[(k + 3) * C_ + col];
            #pragma unroll
            for (int r = 0; r < 4; r++) {
                const float4 y = *(const float4*)&sY[r][k];
                a2[r] += y.x * w0 + y.y * w1 + y.z * w2 + y.w * w3;
            }
        }
    }
    if (kh == 1) {
        #pragma unroll
        for (int r = 0; r < 4; r++) pp[r][col] = a2[r];
    }
    __syncthreads();
    if (kh == 0) {
        #pragma unroll
        for (int r = 0; r < 4; r++)
            g_Ah[(row0 + r) * C_ + col] = __float2half_rn(a2[r] + pp[r][col]);
    }
}

// ---------------------------------------------------------------------------
// K23: combined prologue.  grid = 218 CTAs x 512 thr.
//   blocks 0..199   : Cq[b,i,:] = query[i,b,:] @ W1[256:512]  (split-K over 2)
//   blocks 200..201 : glob + gt (needs g_hg from k1)
//   blocks 202..217 : W2h transpose to fp16
// ---------------------------------------------------------------------------
__global__ void __launch_bounds__(512) k23_pre(
    const float* __restrict__ query, const float* __restrict__ W1,
    const float* __restrict__ policy, const float* __restrict__ b1,
    const float* __restrict__ W2)
{
    const int blk = blockIdx.x;
    const int tid = threadIdx.x;

    if (blk < 200) {
        __shared__ float sQ[C_];
        __shared__ float pq[C_];
        const int b = blk / NQ_, i = blk % NQ_;
        const int col = tid & 255;
        const int kh = tid >> 8;
        if (tid < C_) sQ[tid] = query[(i * B_ + b) * C_ + tid];
        __syncthreads();

        float a[8];
        #pragma unroll
        for (int u = 0; u < 8; u++) a[u] = 0.f;
        const int kb = kh * 128;
        #pragma unroll 4
        for (int k = kb; k < kb + 128; k += 8) {
            #pragma unroll
            for (int u = 0; u < 8; u++)
                a[u] += sQ[k + u] * W1[(C_ + k + u) * C_ + col];
        }
        const float sum =
            ((a[0] + a[1]) + (a[2] + a[3])) + ((a[4] + a[5]) + (a[6] + a[7]));
        if (kh == 1) pq[col] = sum;
        __syncthreads();
        if (kh == 0) g_Cq[blk * C_ + col] = sum + pq[col];
    } else if (blk < 202) {
        const int b = blk - 200;
        const int lane = tid & 31, wid = tid >> 5;
        __shared__ float spol[N_];
        __shared__ float sred[16];
        __shared__ float sps;
        __shared__ float sG[4][HALF_];
        __shared__ float sglob[HALF_];

        float ps = 0.f;
        #pragma unroll
        for (int i = 0; i < 2; i++) {
            const float p = policy[b * N_ + tid + i * 512];
            spol[tid + i * 512] = p;
            ps += p;
        }
        #pragma unroll
        for (int o = 16; o; o >>= 1) ps += __shfl_xor_sync(0xffffffffu, ps, o);
        if (lane == 0) sred[wid] = ps;
        __syncthreads();

        const int c = tid & 127, sl = tid >> 7;     // 4 slices of 256 t
        float acc = 0.f;
        for (int t = sl * 256; t < sl * 256 + 256; t++)
            acc += g_hg[(b * N_ + t) * HALF_ + c] * spol[t];
        sG[sl][c] = acc;
        if (tid == 0) {
            float s = 0.f;
            #pragma unroll
            for (int w = 0; w < 16; w++) s += sred[w];
            sps = s;
        }
        __syncthreads();
        if (tid < HALF_)
            sglob[tid] = (sG[0][tid] + sG[1][tid] + sG[2][tid] + sG[3][tid]) / sps;
        __syncthreads();

        if (tid < C_) {
            float g = b1[tid];
            for (int k = 0; k < HALF_; k++)
                g += sglob[k] * W1[(HALF_ + k) * C_ + tid];
            g_gt[b * C_ + tid] = g;
        }
    } else {
        const int base = (blk - 202) * 2048;
        #pragma unroll
        for (int i = 0; i < 4; i++) {
            const int lin = base + i * 512 + tid;   // index into W2 [k][j]
            const int k = lin >> 7, j = lin & 127;
            g_W2h[j * C_ + k] = __float2half_rn(W2[lin]);
        }
    }
}

// ---------------------------------------------------------------------------
// K4: fused  u = gelu(Aloc[b,t]+Cq[b,i]+gt[b]) ; v = gelu(u@W2+b2) ;
//            w = v@W3+b3 ; out = log_softmax(w)
// fp16 mma.sync m16n8k16, fp32 accum. Double-buffered K-chunks of 64.
// grid (8, 200), 256 threads = 8 warps (2x4 warp tile over 128x128).
// ---------------------------------------------------------------------------
#define KC  64                 // K elements per chunk
#define US  72                 // smem row stride in halves (pad 8)
#define UBUF (128 * US)        // halves per buffer

__global__ void __launch_bounds__(256, 2) k4_h16(
    const float* __restrict__ b2v,
    const float* __restrict__ W3, const float* __restrict__ b3,
    float* __restrict__ out)
{
    extern __shared__ __half dynh[];
    __half* sU = dynh;                  // [2][128*US] gelu tile (fp16)
    __half* sW = dynh + 2 * UBUF;       // [2][128*US] W2 chunk  (fp16)

    __shared__ __align__(16) float sC[C_];
    __shared__ float sB2[HALF_];
    __shared__ float sW3[2 * HALF_];
    __shared__ float sPW[4][HALF_][2];

    const int tid = threadIdx.x;
    const int lane = tid & 31, warp = tid >> 5;
    const int wm = warp >> 2, wn = warp & 3;  // 2x4 warp grid
    const int g = lane >> 2, tig = lane & 3;

    const int bi = blockIdx.y;            // b*100 + i
    const int b = bi / NQ_;
    const int t0 = blockIdx.x * 128;
    const __half* aBase = g_Ah + (b * N_ + t0) * C_;

    sC[tid] = g_Cq[bi * C_ + tid] + g_gt[b * C_ + tid];
    if (tid < HALF_) sB2[tid] = b2v[tid];
    sW3[tid] = W3[tid];

    float acc[4][4][4];
    #pragma unroll
    for (int mi = 0; mi < 4; mi++)
        #pragma unroll
        for (int ni = 0; ni < 4; ni++)
            #pragma unroll
            for (int q = 0; q < 4; q++) acc[mi][ni][q] = 0.f;
    __syncthreads();   // sC ready before first fill

    // fill chunk 0 into buffer 0
    {
        __half* uDst = sU;
        __half* wDst = sW;
        #pragma unroll
        for (int i = 0; i < 4; i++) {
            const int e = tid + i * 256;
            const int t = e >> 3, q = e & 7;       // q: 8-half group in [0,64)
            const uint4 a4 = *(const uint4*)(aBase + t * C_ + q * 8);
            const float2 a0 = __half22float2(*(const __half2*)&a4.x);
            const float2 a1 = __half22float2(*(const __half2*)&a4.y);
            const float2 a2 = __half22float2(*(const __half2*)&a4.z);
            const float2 a3 = __half22float2(*(const __half2*)&a4.w);
            const float4 c0 = *(const float4*)(sC + q * 8);
            const float4 c1 = *(const float4*)(sC + q * 8 + 4);
            uint4 u;
            u.x = gelu2_h2(a0.x + c0.x, a0.y + c0.y);
            u.y = gelu2_h2(a1.x + c0.z, a1.y + c0.w);
            u.z = gelu2_h2(a2.x + c1.x, a2.y + c1.y);
            u.w = gelu2_h2(a3.x + c1.z, a3.y + c1.w);
            *(uint4*)(uDst + t * US + q * 8) = u;
        }
        #pragma unroll
        for (int i = 0; i < 4; i++) {
            const int e = tid + i * 256;
            const int j = e >> 3, q = e & 7;
            *(uint4*)(wDst + j * US + q * 8) =
                *(const uint4*)(g_W2h + j * C_ + q * 8);
        }
    }
    __syncthreads();

    for (int c = 0; c < 4; c++) {
        const __half* bU = sU + (c & 1) * UBUF;
        const __half* bW = sW + (c & 1) * UBUF;

        #pragma unroll
        for (int ks = 0; ks < KC; ks += 16) {
            uint32_t af[4][4], bf[4][2];
            #pragma unroll
            for (int mi = 0; mi < 4; mi++) {
                const int row = wm * 64 + mi * 16 + g;
                af[mi][0] = *(const uint32_t*)(bU + row * US + ks + 2 * tig);
                af[mi][1] = *(const uint32_t*)(bU + (row + 8) * US + ks + 2 * tig);
                af[mi][2] = *(const uint32_t*)(bU + row * US + ks + 2 * tig + 8);
                af[mi][3] = *(const uint32_t*)(bU + (row + 8) * US + ks + 2 * tig + 8);
            }
            #pragma unroll
            for (int ni = 0; ni < 4; ni++) {
                const int j = wn * 32 + ni * 8 + g;
                bf[ni][0] = *(const uint32_t*)(bW + j * US + ks + 2 * tig);
                bf[ni][1] = *(const uint32_t*)(bW + j * US + ks + 2 * tig + 8);
            }
            #pragma unroll
            for (int mi = 0; mi < 4; mi++)
                #pragma unroll
                for (int ni = 0; ni < 4; ni++)
                    mma_f16(acc[mi][ni], af[mi], bf[ni]);
        }

        if (c < 3) {
            const int k0 = (c + 1) * KC;
            __half* uDst = sU + ((c + 1) & 1) * UBUF;
            __half* wDst = sW + ((c + 1) & 1) * UBUF;
            #pragma unroll
            for (int i = 0; i < 4; i++) {
                const int e = tid + i * 256;
                const int t = e >> 3, q = e & 7;
                const uint4 a4 = *(const uint4*)(aBase + t * C_ + k0 + q * 8);
                const float2 a0 = __half22float2(*(const __half2*)&a4.x);
                const float2 a1 = __half22float2(*(const __half2*)&a4.y);
                const float2 a2 = __half22float2(*(const __half2*)&a4.z);
                const float2 a3 = __half22float2(*(const __half2*)&a4.w);
                const float4 c0 = *(const float4*)(sC + k0 + q * 8);
                const float4 c1 = *(const float4*)(sC + k0 + q * 8 + 4);
                uint4 u;
                u.x = gelu2_h2(a0.x + c0.x, a0.y + c0.y);
                u.y = gelu2_h2(a1.x + c0.z, a1.y + c0.w);
                u.z = gelu2_h2(a2.x + c1.x, a2.y + c1.y);
                u.w = gelu2_h2(a3.x + c1.z, a3.y + c1.w);
                *(uint4*)(uDst + t * US + q * 8) = u;
            }
            #pragma unroll
            for (int i = 0; i < 4; i++) {
                const int e = tid + i * 256;
                const int j = e >> 3, q = e & 7;
                *(uint4*)(wDst + j * US + q * 8) =
                    *(const uint4*)(g_W2h + j * C_ + k0 + q * 8);
            }
        }
        __syncthreads();
    }

    // Epilogue: v = gelu(acc + b2), partial w = v @ W3 per warp, reduce.
    #pragma unroll
    for (int mi = 0; mi < 4; mi++) {
        float p00 = 0.f, p01 = 0.f, p10 = 0.f, p11 = 0.f;
        #pragma unroll
        for (int ni = 0; ni < 4; ni++) {
            const int jb = wn * 32 + ni * 8 + tig * 2;
            float v0, v1, v2, v3;
            gelu2_f(acc[mi][ni][0] + sB2[jb], acc[mi][ni][1] + sB2[jb + 1], v0, v1);
            gelu2_f(acc[mi][ni][2] + sB2[jb], acc[mi][ni][3] + sB2[jb + 1], v2, v3);
            p00 += v0 * sW3[2 * jb]     + v1 * sW3[2 * jb + 2];
            p01 += v0 * sW3[2 * jb + 1] + v1 * sW3[2 * jb + 3];
            p10 += v2 * sW3[2 * jb]     + v3 * sW3[2 * jb + 2];
            p11 += v2 * sW3[2 * jb + 1] + v3 * sW3[2 * jb + 3];
        }
        #pragma unroll
        for (int o = 1; o < 4; o <<= 1) {
            p00 += __shfl_xor_sync(0xffffffffu, p00, o);
            p01 += __shfl_xor_sync(0xffffffffu, p01, o);
            p10 += __shfl_xor_sync(0xffffffffu, p10, o);
            p11 += __shfl_xor_sync(0xffffffffu, p11, o);
        }
        if (tig == 0) {
            const int r0 = wm * 64 + mi * 16 + g;
            sPW[wn][r0][0] = p00;  sPW[wn][r0][1] = p01;
            sPW[wn][r0 + 8][0] = p10;  sPW[wn][r0 + 8][1] = p11;
        }
    }
    __syncthreads();

    if (tid < HALF_) {
        float w0 = b3[0], w1 = b3[1];
        #pragma unroll
        for (int w = 0; w < 4; w++) {
            w0 += sPW[w][tid][0];
            w1 += sPW[w][tid][1];
        }
        const float m = fmaxf(w0, w1);
        const float l = m + logf(expf(w0 - m) + expf(w1 - m));
        const int t = t0 + tid;
        const long long o0 = ((long long)bi * N_ + t) * 2;
        out[o0]     = w0 - l;
        out[o0 + 1] = w1 - l;
    }
}

// ---------------------------------------------------------------------------
extern "C" void kernel_launch(void* const* d_in, const int* in_sizes, int n_in,
                              void* d_out, int out_size)
{
    const float* x      = (const float*)d_in[0];
    const float* query  = (const float*)d_in[1];
    const float* policy = (const float*)d_in[2];
    const float* ln_g   = (const float*)d_in[3];
    const float* ln_b   = (const float*)d_in[4];
    const float* W_in   = (const float*)d_in[5];
    const float* b_in   = (const float*)d_in[6];
    const float* W1     = (const float*)d_in[7];
    const float* b1     = (const float*)d_in[8];
    const float* W2     = (const float*)d_in[9];
    const float* b2     = (const float*)d_in[10];
    const float* W3     = (const float*)d_in[11];
    const float* b3     = (const float*)d_in[12];
    float* out = (float*)d_out;

    const int dyn_bytes = 4 * UBUF * (int)sizeof(__half);  // 73728
    cudaFuncSetAttribute(k4_h16, cudaFuncAttributeMaxDynamicSharedMemorySize,
                         dyn_bytes);

    k1_ln_gemm_gelu<<<(B_ * N_) / 4, 512>>>(x, ln_g, ln_b, W_in, b_in, W1);
    k23_pre<<<218, 512>>>(query, W1, policy, b1, W2);
    k4_h16<<<dim3(N_ / 128, B_ * NQ_), 256, dyn_bytes>>>(b2, W3, b3, out);
}

// round 12
// speedup vs baseline: 3.5067x; 1.0518x over previous
#include <cuda_runtime.h>
#include <math.h>
#include <stdint.h>
#include <cuda_fp16.h>

// Problem dims (fixed by the dataset)
#define B_  2
#define N_  1024
#define C_  256
#define NQ_ 100
#define HALF_ 128

// Scratch (device globals: no allocation allowed)
__device__ __half g_Ah[B_ * N_ * C_];      // h_loc @ W1a (fp16)   (per b,t)
__device__ float  g_hg[B_ * N_ * HALF_];   // h glob half          (per b,t)
__device__ float  g_Cq[B_ * NQ_ * C_];     // q@W1c                (per b,i)
__device__ float  g_gt[B_ * C_];           // glob@W1b + b1        (per b)
__device__ __half g_W2h[HALF_ * C_];       // W2 transposed [j][k], fp16

// ---------------------------------------------------------------------------
// gelu, scalar (A-S 7.1.26 erf, |err|<=1.5e-7, branchless)
// ---------------------------------------------------------------------------
__device__ __forceinline__ float gelu_f(float x) {
    const float ax = fabsf(x) * 0.70710678118654752440f;
    const float t = __fdividef(1.0f, fmaf(0.3275911f, ax, 1.0f));
    float p = fmaf(1.061405429f, t, -1.453152027f);
    p = fmaf(p, t, 1.421413741f);
    p = fmaf(p, t, -0.284496736f);
    p = fmaf(p, t, 0.254829592f);
    p = p * t;
    const float e = __expf(-ax * ax);
    const float er = fmaf(-p, e, 1.0f);
    const float s = copysignf(er, x);
    return 0.5f * x * (1.0f + s);
}

// ---------------------------------------------------------------------------
// gelu, packed 2-wide via f32x2 (sm_100+ PTX; full fp32 precision).
// ---------------------------------------------------------------------------
__device__ __forceinline__ uint64_t dup2_(float c) {
    uint64_t r; asm("mov.b64 %0, {%1, %1};" : "=l"(r) : "f"(c)); return r;
}
#define FMA2_(d, a, b, c) asm("fma.rn.f32x2 %0, %1, %2, %3;" : "=l"(d) : "l"(a), "l"(b), "l"(c))
#define MUL2_(d, a, b)    asm("mul.rn.f32x2 %0, %1, %2;"     : "=l"(d) : "l"(a), "l"(b))
#define ADD2_(d, a, b)    asm("add.rn.f32x2 %0, %1, %2;"     : "=l"(d) : "l"(a), "l"(b))

__device__ __forceinline__ void gelu2_f(float xa, float xb, float& ra, float& rb) {
    uint64_t xp; asm("mov.b64 %0, {%1, %2};" : "=l"(xp) : "f"(xa), "f"(xb));
    const uint64_t ap = xp & 0x7FFFFFFF7FFFFFFFULL;
    uint64_t axk; MUL2_(axk, ap, dup2_(0.70710678118654752440f));
    uint64_t den; FMA2_(den, axk, dup2_(0.3275911f), dup2_(1.0f));
    float d0, d1; asm("mov.b64 {%0, %1}, %2;" : "=f"(d0), "=f"(d1) : "l"(den));
    float t0, t1;
    asm("rcp.approx.f32 %0, %1;" : "=f"(t0) : "f"(d0));
    asm("rcp.approx.f32 %0, %1;" : "=f"(t1) : "f"(d1));
    uint64_t t; asm("mov.b64 %0, {%1, %2};" : "=l"(t) : "f"(t0), "f"(t1));
    uint64_t p;
    FMA2_(p, dup2_(1.061405429f), t, dup2_(-1.453152027f));
    FMA2_(p, p, t, dup2_(1.421413741f));
    FMA2_(p, p, t, dup2_(-0.284496736f));
    FMA2_(p, p, t, dup2_(0.254829592f));
    MUL2_(p, p, t);
    uint64_t z2; MUL2_(z2, axk, axk);
    uint64_t w;  MUL2_(w, z2, dup2_(-1.4426950408889634f));   // -z^2 * log2(e)
    float w0, w1; asm("mov.b64 {%0, %1}, %2;" : "=f"(w0), "=f"(w1) : "l"(w));
    float e0, e1;
    asm("ex2.approx.f32 %0, %1;" : "=f"(e0) : "f"(w0));
    asm("ex2.approx.f32 %0, %1;" : "=f"(e1) : "f"(w1));
    uint64_t e; asm("mov.b64 %0, {%1, %2};" : "=l"(e) : "f"(e0), "f"(e1));
    uint64_t pe; MUL2_(pe, p, e);
    uint64_t er; FMA2_(er, pe, dup2_(-1.0f), dup2_(1.0f));    // 1 - p*e = erf(ax)
    const uint64_t s = er | (xp & 0x8000000080000000ULL);     // copysign (er>0)
    uint64_t onep; ADD2_(onep, s, dup2_(1.0f));
    uint64_t hx;   MUL2_(hx, xp, dup2_(0.5f));
    uint64_t res;  MUL2_(res, onep, hx);
    asm("mov.b64 {%0, %1}, %2;" : "=f"(ra), "=f"(rb) : "l"(res));
}

__device__ __forceinline__ uint32_t f2h2(float a, float b) {
    __half2 h = __floats2half2_rn(a, b);
    return *reinterpret_cast<uint32_t*>(&h);
}

__device__ __forceinline__ uint32_t gelu2_h2(float xa, float xb) {
    float ra, rb;
    gelu2_f(xa, xb, ra, rb);
    return f2h2(ra, rb);
}

__device__ __forceinline__ void mma_f16(float* d, const uint32_t* a, const uint32_t* b) {
    asm volatile(
        "mma.sync.aligned.m16n8k16.row.col.f32.f16.f16.f32 "
        "{%0,%1,%2,%3}, {%4,%5,%6,%7}, {%8,%9}, {%0,%1,%2,%3};"
        : "+f"(d[0]), "+f"(d[1]), "+f"(d[2]), "+f"(d[3])
        : "r"(a[0]), "r"(a[1]), "r"(a[2]), "r"(a[3]), "r"(b[0]), "r"(b[1]));
}

#define LDSM_X4(r0, r1, r2, r3, addr) \
    asm volatile("ldmatrix.sync.aligned.m8n8.x4.shared.b16 {%0,%1,%2,%3}, [%4];" \
        : "=r"(r0), "=r"(r1), "=r"(r2), "=r"(r3) : "r"(addr))

__device__ __forceinline__ void cp16(uint32_t saddr, const void* gaddr) {
    asm volatile("cp.async.cg.shared.global [%0], [%1], 16;"
                 :: "r"(saddr), "l"(gaddr) : "memory");
}

// ---------------------------------------------------------------------------
// K1: h = gelu(LN(x) @ W_in + b_in);  A_loc = h[:, :128] @ W1[0:128] (fp16)
// 8 rows per block, 1024 threads, 4-way split-K: thread = (col, kq).
// ---------------------------------------------------------------------------
__global__ void __launch_bounds__(1024) k1_ln_gemm_gelu(
    const float* __restrict__ x, const float* __restrict__ ln_g,
    const float* __restrict__ ln_b, const float* __restrict__ Win,
    const float* __restrict__ bin, const float* __restrict__ W1)
{
    __shared__ __align__(16) float sY[8][C_];
    __shared__ float pp[3][8][C_];
    __shared__ float sred[8][8][2];
    __shared__ float smu[8], ssc[8];

    const int tid = threadIdx.x;
    const int col = tid & 255;
    const int kq  = tid >> 8;            // 0..3
    const int lane = tid & 31;
    const int wid  = tid >> 5;           // 0..31
    const int row0 = blockIdx.x * 8;

    const float gv = ln_g[col];
    const float bv = ln_b[col];

    // --- stats: quarter kq owns rows kq*2, kq*2+1 ---
    const int rbase = kq * 2;
    float xv[2];
    #pragma unroll
    for (int r = 0; r < 2; r++)
        xv[r] = x[(row0 + rbase + r) * C_ + col];

    {
        const int w8 = wid & 7;
        #pragma unroll
        for (int r = 0; r < 2; r++) {
            float s = xv[r], q = xv[r] * xv[r];
            #pragma unroll
            for (int o = 16; o; o >>= 1) {
                s += __shfl_xor_sync(0xffffffffu, s, o);
                q += __shfl_xor_sync(0xffffffffu, q, o);
            }
            if (lane == 0) { sred[rbase + r][w8][0] = s; sred[rbase + r][w8][1] = q; }
        }
    }
    __syncthreads();
    if (wid < 8) {
        float s = (lane < 8) ? sred[wid][lane][0] : 0.f;
        float q = (lane < 8) ? sred[wid][lane][1] : 0.f;
        #pragma unroll
        for (int o = 4; o; o >>= 1) {
            s += __shfl_xor_sync(0xffffffffu, s, o);
            q += __shfl_xor_sync(0xffffffffu, q, o);
        }
        if (lane == 0) {
            const float mu = s * (1.0f / C_);
            const float var = q * (1.0f / C_) - mu * mu;
            smu[wid] = mu;
            ssc[wid] = rsqrtf(var + 1e-5f);
        }
    }
    __syncthreads();
    #pragma unroll
    for (int r = 0; r < 2; r++)
        sY[rbase + r][col] = (xv[r] - smu[rbase + r]) * ssc[rbase + r] * gv + bv;
    __syncthreads();

    // --- GEMM1: y @ W_in, K=256 split 64/64/64/64 across kq ---
    float acc[8];
    #pragma unroll
    for (int r = 0; r < 8; r++) acc[r] = 0.f;
    {
        const int kb = kq * 64;
        for (int k = kb; k < kb + 64; k += 4) {
            const float w0 = Win[(k + 0) * C_ + col];
            const float w1 = Win[(k + 1) * C_ + col];
            const float w2 = Win[(k + 2) * C_ + col];
            const float w3 = Win[(k + 3) * C_ + col];
            #pragma unroll
            for (int r = 0; r < 8; r++) {
                const float4 y = *(const float4*)&sY[r][k];
                acc[r] += y.x * w0 + y.y * w1 + y.z * w2 + y.w * w3;
            }
        }
    }
    if (kq > 0) {
        #pragma unroll
        for (int r = 0; r < 8; r++) pp[kq - 1][r][col] = acc[r];
    }
    __syncthreads();

    if (kq == 0) {
        const float bi0 = bin[col];
        float hr[8];
        #pragma unroll
        for (int r = 0; r < 8; r += 2) {
            const float s0 = acc[r] + pp[0][r][col] + pp[1][r][col] + pp[2][r][col] + bi0;
            const float s1 = acc[r + 1] + pp[0][r + 1][col] + pp[1][r + 1][col] + pp[2][r + 1][col] + bi0;
            gelu2_f(s0, s1, hr[r], hr[r + 1]);
        }
        if (col < HALF_) {
            #pragma unroll
            for (int r = 0; r < 8; r++) sY[r][col] = hr[r];
        } else {
            #pragma unroll
            for (int r = 0; r < 8; r++)
                g_hg[(row0 + r) * HALF_ + col - HALF_] = hr[r];
        }
    }
    __syncthreads();

    // --- GEMM2: h_loc @ W1[0:128], K=128 split 32x4 across kq ---
    float a2[8];
    #pragma unroll
    for (int r = 0; r < 8; r++) a2[r] = 0.f;
    {
        const int kb = kq * 32;
        for (int k = kb; k < kb + 32; k += 4) {
            const float w0 = W1[(k + 0) * C_ + col];
            const float w1 = W1[(k + 1) * C_ + col];
            const float w2 = W1[(k + 2) * C_ + col];
            const float w3 = W1[(k + 3) * C_ + col];
            #pragma unroll
            for (int r = 0; r < 8; r++) {
                const float4 y = *(const float4*)&sY[r][k];
                a2[r] += y.x * w0 + y.y * w1 + y.z * w2 + y.w * w3;
            }
        }
    }
    if (kq > 0) {
        #pragma unroll
        for (int r = 0; r < 8; r++) pp[kq - 1][r][col] = a2[r];
    }
    __syncthreads();
    if (kq == 0) {
        #pragma unroll
        for (int r = 0; r < 8; r++)
            g_Ah[(row0 + r) * C_ + col] =
                __float2half_rn(a2[r] + pp[0][r][col] + pp[1][r][col] + pp[2][r][col]);
    }
}

// ---------------------------------------------------------------------------
// K23: combined prologue.  grid = 218 CTAs x 512 thr.
// ---------------------------------------------------------------------------
__global__ void __launch_bounds__(512) k23_pre(
    const float* __restrict__ query, const float* __restrict__ W1,
    const float* __restrict__ policy, const float* __restrict__ b1,
    const float* __restrict__ W2)
{
    const int blk = blockIdx.x;
    const int tid = threadIdx.x;

    if (blk < 200) {
        __shared__ float sQ[C_];
        __shared__ float pq[C_];
        const int b = blk / NQ_, i = blk % NQ_;
        const int col = tid & 255;
        const int kh = tid >> 8;
        if (tid < C_) sQ[tid] = query[(i * B_ + b) * C_ + tid];
        __syncthreads();

        float a[8];
        #pragma unroll
        for (int u = 0; u < 8; u++) a[u] = 0.f;
        const int kb = kh * 128;
        #pragma unroll 4
        for (int k = kb; k < kb + 128; k += 8) {
            #pragma unroll
            for (int u = 0; u < 8; u++)
                a[u] += sQ[k + u] * W1[(C_ + k + u) * C_ + col];
        }
        const float sum =
            ((a[0] + a[1]) + (a[2] + a[3])) + ((a[4] + a[5]) + (a[6] + a[7]));
        if (kh == 1) pq[col] = sum;
        __syncthreads();
        if (kh == 0) g_Cq[blk * C_ + col] = sum + pq[col];
    } else if (blk < 202) {
        const int b = blk - 200;
        const int lane = tid & 31, wid = tid >> 5;
        __shared__ float spol[N_];
        __shared__ float sred[16];
        __shared__ float sps;
        __shared__ float sG[4][HALF_];
        __shared__ float sglob[HALF_];

        float ps = 0.f;
        #pragma unroll
        for (int i = 0; i < 2; i++) {
            const float p = policy[b * N_ + tid + i * 512];
            spol[tid + i * 512] = p;
            ps += p;
        }
        #pragma unroll
        for (int o = 16; o; o >>= 1) ps += __shfl_xor_sync(0xffffffffu, ps, o);
        if (lane == 0) sred[wid] = ps;
        __syncthreads();

        const int c = tid & 127, sl = tid >> 7;     // 4 slices of 256 t
        float acc = 0.f;
        for (int t = sl * 256; t < sl * 256 + 256; t++)
            acc += g_hg[(b * N_ + t) * HALF_ + c] * spol[t];
        sG[sl][c] = acc;
        if (tid == 0) {
            float s = 0.f;
            #pragma unroll
            for (int w = 0; w < 16; w++) s += sred[w];
            sps = s;
        }
        __syncthreads();
        if (tid < HALF_)
            sglob[tid] = (sG[0][tid] + sG[1][tid] + sG[2][tid] + sG[3][tid]) / sps;
        __syncthreads();

        if (tid < C_) {
            float g = b1[tid];
            for (int k = 0; k < HALF_; k++)
                g += sglob[k] * W1[(HALF_ + k) * C_ + tid];
            g_gt[b * C_ + tid] = g;
        }
    } else {
        const int base = (blk - 202) * 2048;
        #pragma unroll
        for (int i = 0; i < 4; i++) {
            const int lin = base + i * 512 + tid;   // index into W2 [k][j]
            const int k = lin >> 7, j = lin & 127;
            g_W2h[j * C_ + k] = __float2half_rn(W2[lin]);
        }
    }
}

// ---------------------------------------------------------------------------
// K4: fused  u = gelu(Aloc[b,t]+Cq[b,i]+gt[b]) ; v = gelu(u@W2+b2) ;
//            w = v@W3+b3 ; out = log_softmax(w)
// fp16 mma.sync + ldmatrix + cp.async W fill. Double-buffered K-chunks of 64.
// grid (8, 200), 256 threads = 8 warps (2x4 warp tile over 128x128).
// ---------------------------------------------------------------------------
#define KC  64                 // K elements per chunk
#define US  72                 // smem row stride in halves (pad 8)
#define UBUF (128 * US)        // halves per buffer

__global__ void __launch_bounds__(256, 2) k4_h16(
    const float* __restrict__ b2v,
    const float* __restrict__ W3, const float* __restrict__ b3,
    float* __restrict__ out)
{
    extern __shared__ __half dynh[];
    __half* sU = dynh;                  // [2][128*US] gelu tile (fp16)
    __half* sW = dynh + 2 * UBUF;       // [2][128*US] W2 chunk  (fp16)

    __shared__ __align__(16) float sC[C_];
    __shared__ float sB2[HALF_];
    __shared__ float sW3[2 * HALF_];
    __shared__ float sPW[4][HALF_][2];

    const int tid = threadIdx.x;
    const int lane = tid & 31, warp = tid >> 5;
    const int wm = warp >> 2, wn = warp & 3;  // 2x4 warp grid
    const int g = lane >> 2, tig = lane & 3;

    const int bi = blockIdx.y;            // b*100 + i
    const int b = bi / NQ_;
    const int t0 = blockIdx.x * 128;
    const __half* aBase = g_Ah + (b * N_ + t0) * C_;

    const uint32_t sU0 = (uint32_t)__cvta_generic_to_shared(sU);
    const uint32_t sW0 = (uint32_t)__cvta_generic_to_shared(sW);

    sC[tid] = g_Cq[bi * C_ + tid] + g_gt[b * C_ + tid];
    if (tid < HALF_) sB2[tid] = b2v[tid];
    sW3[tid] = W3[tid];

    float acc[4][4][4];
    #pragma unroll
    for (int mi = 0; mi < 4; mi++)
        #pragma unroll
        for (int ni = 0; ni < 4; ni++)
            #pragma unroll
            for (int q = 0; q < 4; q++) acc[mi][ni][q] = 0.f;
    __syncthreads();   // sC ready before first fill

    // ldmatrix per-thread address components (halves offsets; x2 for bytes)
    const int aRow = (lane & 15);                    // + wm*64 + mi*16
    const int aKo  = (lane >> 4) << 3;
    const int bRow = ((lane >> 4) << 3) + (lane & 7);  // + wn*32 + nig*16
    const int bKo  = ((lane >> 3) & 1) << 3;

    // fill chunk 0 into buffer 0
    {
        #pragma unroll
        for (int i = 0; i < 4; i++) {
            const int e = tid + i * 256;
            const int j = e >> 3, q = e & 7;
            cp16(sW0 + (j * US + q * 8) * 2, g_W2h + j * C_ + q * 8);
        }
        asm volatile("cp.async.commit_group;" ::: "memory");
        #pragma unroll
        for (int i = 0; i < 4; i++) {
            const int e = tid + i * 256;
            const int t = e >> 3, q = e & 7;       // q: 8-half group in [0,64)
            const uint4 a4 = *(const uint4*)(aBase + t * C_ + q * 8);
            const float2 a0 = __half22float2(*(const __half2*)&a4.x);
            const float2 a1 = __half22float2(*(const __half2*)&a4.y);
            const float2 a2 = __half22float2(*(const __half2*)&a4.z);
            const float2 a3 = __half22float2(*(const __half2*)&a4.w);
            const float4 c0 = *(const float4*)(sC + q * 8);
            const float4 c1 = *(const float4*)(sC + q * 8 + 4);
            uint4 u;
            u.x = gelu2_h2(a0.x + c0.x, a0.y + c0.y);
            u.y = gelu2_h2(a1.x + c0.z, a1.y + c0.w);
            u.z = gelu2_h2(a2.x + c1.x, a2.y + c1.y);
            u.w = gelu2_h2(a3.x + c1.z, a3.y + c1.w);
            *(uint4*)(sU + t * US + q * 8) = u;
        }
        asm volatile("cp.async.wait_group 0;" ::: "memory");
    }
    __syncthreads();

    for (int c = 0; c < 4; c++) {
        const uint32_t uB = sU0 + (c & 1) * (UBUF * 2);
        const uint32_t wB = sW0 + (c & 1) * (UBUF * 2);
        const uint32_t aPre = uB + ((wm * 64 + aRow) * US + aKo) * 2;
        const uint32_t bPre = wB + ((wn * 32 + bRow) * US + bKo) * 2;

        #pragma unroll
        for (int ks = 0; ks < KC; ks += 16) {
            uint32_t af[4][4], bf[4][2];
            #pragma unroll
            for (int mi = 0; mi < 4; mi++)
                LDSM_X4(af[mi][0], af[mi][1], af[mi][2], af[mi][3],
                        aPre + (mi * 16 * US + ks) * 2);
            LDSM_X4(bf[0][0], bf[0][1], bf[1][0], bf[1][1], bPre + ks * 2);
            LDSM_X4(bf[2][0], bf[2][1], bf[3][0], bf[3][1],
                    bPre + (16 * US + ks) * 2);
            #pragma unroll
            for (int mi = 0; mi < 4; mi++)
                #pragma unroll
                for (int ni = 0; ni < 4; ni++)
                    mma_f16(acc[mi][ni], af[mi], bf[ni]);
        }

        if (c < 3) {
            const int k0 = (c + 1) * KC;
            const uint32_t wN = sW0 + ((c + 1) & 1) * (UBUF * 2);
            __half* uDst = sU + ((c + 1) & 1) * UBUF;
            #pragma unroll
            for (int i = 0; i < 4; i++) {
                const int e = tid + i * 256;
                const int j = e >> 3, q = e & 7;
                cp16(wN + (j * US + q * 8) * 2, g_W2h + j * C_ + k0 + q * 8);
            }
            asm volatile("cp.async.commit_group;" ::: "memory");
            #pragma unroll
            for (int i = 0; i < 4; i++) {
                const int e = tid + i * 256;
                const int t = e >> 3, q = e & 7;
                const uint4 a4 = *(const uint4*)(aBase + t * C_ + k0 + q * 8);
                const float2 a0 = __half22float2(*(const __half2*)&a4.x);
                const float2 a1 = __half22float2(*(const __half2*)&a4.y);
                const float2 a2 = __half22float2(*(const __half2*)&a4.z);
                const float2 a3 = __half22float2(*(const __half2*)&a4.w);
                const float4 c0 = *(const float4*)(sC + k0 + q * 8);
                const float4 c1 = *(const float4*)(sC + k0 + q * 8 + 4);
                uint4 u;
                u.x = gelu2_h2(a0.x + c0.x, a0.y + c0.y);
                u.y = gelu2_h2(a1.x + c0.z, a1.y + c0.w);
                u.z = gelu2_h2(a2.x + c1.x, a2.y + c1.y);
                u.w = gelu2_h2(a3.x + c1.z, a3.y + c1.w);
                *(uint4*)(uDst + t * US + q * 8) = u;
            }
            asm volatile("cp.async.wait_group 0;" ::: "memory");
        }
        __syncthreads();
    }

    // Epilogue: v = gelu(acc + b2), partial w = v @ W3 per warp, reduce.
    #pragma unroll
    for (int mi = 0; mi < 4; mi++) {
        float p00 = 0.f, p01 = 0.f, p10 = 0.f, p11 = 0.f;
        #pragma unroll
        for (int ni = 0; ni < 4; ni++) {
            const int jb = wn * 32 + ni * 8 + tig * 2;
            float v0, v1, v2, v3;
            gelu2_f(acc[mi][ni][0] + sB2[jb], acc[mi][ni][1] + sB2[jb + 1], v0, v1);
            gelu2_f(acc[mi][ni][2] + sB2[jb], acc[mi][ni][3] + sB2[jb + 1], v2, v3);
            p00 += v0 * sW3[2 * jb]     + v1 * sW3[2 * jb + 2];
            p01 += v0 * sW3[2 * jb + 1] + v1 * sW3[2 * jb + 3];
            p10 += v2 * sW3[2 * jb]     + v3 * sW3[2 * jb + 2];
            p11 += v2 * sW3[2 * jb + 1] + v3 * sW3[2 * jb + 3];
        }
        #pragma unroll
        for (int o = 1; o < 4; o <<= 1) {
            p00 += __shfl_xor_sync(0xffffffffu, p00, o);
            p01 += __shfl_xor_sync(0xffffffffu, p01, o);
            p10 += __shfl_xor_sync(0xffffffffu, p10, o);
            p11 += __shfl_xor_sync(0xffffffffu, p11, o);
        }
        if (tig == 0) {
            const int r0 = wm * 64 + mi * 16 + g;
            sPW[wn][r0][0] = p00;  sPW[wn][r0][1] = p01;
            sPW[wn][r0 + 8][0] = p10;  sPW[wn][r0 + 8][1] = p11;
        }
    }
    __syncthreads();

    if (tid < HALF_) {
        float w0 = b3[0], w1 = b3[1];
        #pragma unroll
        for (int w = 0; w < 4; w++) {
            w0 += sPW[w][tid][0];
            w1 += sPW[w][tid][1];
        }
        const float m = fmaxf(w0, w1);
        const float l = m + logf(expf(w0 - m) + expf(w1 - m));
        const int t = t0 + tid;
        const long long o0 = ((long long)bi * N_ + t) * 2;
        out[o0]     = w0 - l;
        out[o0 + 1] = w1 - l;
    }
}

// ---------------------------------------------------------------------------
extern "C" void kernel_launch(void* const* d_in, const int* in_sizes, int n_in,
                              void* d_out, int out_size)
{
    const float* x      = (const float*)d_in[0];
    const float* query  = (const float*)d_in[1];
    const float* policy = (const float*)d_in[2];
    const float* ln_g   = (const float*)d_in[3];
    const float* ln_b   = (const float*)d_in[4];
    const float* W_in   = (const float*)d_in[5];
    const float* b_in   = (const float*)d_in[6];
    const float* W1     = (const float*)d_in[7];
    const float* b1     = (const float*)d_in[8];
    const float* W2     = (const float*)d_in[9];
    const float* b2     = (const float*)d_in[10];
    const float* W3     = (const float*)d_in[11];
    const float* b3     = (const float*)d_in[12];
    float* out = (float*)d_out;

    const int dyn_bytes = 4 * UBUF * (int)sizeof(__half);  // 73728
    cudaFuncSetAttribute(k4_h16, cudaFuncAttributeMaxDynamicSharedMemorySize,
                         dyn_bytes);

    k1_ln_gemm_gelu<<<(B_ * N_) / 8, 1024>>>(x, ln_g, ln_b, W_in, b_in, W1);
    k23_pre<<<218, 512>>>(query, W1, policy, b1, W2);
    k4_h16<<<dim3(N_ / 128, B_ * NQ_), 256, dyn_bytes>>>(b2, W3, b3, out);
}

// round 13
// speedup vs baseline: 4.1722x; 1.1898x over previous
#include <cuda_runtime.h>
#include <math.h>
#include <stdint.h>
#include <cuda_fp16.h>

// Problem dims (fixed by the dataset)
#define B_  2
#define N_  1024
#define C_  256
#define NQ_ 100
#define HALF_ 128

// Scratch (device globals: no allocation allowed)
__device__ __half g_Ah[B_ * N_ * C_];      // h_loc @ W1a (fp16)   (per b,t)
__device__ float  g_hg[B_ * N_ * HALF_];   // h glob half          (per b,t)
__device__ float  g_Cq[B_ * NQ_ * C_];     // q@W1c                (per b,i)
__device__ float  g_gt[B_ * C_];           // glob@W1b + b1        (per b)
__device__ __half g_W2h[HALF_ * C_];       // W2 transposed [j][k], fp16

// ---------------------------------------------------------------------------
// gelu, packed helpers (f32x2, sm_100+ PTX)
// ---------------------------------------------------------------------------
__device__ __forceinline__ uint64_t dup2_(float c) {
    uint64_t r; asm("mov.b64 %0, {%1, %1};" : "=l"(r) : "f"(c)); return r;
}
#define FMA2_(d, a, b, c) asm("fma.rn.f32x2 %0, %1, %2, %3;" : "=l"(d) : "l"(a), "l"(b), "l"(c))
#define MUL2_(d, a, b)    asm("mul.rn.f32x2 %0, %1, %2;"     : "=l"(d) : "l"(a), "l"(b))
#define ADD2_(d, a, b)    asm("add.rn.f32x2 %0, %1, %2;"     : "=l"(d) : "l"(a), "l"(b))

// Exact-precision path: A-S 7.1.26 erf (|err|<=1.5e-7), packed 2-wide.
__device__ __forceinline__ void gelu2_f(float xa, float xb, float& ra, float& rb) {
    uint64_t xp; asm("mov.b64 %0, {%1, %2};" : "=l"(xp) : "f"(xa), "f"(xb));
    const uint64_t ap = xp & 0x7FFFFFFF7FFFFFFFULL;
    uint64_t axk; MUL2_(axk, ap, dup2_(0.70710678118654752440f));
    uint64_t den; FMA2_(den, axk, dup2_(0.3275911f), dup2_(1.0f));
    float d0, d1; asm("mov.b64 {%0, %1}, %2;" : "=f"(d0), "=f"(d1) : "l"(den));
    float t0, t1;
    asm("rcp.approx.f32 %0, %1;" : "=f"(t0) : "f"(d0));
    asm("rcp.approx.f32 %0, %1;" : "=f"(t1) : "f"(d1));
    uint64_t t; asm("mov.b64 %0, {%1, %2};" : "=l"(t) : "f"(t0), "f"(t1));
    uint64_t p;
    FMA2_(p, dup2_(1.061405429f), t, dup2_(-1.453152027f));
    FMA2_(p, p, t, dup2_(1.421413741f));
    FMA2_(p, p, t, dup2_(-0.284496736f));
    FMA2_(p, p, t, dup2_(0.254829592f));
    MUL2_(p, p, t);
    uint64_t z2; MUL2_(z2, axk, axk);
    uint64_t w;  MUL2_(w, z2, dup2_(-1.4426950408889634f));   // -z^2 * log2(e)
    float w0, w1; asm("mov.b64 {%0, %1}, %2;" : "=f"(w0), "=f"(w1) : "l"(w));
    float e0, e1;
    asm("ex2.approx.f32 %0, %1;" : "=f"(e0) : "f"(w0));
    asm("ex2.approx.f32 %0, %1;" : "=f"(e1) : "f"(w1));
    uint64_t e; asm("mov.b64 %0, {%1, %2};" : "=l"(e) : "f"(e0), "f"(e1));
    uint64_t pe; MUL2_(pe, p, e);
    uint64_t er; FMA2_(er, pe, dup2_(-1.0f), dup2_(1.0f));    // 1 - p*e = erf(ax)
    const uint64_t s = er | (xp & 0x8000000080000000ULL);     // copysign (er>0)
    uint64_t onep; ADD2_(onep, s, dup2_(1.0f));
    uint64_t hx;   MUL2_(hx, xp, dup2_(0.5f));
    uint64_t res;  MUL2_(res, onep, hx);
    asm("mov.b64 {%0, %1}, %2;" : "=f"(ra), "=f"(rb) : "l"(res));
}

__device__ __forceinline__ uint32_t f2h2(float a, float b) {
    __half2 h = __floats2half2_rn(a, b);
    return *reinterpret_cast<uint32_t*>(&h);
}

// Fast path for the fp16 fill: tanh-form gelu with HW tanh.approx.
// |gelu_tanh - gelu_erf| <= ~3e-4 abs; washed out through the W2 summation.
__device__ __forceinline__ uint32_t gelu2t_h2(float xa, float xb) {
    uint64_t xp; asm("mov.b64 %0, {%1, %2};" : "=l"(xp) : "f"(xa), "f"(xb));
    uint64_t z2; MUL2_(z2, xp, xp);
    uint64_t cc; FMA2_(cc, z2, dup2_(0.0356774081f), dup2_(0.7978845608f));
    uint64_t in; MUL2_(in, xp, cc);
    float i0, i1; asm("mov.b64 {%0, %1}, %2;" : "=f"(i0), "=f"(i1) : "l"(in));
    float t0, t1;
    asm("tanh.approx.f32 %0, %1;" : "=f"(t0) : "f"(i0));
    asm("tanh.approx.f32 %0, %1;" : "=f"(t1) : "f"(i1));
    uint64_t tp; asm("mov.b64 %0, {%1, %2};" : "=l"(tp) : "f"(t0), "f"(t1));
    uint64_t hf; FMA2_(hf, tp, dup2_(0.5f), dup2_(0.5f));
    uint64_t res; MUL2_(res, xp, hf);
    float ra, rb; asm("mov.b64 {%0, %1}, %2;" : "=f"(ra), "=f"(rb) : "l"(res));
    return f2h2(ra, rb);
}

__device__ __forceinline__ void mma_f16(float* d, const uint32_t* a, const uint32_t* b) {
    asm volatile(
        "mma.sync.aligned.m16n8k16.row.col.f32.f16.f16.f32 "
        "{%0,%1,%2,%3}, {%4,%5,%6,%7}, {%8,%9}, {%0,%1,%2,%3};"
        : "+f"(d[0]), "+f"(d[1]), "+f"(d[2]), "+f"(d[3])
        : "r"(a[0]), "r"(a[1]), "r"(a[2]), "r"(a[3]), "r"(b[0]), "r"(b[1]));
}

// ---------------------------------------------------------------------------
// K1: h = gelu(LN(x) @ W_in + b_in);  A_loc = h[:, :128] @ W1[0:128] (fp16)
// 8 rows per block, 1024 threads, 4-way split-K: thread = (col, kq).
// ---------------------------------------------------------------------------
__global__ void __launch_bounds__(1024) k1_ln_gemm_gelu(
    const float* __restrict__ x, const float* __restrict__ ln_g,
    const float* __restrict__ ln_b, const float* __restrict__ Win,
    const float* __restrict__ bin, const float* __restrict__ W1)
{
    __shared__ __align__(16) float sY[8][C_];
    __shared__ float pp[3][8][C_];
    __shared__ float sred[8][8][2];
    __shared__ float smu[8], ssc[8];

    const int tid = threadIdx.x;
    const int col = tid & 255;
    const int kq  = tid >> 8;            // 0..3
    const int lane = tid & 31;
    const int wid  = tid >> 5;           // 0..31
    const int row0 = blockIdx.x * 8;

    const float gv = ln_g[col];
    const float bv = ln_b[col];

    // --- stats: quarter kq owns rows kq*2, kq*2+1 ---
    const int rbase = kq * 2;
    float xv[2];
    #pragma unroll
    for (int r = 0; r < 2; r++)
        xv[r] = x[(row0 + rbase + r) * C_ + col];

    {
        const int w8 = wid & 7;
        #pragma unroll
        for (int r = 0; r < 2; r++) {
            float s = xv[r], q = xv[r] * xv[r];
            #pragma unroll
            for (int o = 16; o; o >>= 1) {
                s += __shfl_xor_sync(0xffffffffu, s, o);
                q += __shfl_xor_sync(0xffffffffu, q, o);
            }
            if (lane == 0) { sred[rbase + r][w8][0] = s; sred[rbase + r][w8][1] = q; }
        }
    }
    __syncthreads();
    if (wid < 8) {
        float s = (lane < 8) ? sred[wid][lane][0] : 0.f;
        float q = (lane < 8) ? sred[wid][lane][1] : 0.f;
        #pragma unroll
        for (int o = 4; o; o >>= 1) {
            s += __shfl_xor_sync(0xffffffffu, s, o);
            q += __shfl_xor_sync(0xffffffffu, q, o);
        }
        if (lane == 0) {
            const float mu = s * (1.0f / C_);
            const float var = q * (1.0f / C_) - mu * mu;
            smu[wid] = mu;
            ssc[wid] = rsqrtf(var + 1e-5f);
        }
    }
    __syncthreads();
    #pragma unroll
    for (int r = 0; r < 2; r++)
        sY[rbase + r][col] = (xv[r] - smu[rbase + r]) * ssc[rbase + r] * gv + bv;
    __syncthreads();

    // --- GEMM1: y @ W_in, K=256 split 64/64/64/64 across kq ---
    float acc[8];
    #pragma unroll
    for (int r = 0; r < 8; r++) acc[r] = 0.f;
    {
        const int kb = kq * 64;
        for (int k = kb; k < kb + 64; k += 4) {
            const float w0 = Win[(k + 0) * C_ + col];
            const float w1 = Win[(k + 1) * C_ + col];
            const float w2 = Win[(k + 2) * C_ + col];
            const float w3 = Win[(k + 3) * C_ + col];
            #pragma unroll
            for (int r = 0; r < 8; r++) {
                const float4 y = *(const float4*)&sY[r][k];
                acc[r] += y.x * w0 + y.y * w1 + y.z * w2 + y.w * w3;
            }
        }
    }
    if (kq > 0) {
        #pragma unroll
        for (int r = 0; r < 8; r++) pp[kq - 1][r][col] = acc[r];
    }
    __syncthreads();

    if (kq == 0) {
        const float bi0 = bin[col];
        float hr[8];
        #pragma unroll
        for (int r = 0; r < 8; r += 2) {
            const float s0 = acc[r] + pp[0][r][col] + pp[1][r][col] + pp[2][r][col] + bi0;
            const float s1 = acc[r + 1] + pp[0][r + 1][col] + pp[1][r + 1][col] + pp[2][r + 1][col] + bi0;
            gelu2_f(s0, s1, hr[r], hr[r + 1]);
        }
        if (col < HALF_) {
            #pragma unroll
            for (int r = 0; r < 8; r++) sY[r][col] = hr[r];
        } else {
            #pragma unroll
            for (int r = 0; r < 8; r++)
                g_hg[(row0 + r) * HALF_ + col - HALF_] = hr[r];
        }
    }
    __syncthreads();

    // --- GEMM2: h_loc @ W1[0:128], K=128 split 32x4 across kq ---
    float a2[8];
    #pragma unroll
    for (int r = 0; r < 8; r++) a2[r] = 0.f;
    {
        const int kb = kq * 32;
        for (int k = kb; k < kb + 32; k += 4) {
            const float w0 = W1[(k + 0) * C_ + col];
            const float w1 = W1[(k + 1) * C_ + col];
            const float w2 = W1[(k + 2) * C_ + col];
            const float w3 = W1[(k + 3) * C_ + col];
            #pragma unroll
            for (int r = 0; r < 8; r++) {
                const float4 y = *(const float4*)&sY[r][k];
                a2[r] += y.x * w0 + y.y * w1 + y.z * w2 + y.w * w3;
            }
        }
    }
    if (kq > 0) {
        #pragma unroll
        for (int r = 0; r < 8; r++) pp[kq - 1][r][col] = a2[r];
    }
    __syncthreads();
    if (kq == 0) {
        #pragma unroll
        for (int r = 0; r < 8; r++)
            g_Ah[(row0 + r) * C_ + col] =
                __float2half_rn(a2[r] + pp[0][r][col] + pp[1][r][col] + pp[2][r][col]);
    }
}

// ---------------------------------------------------------------------------
// K23: combined prologue.  grid = 218 CTAs x 512 thr.
// ---------------------------------------------------------------------------
__global__ void __launch_bounds__(512) k23_pre(
    const float* __restrict__ query, const float* __restrict__ W1,
    const float* __restrict__ policy, const float* __restrict__ b1,
    const float* __restrict__ W2)
{
    const int blk = blockIdx.x;
    const int tid = threadIdx.x;

    if (blk < 200) {
        __shared__ float sQ[C_];
        __shared__ float pq[C_];
        const int b = blk / NQ_, i = blk % NQ_;
        const int col = tid & 255;
        const int kh = tid >> 8;
        if (tid < C_) sQ[tid] = query[(i * B_ + b) * C_ + tid];
        __syncthreads();

        float a[8];
        #pragma unroll
        for (int u = 0; u < 8; u++) a[u] = 0.f;
        const int kb = kh * 128;
        #pragma unroll 4
        for (int k = kb; k < kb + 128; k += 8) {
            #pragma unroll
            for (int u = 0; u < 8; u++)
                a[u] += sQ[k + u] * W1[(C_ + k + u) * C_ + col];
        }
        const float sum =
            ((a[0] + a[1]) + (a[2] + a[3])) + ((a[4] + a[5]) + (a[6] + a[7]));
        if (kh == 1) pq[col] = sum;
        __syncthreads();
        if (kh == 0) g_Cq[blk * C_ + col] = sum + pq[col];
    } else if (blk < 202) {
        const int b = blk - 200;
        const int lane = tid & 31, wid = tid >> 5;
        __shared__ float spol[N_];
        __shared__ float sred[16];
        __shared__ float sps;
        __shared__ float sG[4][HALF_];
        __shared__ float sglob[HALF_];

        float ps = 0.f;
        #pragma unroll
        for (int i = 0; i < 2; i++) {
            const float p = policy[b * N_ + tid + i * 512];
            spol[tid + i * 512] = p;
            ps += p;
        }
        #pragma unroll
        for (int o = 16; o; o >>= 1) ps += __shfl_xor_sync(0xffffffffu, ps, o);
        if (lane == 0) sred[wid] = ps;
        __syncthreads();

        const int c = tid & 127, sl = tid >> 7;     // 4 slices of 256 t
        float acc = 0.f;
        for (int t = sl * 256; t < sl * 256 + 256; t++)
            acc += g_hg[(b * N_ + t) * HALF_ + c] * spol[t];
        sG[sl][c] = acc;
        if (tid == 0) {
            float s = 0.f;
            #pragma unroll
            for (int w = 0; w < 16; w++) s += sred[w];
            sps = s;
        }
        __syncthreads();
        if (tid < HALF_)
            sglob[tid] = (sG[0][tid] + sG[1][tid] + sG[2][tid] + sG[3][tid]) / sps;
        __syncthreads();

        if (tid < C_) {
            float g = b1[tid];
            for (int k = 0; k < HALF_; k++)
                g += sglob[k] * W1[(HALF_ + k) * C_ + tid];
            g_gt[b * C_ + tid] = g;
        }
    } else {
        const int base = (blk - 202) * 2048;
        #pragma unroll
        for (int i = 0; i < 4; i++) {
            const int lin = base + i * 512 + tid;   // index into W2 [k][j]
            const int k = lin >> 7, j = lin & 127;
            g_W2h[j * C_ + k] = __float2half_rn(W2[lin]);
        }
    }
}

// ---------------------------------------------------------------------------
// K4: fused  u = gelu(Aloc[b,t]+Cq[b,i]+gt[b]) ; v = gelu(u@W2+b2) ;
//            w = v@W3+b3 ; out = log_softmax(w)
// fp16 mma.sync m16n8k16, fp32 accum. Double-buffered K-chunks of 64.
// grid (8, 200), 256 threads = 8 warps (2x4 warp tile over 128x128).
// ---------------------------------------------------------------------------
#define KC  64                 // K elements per chunk
#define US  72                 // smem row stride in halves (pad 8)
#define UBUF (128 * US)        // halves per buffer

__global__ void __launch_bounds__(256, 2) k4_h16(
    const float* __restrict__ b2v,
    const float* __restrict__ W3, const float* __restrict__ b3,
    float* __restrict__ out)
{
    extern __shared__ __half dynh[];
    __half* sU = dynh;                  // [2][128*US] gelu tile (fp16)
    __half* sW = dynh + 2 * UBUF;       // [2][128*US] W2 chunk  (fp16)

    __shared__ __align__(16) float sC[C_];
    __shared__ float sB2[HALF_];
    __shared__ float sW3[2 * HALF_];
    __shared__ float sPW[4][HALF_][2];

    const int tid = threadIdx.x;
    const int lane = tid & 31, warp = tid >> 5;
    const int wm = warp >> 2, wn = warp & 3;  // 2x4 warp grid
    const int g = lane >> 2, tig = lane & 3;

    const int bi = blockIdx.y;            // b*100 + i
    const int b = bi / NQ_;
    const int t0 = blockIdx.x * 128;
    const __half* aBase = g_Ah + (b * N_ + t0) * C_;

    sC[tid] = g_Cq[bi * C_ + tid] + g_gt[b * C_ + tid];
    if (tid < HALF_) sB2[tid] = b2v[tid];
    sW3[tid] = W3[tid];

    float acc[4][4][4];
    #pragma unroll
    for (int mi = 0; mi < 4; mi++)
        #pragma unroll
        for (int ni = 0; ni < 4; ni++)
            #pragma unroll
            for (int q = 0; q < 4; q++) acc[mi][ni][q] = 0.f;
    __syncthreads();   // sC ready before first fill

    // fill chunk 0 into buffer 0
    {
        __half* uDst = sU;
        __half* wDst = sW;
        #pragma unroll
        for (int i = 0; i < 4; i++) {
            const int e = tid + i * 256;
            const int t = e >> 3, q = e & 7;       // q: 8-half group in [0,64)
            const uint4 a4 = *(const uint4*)(aBase + t * C_ + q * 8);
            const float2 a0 = __half22float2(*(const __half2*)&a4.x);
            const float2 a1 = __half22float2(*(const __half2*)&a4.y);
            const float2 a2 = __half22float2(*(const __half2*)&a4.z);
            const float2 a3 = __half22float2(*(const __half2*)&a4.w);
            const float4 c0 = *(const float4*)(sC + q * 8);
            const float4 c1 = *(const float4*)(sC + q * 8 + 4);
            uint4 u;
            u.x = gelu2t_h2(a0.x + c0.x, a0.y + c0.y);
            u.y = gelu2t_h2(a1.x + c0.z, a1.y + c0.w);
            u.z = gelu2t_h2(a2.x + c1.x, a2.y + c1.y);
            u.w = gelu2t_h2(a3.x + c1.z, a3.y + c1.w);
            *(uint4*)(uDst + t * US + q * 8) = u;
        }
        #pragma unroll
        for (int i = 0; i < 4; i++) {
            const int e = tid + i * 256;
            const int j = e >> 3, q = e & 7;
            *(uint4*)(wDst + j * US + q * 8) =
                *(const uint4*)(g_W2h + j * C_ + q * 8);
        }
    }
    __syncthreads();

    for (int c = 0; c < 4; c++) {
        const __half* bU = sU + (c & 1) * UBUF;
        const __half* bW = sW + (c & 1) * UBUF;

        #pragma unroll
        for (int ks = 0; ks < KC; ks += 16) {
            uint32_t af[4][4], bf[4][2];
            #pragma unroll
            for (int mi = 0; mi < 4; mi++) {
                const int row = wm * 64 + mi * 16 + g;
                af[mi][0] = *(const uint32_t*)(bU + row * US + ks + 2 * tig);
                af[mi][1] = *(const uint32_t*)(bU + (row + 8) * US + ks + 2 * tig);
                af[mi][2] = *(const uint32_t*)(bU + row * US + ks + 2 * tig + 8);
                af[mi][3] = *(const uint32_t*)(bU + (row + 8) * US + ks + 2 * tig + 8);
            }
            #pragma unroll
            for (int ni = 0; ni < 4; ni++) {
                const int j = wn * 32 + ni * 8 + g;
                bf[ni][0] = *(const uint32_t*)(bW + j * US + ks + 2 * tig);
                bf[ni][1] = *(const uint32_t*)(bW + j * US + ks + 2 * tig + 8);
            }
            #pragma unroll
            for (int mi = 0; mi < 4; mi++)
                #pragma unroll
                for (int ni = 0; ni < 4; ni++)
                    mma_f16(acc[mi][ni], af[mi], bf[ni]);
        }

        if (c < 3) {
            const int k0 = (c + 1) * KC;
            __half* uDst = sU + ((c + 1) & 1) * UBUF;
            __half* wDst = sW + ((c + 1) & 1) * UBUF;
            #pragma unroll
            for (int i = 0; i < 4; i++) {
                const int e = tid + i * 256;
                const int t = e >> 3, q = e & 7;
                const uint4 a4 = *(const uint4*)(aBase + t * C_ + k0 + q * 8);
                const float2 a0 = __half22float2(*(const __half2*)&a4.x);
                const float2 a1 = __half22float2(*(const __half2*)&a4.y);
                const float2 a2 = __half22float2(*(const __half2*)&a4.z);
                const float2 a3 = __half22float2(*(const __half2*)&a4.w);
                const float4 c0 = *(const float4*)(sC + k0 + q * 8);
                const float4 c1 = *(const float4*)(sC + k0 + q * 8 + 4);
                uint4 u;
                u.x = gelu2t_h2(a0.x + c0.x, a0.y + c0.y);
                u.y = gelu2t_h2(a1.x + c0.z, a1.y + c0.w);
                u.z = gelu2t_h2(a2.x + c1.x, a2.y + c1.y);
                u.w = gelu2t_h2(a3.x + c1.z, a3.y + c1.w);
                *(uint4*)(uDst + t * US + q * 8) = u;
            }
            #pragma unroll
            for (int i = 0; i < 4; i++) {
                const int e = tid + i * 256;
                const int j = e >> 3, q = e & 7;
                *(uint4*)(wDst + j * US + q * 8) =
                    *(const uint4*)(g_W2h + j * C_ + k0 + q * 8);
            }
        }
        __syncthreads();
    }

    // Epilogue: v = gelu(acc + b2) [exact A-S erf], w = v @ W3, reduce.
    #pragma unroll
    for (int mi = 0; mi < 4; mi++) {
        float p00 = 0.f, p01 = 0.f, p10 = 0.f, p11 = 0.f;
        #pragma unroll
        for (int ni = 0; ni < 4; ni++) {
            const int jb = wn * 32 + ni * 8 + tig * 2;
            float v0, v1, v2, v3;
            gelu2_f(acc[mi][ni][0] + sB2[jb], acc[mi][ni][1] + sB2[jb + 1], v0, v1);
            gelu2_f(acc[mi][ni][2] + sB2[jb], acc[mi][ni][3] + sB2[jb + 1], v2, v3);
            p00 += v0 * sW3[2 * jb]     + v1 * sW3[2 * jb + 2];
            p01 += v0 * sW3[2 * jb + 1] + v1 * sW3[2 * jb + 3];
            p10 += v2 * sW3[2 * jb]     + v3 * sW3[2 * jb + 2];
            p11 += v2 * sW3[2 * jb + 1] + v3 * sW3[2 * jb + 3];
        }
        #pragma unroll
        for (int o = 1; o < 4; o <<= 1) {
            p00 += __shfl_xor_sync(0xffffffffu, p00, o);
            p01 += __shfl_xor_sync(0xffffffffu, p01, o);
            p10 += __shfl_xor_sync(0xffffffffu, p10, o);
            p11 += __shfl_xor_sync(0xffffffffu, p11, o);
        }
        if (tig == 0) {
            const int r0 = wm * 64 + mi * 16 + g;
            sPW[wn][r0][0] = p00;  sPW[wn][r0][1] = p01;
            sPW[wn][r0 + 8][0] = p10;  sPW[wn][r0 + 8][1] = p11;
        }
    }
    __syncthreads();

    if (tid < HALF_) {
        float w0 = b3[0], w1 = b3[1];
        #pragma unroll
        for (int w = 0; w < 4; w++) {
            w0 += sPW[w][tid][0];
            w1 += sPW[w][tid][1];
        }
        const float m = fmaxf(w0, w1);
        const float l = m + logf(expf(w0 - m) + expf(w1 - m));
        const int t = t0 + tid;
        const long long o0 = ((long long)bi * N_ + t) * 2;
        out[o0]     = w0 - l;
        out[o0 + 1] = w1 - l;
    }
}

// ---------------------------------------------------------------------------
extern "C" void kernel_launch(void* const* d_in, const int* in_sizes, int n_in,
                              void* d_out, int out_size)
{
    const float* x      = (const float*)d_in[0];
    const float* query  = (const float*)d_in[1];
    const float* policy = (const float*)d_in[2];
    const float* ln_g   = (const float*)d_in[3];
    const float* ln_b   = (const float*)d_in[4];
    const float* W_in   = (const float*)d_in[5];
    const float* b_in   = (const float*)d_in[6];
    const float* W1     = (const float*)d_in[7];
    const float* b1     = (const float*)d_in[8];
    const float* W2     = (const float*)d_in[9];
    const float* b2     = (const float*)d_in[10];
    const float* W3     = (const float*)d_in[11];
    const float* b3     = (const float*)d_in[12];
    float* out = (float*)d_out;

    const int dyn_bytes = 4 * UBUF * (int)sizeof(__half);  // 73728
    cudaFuncSetAttribute(k4_h16, cudaFuncAttributeMaxDynamicSharedMemorySize,
                         dyn_bytes);

    k1_ln_gemm_gelu<<<(B_ * N_) / 8, 1024>>>(x, ln_g, ln_b, W_in, b_in, W1);
    k23_pre<<<218, 512>>>(query, W1, policy, b1, W2);
    k4_h16<<<dim3(N_ / 128, B_ * NQ_), 256, dyn_bytes>>>(b2, W3, b3, out);
}

// round 14
// speedup vs baseline: 4.7307x; 1.1339x over previous
#include <cuda_runtime.h>
#include <math.h>
#include <stdint.h>
#include <cuda_fp16.h>

// Problem dims (fixed by the dataset)
#define B_  2
#define N_  1024
#define C_  256
#define NQ_ 100
#define HALF_ 128

// Scratch (device globals: no allocation allowed)
__device__ __half g_Ah[B_ * N_ * C_];      // h_loc @ W1a (fp16)   (per b,t)
__device__ float  g_hg[B_ * N_ * HALF_];   // h glob half          (per b,t)
__device__ float  g_Cq[B_ * NQ_ * C_];     // q@W1c                (per b,i)
__device__ float  g_gt[B_ * C_];           // glob@W1b + b1        (per b)
__device__ __half g_W2h[HALF_ * C_];       // W2 transposed [j][k], fp16

// ---------------------------------------------------------------------------
// gelu, packed helpers (f32x2, sm_100+ PTX)
// ---------------------------------------------------------------------------
__device__ __forceinline__ uint64_t dup2_(float c) {
    uint64_t r; asm("mov.b64 %0, {%1, %1};" : "=l"(r) : "f"(c)); return r;
}
#define FMA2_(d, a, b, c) asm("fma.rn.f32x2 %0, %1, %2, %3;" : "=l"(d) : "l"(a), "l"(b), "l"(c))
#define MUL2_(d, a, b)    asm("mul.rn.f32x2 %0, %1, %2;"     : "=l"(d) : "l"(a), "l"(b))
#define ADD2_(d, a, b)    asm("add.rn.f32x2 %0, %1, %2;"     : "=l"(d) : "l"(a), "l"(b))

// Exact-precision path: A-S 7.1.26 erf (|err|<=1.5e-7), packed 2-wide.
__device__ __forceinline__ void gelu2_f(float xa, float xb, float& ra, float& rb) {
    uint64_t xp; asm("mov.b64 %0, {%1, %2};" : "=l"(xp) : "f"(xa), "f"(xb));
    const uint64_t ap = xp & 0x7FFFFFFF7FFFFFFFULL;
    uint64_t axk; MUL2_(axk, ap, dup2_(0.70710678118654752440f));
    uint64_t den; FMA2_(den, axk, dup2_(0.3275911f), dup2_(1.0f));
    float d0, d1; asm("mov.b64 {%0, %1}, %2;" : "=f"(d0), "=f"(d1) : "l"(den));
    float t0, t1;
    asm("rcp.approx.f32 %0, %1;" : "=f"(t0) : "f"(d0));
    asm("rcp.approx.f32 %0, %1;" : "=f"(t1) : "f"(d1));
    uint64_t t; asm("mov.b64 %0, {%1, %2};" : "=l"(t) : "f"(t0), "f"(t1));
    uint64_t p;
    FMA2_(p, dup2_(1.061405429f), t, dup2_(-1.453152027f));
    FMA2_(p, p, t, dup2_(1.421413741f));
    FMA2_(p, p, t, dup2_(-0.284496736f));
    FMA2_(p, p, t, dup2_(0.254829592f));
    MUL2_(p, p, t);
    uint64_t z2; MUL2_(z2, axk, axk);
    uint64_t w;  MUL2_(w, z2, dup2_(-1.4426950408889634f));   // -z^2 * log2(e)
    float w0, w1; asm("mov.b64 {%0, %1}, %2;" : "=f"(w0), "=f"(w1) : "l"(w));
    float e0, e1;
    asm("ex2.approx.f32 %0, %1;" : "=f"(e0) : "f"(w0));
    asm("ex2.approx.f32 %0, %1;" : "=f"(e1) : "f"(w1));
    uint64_t e; asm("mov.b64 %0, {%1, %2};" : "=l"(e) : "f"(e0), "f"(e1));
    uint64_t pe; MUL2_(pe, p, e);
    uint64_t er; FMA2_(er, pe, dup2_(-1.0f), dup2_(1.0f));    // 1 - p*e = erf(ax)
    const uint64_t s = er | (xp & 0x8000000080000000ULL);     // copysign (er>0)
    uint64_t onep; ADD2_(onep, s, dup2_(1.0f));
    uint64_t hx;   MUL2_(hx, xp, dup2_(0.5f));
    uint64_t res;  MUL2_(res, onep, hx);
    asm("mov.b64 {%0, %1}, %2;" : "=f"(ra), "=f"(rb) : "l"(res));
}

__device__ __forceinline__ uint32_t f2h2(float a, float b) {
    __half2 h = __floats2half2_rn(a, b);
    return *reinterpret_cast<uint32_t*>(&h);
}

// Fast path: tanh-form gelu with HW tanh.approx (floats out).
// |gelu_tanh - gelu_erf| <= ~3e-4 abs.
__device__ __forceinline__ void gelu2t_f(float xa, float xb, float& ra, float& rb) {
    uint64_t xp; asm("mov.b64 %0, {%1, %2};" : "=l"(xp) : "f"(xa), "f"(xb));
    uint64_t z2; MUL2_(z2, xp, xp);
    uint64_t cc; FMA2_(cc, z2, dup2_(0.0356774081f), dup2_(0.7978845608f));
    uint64_t in; MUL2_(in, xp, cc);
    float i0, i1; asm("mov.b64 {%0, %1}, %2;" : "=f"(i0), "=f"(i1) : "l"(in));
    float t0, t1;
    asm("tanh.approx.f32 %0, %1;" : "=f"(t0) : "f"(i0));
    asm("tanh.approx.f32 %0, %1;" : "=f"(t1) : "f"(i1));
    uint64_t tp; asm("mov.b64 %0, {%1, %2};" : "=l"(tp) : "f"(t0), "f"(t1));
    uint64_t hf; FMA2_(hf, tp, dup2_(0.5f), dup2_(0.5f));
    uint64_t res; MUL2_(res, xp, hf);
    asm("mov.b64 {%0, %1}, %2;" : "=f"(ra), "=f"(rb) : "l"(res));
}

__device__ __forceinline__ uint32_t gelu2t_h2(float xa, float xb) {
    float ra, rb;
    gelu2t_f(xa, xb, ra, rb);
    return f2h2(ra, rb);
}

__device__ __forceinline__ void mma_f16(float* d, const uint32_t* a, const uint32_t* b) {
    asm volatile(
        "mma.sync.aligned.m16n8k16.row.col.f32.f16.f16.f32 "
        "{%0,%1,%2,%3}, {%4,%5,%6,%7}, {%8,%9}, {%0,%1,%2,%3};"
        : "+f"(d[0]), "+f"(d[1]), "+f"(d[2]), "+f"(d[3])
        : "r"(a[0]), "r"(a[1]), "r"(a[2]), "r"(a[3]), "r"(b[0]), "r"(b[1]));
}

// ---------------------------------------------------------------------------
// K1 (merged): blocks 0..255   : h = gelu(LN(x)@W_in+b_in); A_loc = h_loc@W1a
//              blocks 256..455 : Cq[b,i,:] = query[i,b,:] @ W1[256:512]
// 1024 threads, 4-way split-K: thread = (col, kq).
// ---------------------------------------------------------------------------
__global__ void __launch_bounds__(1024) k1_ln_gemm_gelu(
    const float* __restrict__ x, const float* __restrict__ ln_g,
    const float* __restrict__ ln_b, const float* __restrict__ Win,
    const float* __restrict__ bin, const float* __restrict__ W1,
    const float* __restrict__ query)
{
    const int blk = blockIdx.x;
    const int tid = threadIdx.x;
    const int col = tid & 255;
    const int kq  = tid >> 8;            // 0..3

    if (blk >= 256) {
        // ---- query GEMM: one CTA per (b,i) ----
        __shared__ float sQ[C_];
        __shared__ float pq[3][C_];
        const int bi = blk - 256;
        const int b = bi / NQ_, i = bi % NQ_;
        if (tid < C_) sQ[tid] = query[(i * B_ + b) * C_ + tid];
        __syncthreads();

        float a[8];
        #pragma unroll
        for (int u = 0; u < 8; u++) a[u] = 0.f;
        const int kb = kq * 64;
        #pragma unroll 2
        for (int k = kb; k < kb + 64; k += 8) {
            #pragma unroll
            for (int u = 0; u < 8; u++)
                a[u] += sQ[k + u] * W1[(C_ + k + u) * C_ + col];
        }
        const float sum =
            ((a[0] + a[1]) + (a[2] + a[3])) + ((a[4] + a[5]) + (a[6] + a[7]));
        if (kq > 0) pq[kq - 1][col] = sum;
        __syncthreads();
        if (kq == 0)
            g_Cq[bi * C_ + col] = sum + pq[0][col] + pq[1][col] + pq[2][col];
        return;
    }

    __shared__ __align__(16) float sY[8][C_];
    __shared__ float pp[3][8][C_];
    __shared__ float sred[8][8][2];
    __shared__ float smu[8], ssc[8];

    const int lane = tid & 31;
    const int wid  = tid >> 5;           // 0..31
    const int row0 = blk * 8;

    const float gv = ln_g[col];
    const float bv = ln_b[col];

    // --- stats: quarter kq owns rows kq*2, kq*2+1 ---
    const int rbase = kq * 2;
    float xv[2];
    #pragma unroll
    for (int r = 0; r < 2; r++)
        xv[r] = x[(row0 + rbase + r) * C_ + col];

    {
        const int w8 = wid & 7;
        #pragma unroll
        for (int r = 0; r < 2; r++) {
            float s = xv[r], q = xv[r] * xv[r];
            #pragma unroll
            for (int o = 16; o; o >>= 1) {
                s += __shfl_xor_sync(0xffffffffu, s, o);
                q += __shfl_xor_sync(0xffffffffu, q, o);
            }
            if (lane == 0) { sred[rbase + r][w8][0] = s; sred[rbase + r][w8][1] = q; }
        }
    }
    __syncthreads();
    if (wid < 8) {
        float s = (lane < 8) ? sred[wid][lane][0] : 0.f;
        float q = (lane < 8) ? sred[wid][lane][1] : 0.f;
        #pragma unroll
        for (int o = 4; o; o >>= 1) {
            s += __shfl_xor_sync(0xffffffffu, s, o);
            q += __shfl_xor_sync(0xffffffffu, q, o);
        }
        if (lane == 0) {
            const float mu = s * (1.0f / C_);
            const float var = q * (1.0f / C_) - mu * mu;
            smu[wid] = mu;
            ssc[wid] = rsqrtf(var + 1e-5f);
        }
    }
    __syncthreads();
    #pragma unroll
    for (int r = 0; r < 2; r++)
        sY[rbase + r][col] = (xv[r] - smu[rbase + r]) * ssc[rbase + r] * gv + bv;
    __syncthreads();

    // --- GEMM1: y @ W_in, K=256 split 64/64/64/64 across kq ---
    float acc[8];
    #pragma unroll
    for (int r = 0; r < 8; r++) acc[r] = 0.f;
    {
        const int kb = kq * 64;
        for (int k = kb; k < kb + 64; k += 4) {
            const float w0 = Win[(k + 0) * C_ + col];
            const float w1 = Win[(k + 1) * C_ + col];
            const float w2 = Win[(k + 2) * C_ + col];
            const float w3 = Win[(k + 3) * C_ + col];
            #pragma unroll
            for (int r = 0; r < 8; r++) {
                const float4 y = *(const float4*)&sY[r][k];
                acc[r] += y.x * w0 + y.y * w1 + y.z * w2 + y.w * w3;
            }
        }
    }
    if (kq > 0) {
        #pragma unroll
        for (int r = 0; r < 8; r++) pp[kq - 1][r][col] = acc[r];
    }
    __syncthreads();

    if (kq == 0) {
        const float bi0 = bin[col];
        float hr[8];
        #pragma unroll
        for (int r = 0; r < 8; r += 2) {
            const float s0 = acc[r] + pp[0][r][col] + pp[1][r][col] + pp[2][r][col] + bi0;
            const float s1 = acc[r + 1] + pp[0][r + 1][col] + pp[1][r + 1][col] + pp[2][r + 1][col] + bi0;
            gelu2_f(s0, s1, hr[r], hr[r + 1]);
        }
        if (col < HALF_) {
            #pragma unroll
            for (int r = 0; r < 8; r++) sY[r][col] = hr[r];
        } else {
            #pragma unroll
            for (int r = 0; r < 8; r++)
                g_hg[(row0 + r) * HALF_ + col - HALF_] = hr[r];
        }
    }
    __syncthreads();

    // --- GEMM2: h_loc @ W1[0:128], K=128 split 32x4 across kq ---
    float a2[8];
    #pragma unroll
    for (int r = 0; r < 8; r++) a2[r] = 0.f;
    {
        const int kb = kq * 32;
        for (int k = kb; k < kb + 32; k += 4) {
            const float w0 = W1[(k + 0) * C_ + col];
            const float w1 = W1[(k + 1) * C_ + col];
            const float w2 = W1[(k + 2) * C_ + col];
            const float w3 = W1[(k + 3) * C_ + col];
            #pragma unroll
            for (int r = 0; r < 8; r++) {
                const float4 y = *(const float4*)&sY[r][k];
                a2[r] += y.x * w0 + y.y * w1 + y.z * w2 + y.w * w3;
            }
        }
    }
    if (kq > 0) {
        #pragma unroll
        for (int r = 0; r < 8; r++) pp[kq - 1][r][col] = a2[r];
    }
    __syncthreads();
    if (kq == 0) {
        #pragma unroll
        for (int r = 0; r < 8; r++)
            g_Ah[(row0 + r) * C_ + col] =
                __float2half_rn(a2[r] + pp[0][r][col] + pp[1][r][col] + pp[2][r][col]);
    }
}

// ---------------------------------------------------------------------------
// K23: remaining prologue.  grid = 18 CTAs x 512 thr.
//   blocks 0..1   : glob + gt (needs g_hg from k1)
//   blocks 2..17  : W2h transpose to fp16
// ---------------------------------------------------------------------------
__global__ void __launch_bounds__(512) k23_pre(
    const float* __restrict__ W1, const float* __restrict__ policy,
    const float* __restrict__ b1, const float* __restrict__ W2)
{
    const int blk = blockIdx.x;
    const int tid = threadIdx.x;

    if (blk < 2) {
        const int b = blk;
        const int lane = tid & 31, wid = tid >> 5;
        __shared__ float spol[N_];
        __shared__ float sred[16];
        __shared__ float sps;
        __shared__ float sG[4][HALF_];
        __shared__ float sglob[HALF_];

        float ps = 0.f;
        #pragma unroll
        for (int i = 0; i < 2; i++) {
            const float p = policy[b * N_ + tid + i * 512];
            spol[tid + i * 512] = p;
            ps += p;
        }
        #pragma unroll
        for (int o = 16; o; o >>= 1) ps += __shfl_xor_sync(0xffffffffu, ps, o);
        if (lane == 0) sred[wid] = ps;
        __syncthreads();

        const int c = tid & 127, sl = tid >> 7;     // 4 slices of 256 t
        float acc = 0.f;
        for (int t = sl * 256; t < sl * 256 + 256; t++)
            acc += g_hg[(b * N_ + t) * HALF_ + c] * spol[t];
        sG[sl][c] = acc;
        if (tid == 0) {
            float s = 0.f;
            #pragma unroll
            for (int w = 0; w < 16; w++) s += sred[w];
            sps = s;
        }
        __syncthreads();
        if (tid < HALF_)
            sglob[tid] = (sG[0][tid] + sG[1][tid] + sG[2][tid] + sG[3][tid]) / sps;
        __syncthreads();

        if (tid < C_) {
            float g = b1[tid];
            for (int k = 0; k < HALF_; k++)
                g += sglob[k] * W1[(HALF_ + k) * C_ + tid];
            g_gt[b * C_ + tid] = g;
        }
    } else {
        const int base = (blk - 2) * 2048;
        #pragma unroll
        for (int i = 0; i < 4; i++) {
            const int lin = base + i * 512 + tid;   // index into W2 [k][j]
            const int k = lin >> 7, j = lin & 127;
            g_W2h[j * C_ + k] = __float2half_rn(W2[lin]);
        }
    }
}

// ---------------------------------------------------------------------------
// K4: fused  u = gelu(Aloc[b,t]+Cq[b,i]+gt[b]) ; v = gelu(u@W2+b2) ;
//            w = v@W3+b3 ; out = log_softmax(w)
// fp16 mma.sync m16n8k16, fp32 accum. Double-buffered K-chunks of 64.
// grid (8, 200), 256 threads = 8 warps (2x4 warp tile over 128x128).
// ---------------------------------------------------------------------------
#define KC  64                 // K elements per chunk
#define US  72                 // smem row stride in halves (pad 8)
#define UBUF (128 * US)        // halves per buffer

__global__ void __launch_bounds__(256, 2) k4_h16(
    const float* __restrict__ b2v,
    const float* __restrict__ W3, const float* __restrict__ b3,
    float* __restrict__ out)
{
    extern __shared__ __half dynh[];
    __half* sU = dynh;                  // [2][128*US] gelu tile (fp16)
    __half* sW = dynh + 2 * UBUF;       // [2][128*US] W2 chunk  (fp16)

    __shared__ __align__(16) float sC[C_];
    __shared__ float sB2[HALF_];
    __shared__ float sW3[2 * HALF_];
    __shared__ float sPW[4][HALF_][2];

    const int tid = threadIdx.x;
    const int lane = tid & 31, warp = tid >> 5;
    const int wm = warp >> 2, wn = warp & 3;  // 2x4 warp grid
    const int g = lane >> 2, tig = lane & 3;

    const int bi = blockIdx.y;            // b*100 + i
    const int b = bi / NQ_;
    const int t0 = blockIdx.x * 128;
    const __half* aBase = g_Ah + (b * N_ + t0) * C_;

    sC[tid] = g_Cq[bi * C_ + tid] + g_gt[b * C_ + tid];
    if (tid < HALF_) sB2[tid] = b2v[tid];
    sW3[tid] = W3[tid];

    float acc[4][4][4];
    #pragma unroll
    for (int mi = 0; mi < 4; mi++)
        #pragma unroll
        for (int ni = 0; ni < 4; ni++)
            #pragma unroll
            for (int q = 0; q < 4; q++) acc[mi][ni][q] = 0.f;
    __syncthreads();   // sC ready before first fill

    // fill chunk 0 into buffer 0
    {
        __half* uDst = sU;
        __half* wDst = sW;
        #pragma unroll
        for (int i = 0; i < 4; i++) {
            const int e = tid + i * 256;
            const int t = e >> 3, q = e & 7;       // q: 8-half group in [0,64)
            const uint4 a4 = *(const uint4*)(aBase + t * C_ + q * 8);
            const float2 a0 = __half22float2(*(const __half2*)&a4.x);
            const float2 a1 = __half22float2(*(const __half2*)&a4.y);
            const float2 a2 = __half22float2(*(const __half2*)&a4.z);
            const float2 a3 = __half22float2(*(const __half2*)&a4.w);
            const float4 c0 = *(const float4*)(sC + q * 8);
            const float4 c1 = *(const float4*)(sC + q * 8 + 4);
            uint4 u;
            u.x = gelu2t_h2(a0.x + c0.x, a0.y + c0.y);
            u.y = gelu2t_h2(a1.x + c0.z, a1.y + c0.w);
            u.z = gelu2t_h2(a2.x + c1.x, a2.y + c1.y);
            u.w = gelu2t_h2(a3.x + c1.z, a3.y + c1.w);
            *(uint4*)(uDst + t * US + q * 8) = u;
        }
        #pragma unroll
        for (int i = 0; i < 4; i++) {
            const int e = tid + i * 256;
            const int j = e >> 3, q = e & 7;
            *(uint4*)(wDst + j * US + q * 8) =
                *(const uint4*)(g_W2h + j * C_ + q * 8);
        }
    }
    __syncthreads();

    for (int c = 0; c < 4; c++) {
        const __half* bU = sU + (c & 1) * UBUF;
        const __half* bW = sW + (c & 1) * UBUF;

        #pragma unroll
        for (int ks = 0; ks < KC; ks += 16) {
            uint32_t af[4][4], bf[4][2];
            #pragma unroll
            for (int mi = 0; mi < 4; mi++) {
                const int row = wm * 64 + mi * 16 + g;
                af[mi][0] = *(const uint32_t*)(bU + row * US + ks + 2 * tig);
                af[mi][1] = *(const uint32_t*)(bU + (row + 8) * US + ks + 2 * tig);
                af[mi][2] = *(const uint32_t*)(bU + row * US + ks + 2 * tig + 8);
                af[mi][3] = *(const uint32_t*)(bU + (row + 8) * US + ks + 2 * tig + 8);
            }
            #pragma unroll
            for (int ni = 0; ni < 4; ni++) {
                const int j = wn * 32 + ni * 8 + g;
                bf[ni][0] = *(const uint32_t*)(bW + j * US + ks + 2 * tig);
                bf[ni][1] = *(const uint32_t*)(bW + j * US + ks + 2 * tig + 8);
            }
            #pragma unroll
            for (int mi = 0; mi < 4; mi++)
                #pragma unroll
                for (int ni = 0; ni < 4; ni++)
                    mma_f16(acc[mi][ni], af[mi], bf[ni]);
        }

        if (c < 3) {
            const int k0 = (c + 1) * KC;
            __half* uDst = sU + ((c + 1) & 1) * UBUF;
            __half* wDst = sW + ((c + 1) & 1) * UBUF;
            #pragma unroll
            for (int i = 0; i < 4; i++) {
                const int e = tid + i * 256;
                const int t = e >> 3, q = e & 7;
                const uint4 a4 = *(const uint4*)(aBase + t * C_ + k0 + q * 8);
                const float2 a0 = __half22float2(*(const __half2*)&a4.x);
                const float2 a1 = __half22float2(*(const __half2*)&a4.y);
                const float2 a2 = __half22float2(*(const __half2*)&a4.z);
                const float2 a3 = __half22float2(*(const __half2*)&a4.w);
                const float4 c0 = *(const float4*)(sC + k0 + q * 8);
                const float4 c1 = *(const float4*)(sC + k0 + q * 8 + 4);
                uint4 u;
                u.x = gelu2t_h2(a0.x + c0.x, a0.y + c0.y);
                u.y = gelu2t_h2(a1.x + c0.z, a1.y + c0.w);
                u.z = gelu2t_h2(a2.x + c1.x, a2.y + c1.y);
                u.w = gelu2t_h2(a3.x + c1.z, a3.y + c1.w);
                *(uint4*)(uDst + t * US + q * 8) = u;
            }
            #pragma unroll
            for (int i = 0; i < 4; i++) {
                const int e = tid + i * 256;
                const int j = e >> 3, q = e & 7;
                *(uint4*)(wDst + j * US + q * 8) =
                    *(const uint4*)(g_W2h + j * C_ + k0 + q * 8);
            }
        }
        __syncthreads();
    }

    // Epilogue: v = gelu_tanh(acc + b2), w = v @ W3, reduce.
    #pragma unroll
    for (int mi = 0; mi < 4; mi++) {
        float p00 = 0.f, p01 = 0.f, p10 = 0.f, p11 = 0.f;
        #pragma unroll
        for (int ni = 0; ni < 4; ni++) {
            const int jb = wn * 32 + ni * 8 + tig * 2;
            float v0, v1, v2, v3;
            gelu2t_f(acc[mi][ni][0] + sB2[jb], acc[mi][ni][1] + sB2[jb + 1], v0, v1);
            gelu2t_f(acc[mi][ni][2] + sB2[jb], acc[mi][ni][3] + sB2[jb + 1], v2, v3);
            p00 += v0 * sW3[2 * jb]     + v1 * sW3[2 * jb + 2];
            p01 += v0 * sW3[2 * jb + 1] + v1 * sW3[2 * jb + 3];
            p10 += v2 * sW3[2 * jb]     + v3 * sW3[2 * jb + 2];
            p11 += v2 * sW3[2 * jb + 1] + v3 * sW3[2 * jb + 3];
        }
        #pragma unroll
        for (int o = 1; o < 4; o <<= 1) {
            p00 += __shfl_xor_sync(0xffffffffu, p00, o);
            p01 += __shfl_xor_sync(0xffffffffu, p01, o);
            p10 += __shfl_xor_sync(0xffffffffu, p10, o);
            p11 += __shfl_xor_sync(0xffffffffu, p11, o);
        }
        if (tig == 0) {
            const int r0 = wm * 64 + mi * 16 + g;
            sPW[wn][r0][0] = p00;  sPW[wn][r0][1] = p01;
            sPW[wn][r0 + 8][0] = p10;  sPW[wn][r0 + 8][1] = p11;
        }
    }
    __syncthreads();

    if (tid < HALF_) {
        float w0 = b3[0], w1 = b3[1];
        #pragma unroll
        for (int w = 0; w < 4; w++) {
            w0 += sPW[w][tid][0];
            w1 += sPW[w][tid][1];
        }
        const float m = fmaxf(w0, w1);
        const float l = m + logf(expf(w0 - m) + expf(w1 - m));
        const int t = t0 + tid;
        const long long o0 = ((long long)bi * N_ + t) * 2;
        out[o0]     = w0 - l;
        out[o0 + 1] = w1 - l;
    }
}

// ---------------------------------------------------------------------------
extern "C" void kernel_launch(void* const* d_in, const int* in_sizes, int n_in,
                              void* d_out, int out_size)
{
    const float* x      = (const float*)d_in[0];
    const float* query  = (const float*)d_in[1];
    const float* policy = (const float*)d_in[2];
    const float* ln_g   = (const float*)d_in[3];
    const float* ln_b   = (const float*)d_in[4];
    const float* W_in   = (const float*)d_in[5];
    const float* b_in   = (const float*)d_in[6];
    const float* W1     = (const float*)d_in[7];
    const float* b1     = (const float*)d_in[8];
    const float* W2     = (const float*)d_in[9];
    const float* b2     = (const float*)d_in[10];
    const float* W3     = (const float*)d_in[11];
    const float* b3     = (const float*)d_in[12];
    float* out = (float*)d_out;

    const int dyn_bytes = 4 * UBUF * (int)sizeof(__half);  // 73728
    cudaFuncSetAttribute(k4_h16, cudaFuncAttributeMaxDynamicSharedMemorySize,
                         dyn_bytes);

    k1_ln_gemm_gelu<<<256 + B_ * NQ_, 1024>>>(x, ln_g, ln_b, W_in, b_in, W1, query);
    k23_pre<<<18, 512>>>(W1, policy, b1, W2);
    k4_h16<<<dim3(N_ / 128, B_ * NQ_), 256, dyn_bytes>>>(b2, W3, b3, out);
}